// round 4
// baseline (speedup 1.0000x reference)
#include <cuda_runtime.h>
#include <cuda_bf16.h>
#include <math.h>

// Problem constants
#define S_LEN 2048
#define HID   4096
#define NH    32
#define NKV   8
#define HD    128
#define NQ    (NH * HD)    // 4096
#define NKVD  (NKV * HD)   // 1024

// ---------------------------------------------------------------------------
// Scratch (static device arrays; no cudaMalloc allowed)
// ---------------------------------------------------------------------------
__device__ float g_q [S_LEN * NQ];    // Q projection  [S][NQ]
__device__ float g_kp[S_LEN * NKVD];  // K projection  [S][NKVD]
__device__ float g_vp[S_LEN * NKVD];  // V projection  [S][NKVD]
__device__ float g_qh[S_LEN * NQ];    // Q rope, head-major [NH][S][HD]
__device__ float g_kh[S_LEN * NKVD];  // K rope, head-major [NKV][S][HD]
__device__ float g_vh[S_LEN * NKVD];  // V head-major      [NKV][S][HD]
__device__ float g_ao[S_LEN * NQ];    // attention output  [S][NQ]

// ---------------------------------------------------------------------------
// SGEMM: C[M,N] = A[M,K] @ B[K,N], all row-major fp32.
// 128x128 block tile, 8x8 per-thread microtile, 256 threads, double-buffered.
// Requires M%128==0, N%128==0, K%8==0 (true for all shapes here).
// ---------------------------------------------------------------------------
__global__ __launch_bounds__(256) void sgemm128x128(
    const float* __restrict__ A, const float* __restrict__ B,
    float* __restrict__ C, int M, int N, int K)
{
    __shared__ float As[2][8][128];   // [k][m]
    __shared__ float Bs[2][8][128];   // [k][n]

    const int tid = threadIdx.x;
    const int tx  = tid & 15;
    const int ty  = tid >> 4;
    const int bm  = blockIdx.y * 128;
    const int bn  = blockIdx.x * 128;

    // A load pattern: thread -> (row ar, kcol ac..ac+3), transposed into As
    const int ar = tid >> 1;
    const int ac = (tid & 1) << 2;
    // B load pattern: thread -> (krow br, col bc..bc+3), direct into Bs
    const int br = tid >> 5;
    const int bc = (tid & 31) << 2;

    const float* Aptr = A + (size_t)(bm + ar) * K + ac;
    const float* Bptr = B + (size_t)br * N + bn + bc;

    float acc[8][8];
#pragma unroll
    for (int i = 0; i < 8; ++i)
#pragma unroll
        for (int j = 0; j < 8; ++j) acc[i][j] = 0.0f;

    // prologue: tile 0
    {
        float4 a4 = *(const float4*)(Aptr);
        float4 b4 = *(const float4*)(Bptr);
        As[0][ac + 0][ar] = a4.x;
        As[0][ac + 1][ar] = a4.y;
        As[0][ac + 2][ar] = a4.z;
        As[0][ac + 3][ar] = a4.w;
        *(float4*)&Bs[0][br][bc] = b4;
    }
    __syncthreads();

    const int nk = K >> 3;
    for (int kt = 0; kt < nk; ++kt) {
        const int cur = kt & 1;
        const int nxt = cur ^ 1;
        float4 na, nb;
        const bool more = (kt + 1 < nk);
        if (more) {
            na = *(const float4*)(Aptr + (kt + 1) * 8);
            nb = *(const float4*)(Bptr + (size_t)(kt + 1) * 8 * N);
        }
#pragma unroll
        for (int k = 0; k < 8; ++k) {
            float4 a0 = *(const float4*)&As[cur][k][ty * 4];
            float4 a1 = *(const float4*)&As[cur][k][64 + ty * 4];
            float4 b0 = *(const float4*)&Bs[cur][k][tx * 4];
            float4 b1 = *(const float4*)&Bs[cur][k][64 + tx * 4];
            float av[8] = {a0.x, a0.y, a0.z, a0.w, a1.x, a1.y, a1.z, a1.w};
            float bv[8] = {b0.x, b0.y, b0.z, b0.w, b1.x, b1.y, b1.z, b1.w};
#pragma unroll
            for (int i = 0; i < 8; ++i)
#pragma unroll
                for (int j = 0; j < 8; ++j)
                    acc[i][j] = fmaf(av[i], bv[j], acc[i][j]);
        }
        if (more) {
            As[nxt][ac + 0][ar] = na.x;
            As[nxt][ac + 1][ar] = na.y;
            As[nxt][ac + 2][ar] = na.z;
            As[nxt][ac + 3][ar] = na.w;
            *(float4*)&Bs[nxt][br][bc] = nb;
        }
        __syncthreads();
    }

    // epilogue
#pragma unroll
    for (int i = 0; i < 8; ++i) {
        const int m = bm + ((i < 4) ? (ty * 4 + i) : (64 + ty * 4 + (i - 4)));
        float4 c0 = make_float4(acc[i][0], acc[i][1], acc[i][2], acc[i][3]);
        float4 c1 = make_float4(acc[i][4], acc[i][5], acc[i][6], acc[i][7]);
        *(float4*)&C[(size_t)m * N + bn + tx * 4]      = c0;
        *(float4*)&C[(size_t)m * N + bn + 64 + tx * 4] = c1;
    }
}

// ---------------------------------------------------------------------------
// RoPE + head-major transpose.
// src: [S][H*HD] projection output; dst: [H][S][HD].
// rotate_half(x)[d] = d<64 ? -x[d+64] : x[d-64]  (= sign * x[d^64])
// ---------------------------------------------------------------------------
__global__ __launch_bounds__(128) void rope_transpose(
    const float* __restrict__ src, const float* __restrict__ cosp,
    const float* __restrict__ sinp, float* __restrict__ dst,
    int H, int apply_rope)
{
    const int s = blockIdx.x;
    const int h = blockIdx.y;
    const int d = threadIdx.x;
    const int stride = H * HD;

    const float x = src[(size_t)s * stride + h * HD + d];
    float val;
    if (apply_rope) {
        const float p   = src[(size_t)s * stride + h * HD + (d ^ 64)];
        const float rot = (d < 64) ? -p : p;
        val = x * cosp[s * HD + d] + rot * sinp[s * HD + d];
    } else {
        val = x;
    }
    dst[((size_t)h * S_LEN + s) * HD + d] = val;
}

// ---------------------------------------------------------------------------
// Flash attention (fp32, causal, GQA 4:1).
// Grid: (S/64 query tiles, NH heads). 256 threads as 16x16.
// smem: Qs[d][m] 128x64, Kst[d][n] 128x64, Vs[kk][d] 64x128, Ps[n][m] 64x68.
// Each thread: 4x4 score fragment, 4x8 output fragment.
// ---------------------------------------------------------------------------
#define PS_STRIDE 68
#define SMEM_FA ((128 * 64 + 128 * 64 + 64 * 128 + 64 * PS_STRIDE) * 4)

__global__ __launch_bounds__(256) void flash_attn(
    const float* __restrict__ Qh, const float* __restrict__ Kh,
    const float* __restrict__ Vh, float* __restrict__ O)
{
    extern __shared__ float sm[];
    float* Qs  = sm;                    // [128][64]
    float* Kst = Qs + 128 * 64;         // [128][64]
    float* Vs  = Kst + 128 * 64;        // [64][128]
    float* Ps  = Vs + 64 * 128;         // [64][PS_STRIDE]

    const int tid = threadIdx.x;
    const int tx  = tid & 15;
    const int ty  = tid >> 4;
    const int ty4 = ty * 4, tx4 = tx * 4, tx8 = tx * 8;
    const int qb  = blockIdx.x;     // query tile index
    const int h   = blockIdx.y;     // head
    const int kvh = h >> 2;         // N_REP = 4

    const float* Qbase = Qh + ((size_t)h * S_LEN + qb * 64) * HD;
    const float* Kbase = Kh + (size_t)kvh * S_LEN * HD;
    const float* Vbase = Vh + (size_t)kvh * S_LEN * HD;

    // Load Q tile transposed into Qs[d][m]
    {
        const int r     = tid >> 2;
        const int dbase = (tid & 3) * 32;
#pragma unroll
        for (int i = 0; i < 8; ++i) {
            float4 v = *(const float4*)(Qbase + r * HD + dbase + i * 4);
            Qs[(dbase + i * 4 + 0) * 64 + r] = v.x;
            Qs[(dbase + i * 4 + 1) * 64 + r] = v.y;
            Qs[(dbase + i * 4 + 2) * 64 + r] = v.z;
            Qs[(dbase + i * 4 + 3) * 64 + r] = v.w;
        }
    }

    float m_i[4], l_i[4], o[4][8];
#pragma unroll
    for (int i = 0; i < 4; ++i) {
        m_i[i] = -1e30f;
        l_i[i] = 0.0f;
#pragma unroll
        for (int j = 0; j < 8; ++j) o[i][j] = 0.0f;
    }

    const float sc = 0.08838834764831845f;  // 1/sqrt(128)

    for (int jt = 0; jt <= qb; ++jt) {
        __syncthreads();  // prev PV done reading Kst/Vs/Ps
        // Load K tile transposed + V tile
        {
            const int r     = tid >> 2;
            const int dbase = (tid & 3) * 32;
            const float* kp = Kbase + (size_t)(jt * 64 + r) * HD + dbase;
            const float* vp = Vbase + (size_t)(jt * 64 + r) * HD + dbase;
#pragma unroll
            for (int i = 0; i < 8; ++i) {
                float4 kv = *(const float4*)(kp + i * 4);
                Kst[(dbase + i * 4 + 0) * 64 + r] = kv.x;
                Kst[(dbase + i * 4 + 1) * 64 + r] = kv.y;
                Kst[(dbase + i * 4 + 2) * 64 + r] = kv.z;
                Kst[(dbase + i * 4 + 3) * 64 + r] = kv.w;
                float4 vv = *(const float4*)(vp + i * 4);
                *(float4*)&Vs[r * 128 + dbase + i * 4] = vv;
            }
        }
        __syncthreads();

        // Scores S = Q K^T (64x64)
        float s[4][4];
#pragma unroll
        for (int i = 0; i < 4; ++i)
#pragma unroll
            for (int j = 0; j < 4; ++j) s[i][j] = 0.0f;

#pragma unroll 8
        for (int d = 0; d < 128; ++d) {
            float4 q4 = *(const float4*)&Qs[d * 64 + ty4];
            float4 k4 = *(const float4*)&Kst[d * 64 + tx4];
            float qa[4] = {q4.x, q4.y, q4.z, q4.w};
            float ka[4] = {k4.x, k4.y, k4.z, k4.w};
#pragma unroll
            for (int i = 0; i < 4; ++i)
#pragma unroll
                for (int j = 0; j < 4; ++j)
                    s[i][j] = fmaf(qa[i], ka[j], s[i][j]);
        }

        const bool diag = (jt == qb);
#pragma unroll
        for (int i = 0; i < 4; ++i)
#pragma unroll
            for (int j = 0; j < 4; ++j) {
                float v = s[i][j] * sc;
                if (diag && (tx4 + j) > (ty4 + i)) v = -1e30f;  // causal mask
                s[i][j] = v;
            }

        // Online softmax per row
#pragma unroll
        for (int i = 0; i < 4; ++i) {
            float mx = fmaxf(fmaxf(s[i][0], s[i][1]), fmaxf(s[i][2], s[i][3]));
#pragma unroll
            for (int off = 8; off >= 1; off >>= 1)
                mx = fmaxf(mx, __shfl_xor_sync(0xffffffffu, mx, off, 16));
            const float mnew  = fmaxf(m_i[i], mx);
            const float alpha = __expf(m_i[i] - mnew);
            m_i[i] = mnew;
            float rs = 0.0f;
#pragma unroll
            for (int j = 0; j < 4; ++j) {
                const float p = __expf(s[i][j] - mnew);
                s[i][j] = p;
                rs += p;
            }
#pragma unroll
            for (int off = 8; off >= 1; off >>= 1)
                rs += __shfl_xor_sync(0xffffffffu, rs, off, 16);
            l_i[i] = l_i[i] * alpha + rs;
#pragma unroll
            for (int j = 0; j < 8; ++j) o[i][j] *= alpha;
        }

        // Stage P transposed: Ps[n][m]
#pragma unroll
        for (int i = 0; i < 4; ++i)
#pragma unroll
            for (int j = 0; j < 4; ++j)
                Ps[(tx4 + j) * PS_STRIDE + ty4 + i] = s[i][j];
        __syncthreads();

        // O += P @ V
#pragma unroll 4
        for (int kk = 0; kk < 64; ++kk) {
            float4 p4 = *(const float4*)&Ps[kk * PS_STRIDE + ty4];
            float4 v0 = *(const float4*)&Vs[kk * 128 + tx8];
            float4 v1 = *(const float4*)&Vs[kk * 128 + tx8 + 4];
            float pa[4] = {p4.x, p4.y, p4.z, p4.w};
#pragma unroll
            for (int i = 0; i < 4; ++i) {
                o[i][0] = fmaf(pa[i], v0.x, o[i][0]);
                o[i][1] = fmaf(pa[i], v0.y, o[i][1]);
                o[i][2] = fmaf(pa[i], v0.z, o[i][2]);
                o[i][3] = fmaf(pa[i], v0.w, o[i][3]);
                o[i][4] = fmaf(pa[i], v1.x, o[i][4]);
                o[i][5] = fmaf(pa[i], v1.y, o[i][5]);
                o[i][6] = fmaf(pa[i], v1.z, o[i][6]);
                o[i][7] = fmaf(pa[i], v1.w, o[i][7]);
            }
        }
    }

    // Epilogue: normalize and store to [S][NQ] with head offset
    float* Op = O + (size_t)(qb * 64) * NQ + h * HD;
#pragma unroll
    for (int i = 0; i < 4; ++i) {
        const float inv = 1.0f / l_i[i];
        const int m = ty4 + i;
        float4 r0 = make_float4(o[i][0] * inv, o[i][1] * inv, o[i][2] * inv, o[i][3] * inv);
        float4 r1 = make_float4(o[i][4] * inv, o[i][5] * inv, o[i][6] * inv, o[i][7] * inv);
        *(float4*)&Op[(size_t)m * NQ + tx8]     = r0;
        *(float4*)&Op[(size_t)m * NQ + tx8 + 4] = r1;
    }
}

// ---------------------------------------------------------------------------
// Launch
// Inputs (metadata order): 0 hidden_states, 1 attention_mask (unused; causal
// computed inline), 2 wq, 3 wk, 4 wv, 5 wo, 6 cos, 7 sin.
// ---------------------------------------------------------------------------
extern "C" void kernel_launch(void* const* d_in, const int* in_sizes, int n_in,
                              void* d_out, int out_size)
{
    (void)in_sizes; (void)n_in; (void)out_size;
    const float* hs = (const float*)d_in[0];
    const float* wq = (const float*)d_in[2];
    const float* wk = (const float*)d_in[3];
    const float* wv = (const float*)d_in[4];
    const float* wo = (const float*)d_in[5];
    const float* cs = (const float*)d_in[6];
    const float* sn = (const float*)d_in[7];
    float* out = (float*)d_out;

    float *q, *kp, *vp, *qh, *kh, *vh, *ao;
    cudaGetSymbolAddress((void**)&q,  g_q);
    cudaGetSymbolAddress((void**)&kp, g_kp);
    cudaGetSymbolAddress((void**)&vp, g_vp);
    cudaGetSymbolAddress((void**)&qh, g_qh);
    cudaGetSymbolAddress((void**)&kh, g_kh);
    cudaGetSymbolAddress((void**)&vh, g_vh);
    cudaGetSymbolAddress((void**)&ao, g_ao);

    // QKV projections
    sgemm128x128<<<dim3(NQ / 128,   S_LEN / 128), 256>>>(hs, wq, q,  S_LEN, NQ,   HID);
    sgemm128x128<<<dim3(NKVD / 128, S_LEN / 128), 256>>>(hs, wk, kp, S_LEN, NKVD, HID);
    sgemm128x128<<<dim3(NKVD / 128, S_LEN / 128), 256>>>(hs, wv, vp, S_LEN, NKVD, HID);

    // RoPE + transpose to head-major
    rope_transpose<<<dim3(S_LEN, NH),  128>>>(q,  cs, sn, qh, NH,  1);
    rope_transpose<<<dim3(S_LEN, NKV), 128>>>(kp, cs, sn, kh, NKV, 1);
    rope_transpose<<<dim3(S_LEN, NKV), 128>>>(vp, cs, sn, vh, NKV, 0);

    // Flash attention (needs >48KB dynamic smem)
    cudaFuncSetAttribute(flash_attn, cudaFuncAttributeMaxDynamicSharedMemorySize, SMEM_FA);
    flash_attn<<<dim3(S_LEN / 64, NH), 256, SMEM_FA>>>(qh, kh, vh, ao);

    // Output projection
    sgemm128x128<<<dim3(HID / 128, S_LEN / 128), 256>>>(ao, wo, out, S_LEN, HID, NQ);
}

// round 6
// speedup vs baseline: 2.1783x; 2.1783x over previous
#include <cuda_runtime.h>
#include <cuda_bf16.h>
#include <math.h>
#include <stdint.h>

// Problem constants
#define S_LEN 2048
#define HID   4096
#define NH    32
#define NKV   8
#define HD    128
#define NQ    (NH * HD)    // 4096
#define NKVD  (NKV * HD)   // 1024

// ---------------------------------------------------------------------------
// Scratch (static device arrays; no cudaMalloc allowed)
// ---------------------------------------------------------------------------
__device__ float g_hsr [S_LEN * HID];      // hidden states, tf32-rounded
__device__ float g_wqT [NQ * HID];         // wq^T  [4096][4096]
__device__ float g_wkvT[2 * NKVD * HID];   // [wk^T ; wv^T]  [2048][4096]
__device__ float g_woT [HID * NQ];         // wo^T  [4096][4096]
__device__ float g_q   [S_LEN * NQ];       // Q projection [S][4096]
__device__ float g_kvp [S_LEN * 2 * NKVD]; // KV projection [S][2048]
__device__ float g_qh  [S_LEN * NQ];       // Q rope, head-major [NH][S][HD]
__device__ float g_kh  [S_LEN * NKVD];     // K rope, head-major [NKV][S][HD]
__device__ float g_vh  [S_LEN * NKVD];     // V head-major
__device__ float g_ao  [S_LEN * NQ];       // attention out [S][4096]

// ---------------------------------------------------------------------------
// Helpers
// ---------------------------------------------------------------------------
__device__ __forceinline__ float rna_tf32(float v) {
    uint32_t o;
    asm("cvt.rna.tf32.f32 %0, %1;" : "=r"(o) : "f"(v));
    return __uint_as_float(o);
}
__device__ __forceinline__ void mma_tf32(float* c, const uint32_t* a, const uint32_t* b) {
    asm("mma.sync.aligned.m16n8k8.row.col.f32.tf32.tf32.f32 "
        "{%0,%1,%2,%3}, {%4,%5,%6,%7}, {%8,%9}, {%0,%1,%2,%3};"
        : "+f"(c[0]), "+f"(c[1]), "+f"(c[2]), "+f"(c[3])
        : "r"(a[0]), "r"(a[1]), "r"(a[2]), "r"(a[3]), "r"(b[0]), "r"(b[1]));
}

// ---------------------------------------------------------------------------
// tf32 mma GEMM: C[M,N] = A[M,K] @ BT[N,K]^T  (A row-major, BT K-major; both
// tf32-pre-rounded). Block 128x256, 8 warps (2m x 4n) of 64x64 warp tiles,
// BK=16, double-buffered smem with conflict-free padded strides.
// ---------------------------------------------------------------------------
#define GBM 128
#define GBN 256
#define GBK 16
#define ASTR 20   // 20 mod 32 gives distinct bank bases for the 8 g-rows
#define BSTR 20
#define GEMM_SMEM ((2 * GBM * ASTR + 2 * GBN * BSTR) * 4)   // 61440 B

__global__ __launch_bounds__(256, 1) void gemm_mma(
    const float* __restrict__ A, const float* __restrict__ BT,
    float* __restrict__ C, int M, int N, int K)
{
    extern __shared__ float sm[];
    float* As0 = sm;
    float* As1 = sm + GBM * ASTR;
    float* Bs0 = sm + 2 * GBM * ASTR;
    float* Bs1 = Bs0 + GBN * BSTR;

    const int tid  = threadIdx.x;
    const int lane = tid & 31;
    const int wid  = tid >> 5;
    const int wm   = wid >> 2;           // 0..1
    const int wn   = wid & 3;            // 0..3
    const int g    = lane >> 2;          // 0..7
    const int tig  = lane & 3;           // 0..3
    const int bm   = blockIdx.y * GBM;
    const int bn   = blockIdx.x * GBN;

    // Loader mapping: A 128x16 (2 float4/thread), B 256x16 (4 float4/thread)
    const int arow = tid >> 1;
    const int acol = (tid & 1) * 8;
    const float* Ap = A  + (size_t)(bm + arow) * K + acol;
    const float* Bp = BT + (size_t)(bn + tid) * K;
    float* AsW0 = As0 + arow * ASTR + acol;
    float* AsW1 = As1 + arow * ASTR + acol;
    float* BsW0 = Bs0 + tid * BSTR;
    float* BsW1 = Bs1 + tid * BSTR;

    float c[4][8][4];
#pragma unroll
    for (int mt = 0; mt < 4; ++mt)
#pragma unroll
        for (int nt = 0; nt < 8; ++nt)
#pragma unroll
            for (int i = 0; i < 4; ++i) c[mt][nt][i] = 0.0f;

    // prologue: tile 0 -> buffer 0
    {
        float4 a0 = *(const float4*)(Ap);
        float4 a1 = *(const float4*)(Ap + 4);
        *(float4*)(AsW0)     = a0;
        *(float4*)(AsW0 + 4) = a1;
#pragma unroll
        for (int i = 0; i < 4; ++i)
            *(float4*)(BsW0 + i * 4) = *(const float4*)(Bp + i * 4);
    }
    __syncthreads();

    const int nkt = K / GBK;
#pragma unroll 1
    for (int kt = 0; kt < nkt; ++kt) {
        const float* Asc = (kt & 1) ? As1 : As0;
        const float* Bsc = (kt & 1) ? Bs1 : Bs0;
        float* Asn = (kt & 1) ? AsW0 : AsW1;
        float* Bsn = (kt & 1) ? BsW0 : BsW1;

        float4 pa0, pa1, pb[4];
        const bool more = (kt + 1 < nkt);
        if (more) {
            const float* ap = Ap + (kt + 1) * GBK;
            const float* bp = Bp + (kt + 1) * GBK;
            pa0 = *(const float4*)(ap);
            pa1 = *(const float4*)(ap + 4);
#pragma unroll
            for (int i = 0; i < 4; ++i) pb[i] = *(const float4*)(bp + i * 4);
        }

#pragma unroll
        for (int ks = 0; ks < 2; ++ks) {
            const int k0 = ks * 8;
            uint32_t af[4][4];
#pragma unroll
            for (int mt = 0; mt < 4; ++mt) {
                const int r = wm * 64 + mt * 16 + g;
                af[mt][0] = __float_as_uint(Asc[r * ASTR + k0 + tig]);
                af[mt][1] = __float_as_uint(Asc[(r + 8) * ASTR + k0 + tig]);
                af[mt][2] = __float_as_uint(Asc[r * ASTR + k0 + tig + 4]);
                af[mt][3] = __float_as_uint(Asc[(r + 8) * ASTR + k0 + tig + 4]);
            }
            uint32_t bf[8][2];
#pragma unroll
            for (int nt = 0; nt < 8; ++nt) {
                const int n = wn * 64 + nt * 8 + g;
                bf[nt][0] = __float_as_uint(Bsc[n * BSTR + k0 + tig]);
                bf[nt][1] = __float_as_uint(Bsc[n * BSTR + k0 + tig + 4]);
            }
#pragma unroll
            for (int mt = 0; mt < 4; ++mt)
#pragma unroll
                for (int nt = 0; nt < 8; ++nt)
                    mma_tf32(c[mt][nt], af[mt], bf[nt]);
        }

        if (more) {
            *(float4*)(Asn)     = pa0;
            *(float4*)(Asn + 4) = pa1;
#pragma unroll
            for (int i = 0; i < 4; ++i) *(float4*)(Bsn + i * 4) = pb[i];
        }
        __syncthreads();
    }

    // Epilogue: C fragment layout -> row-major gmem
#pragma unroll
    for (int mt = 0; mt < 4; ++mt) {
        const int r0 = bm + wm * 64 + mt * 16 + g;
#pragma unroll
        for (int nt = 0; nt < 8; ++nt) {
            const int cc = bn + wn * 64 + nt * 8 + tig * 2;
            *(float2*)&C[(size_t)r0 * N + cc]       = make_float2(c[mt][nt][0], c[mt][nt][1]);
            *(float2*)&C[(size_t)(r0 + 8) * N + cc] = make_float2(c[mt][nt][2], c[mt][nt][3]);
        }
    }
}

// ---------------------------------------------------------------------------
// Pre-passes
// ---------------------------------------------------------------------------
__global__ __launch_bounds__(256) void round_tf32_kernel(
    const float* __restrict__ in, float* __restrict__ out, int n4)
{
    int i = blockIdx.x * 256 + threadIdx.x;
    if (i < n4) {
        float4 v = ((const float4*)in)[i];
        v.x = rna_tf32(v.x); v.y = rna_tf32(v.y);
        v.z = rna_tf32(v.z); v.w = rna_tf32(v.w);
        ((float4*)out)[i] = v;
    }
}

// in: [K][N] row-major -> out: [N][K] row-major, tf32-rounded.
__global__ __launch_bounds__(256) void transpose_rna(
    const float* __restrict__ in, float* __restrict__ out, int K, int N)
{
    __shared__ float t[32][33];
    const int n0 = blockIdx.x * 32, k0 = blockIdx.y * 32;
    const int tx = threadIdx.x, ty = threadIdx.y;  // 32 x 8
#pragma unroll
    for (int i = ty; i < 32; i += 8)
        t[i][tx] = in[(size_t)(k0 + i) * N + n0 + tx];
    __syncthreads();
#pragma unroll
    for (int i = ty; i < 32; i += 8)
        out[(size_t)(n0 + i) * K + k0 + tx] = rna_tf32(t[tx][i]);
}

// ---------------------------------------------------------------------------
// RoPE + head-major transpose, tf32-rounded output (feeds mma attention).
// src: [S][srcStride] (pre-offset to the first head col); dst: [H][S][HD]
// ---------------------------------------------------------------------------
__global__ __launch_bounds__(128) void rope_transpose(
    const float* __restrict__ src, int srcStride,
    const float* __restrict__ cosp, const float* __restrict__ sinp,
    float* __restrict__ dst, int apply_rope)
{
    const int s = blockIdx.x;
    const int h = blockIdx.y;
    const int d = threadIdx.x;

    const float x = src[(size_t)s * srcStride + h * HD + d];
    float val;
    if (apply_rope) {
        const float p   = src[(size_t)s * srcStride + h * HD + (d ^ 64)];
        const float rot = (d < 64) ? -p : p;
        val = x * cosp[s * HD + d] + rot * sinp[s * HD + d];
    } else {
        val = x;
    }
    dst[((size_t)h * S_LEN + s) * HD + d] = rna_tf32(val);
}

// ---------------------------------------------------------------------------
// Flash attention on mma.sync tf32. BM=128, BN=64, 8 warps (16 q-rows each).
// smem strides chosen conflict-free for each fragment access pattern:
//   Qs/Ks stride 132 (=4 mod 32, rows indexed by g), Vs stride 136 (=8 mod 32,
//   rows indexed by tig), Ps stride 68 (=4 mod 32).
// ---------------------------------------------------------------------------
#define FA_QSTR 132
#define FA_KSTR 132
#define FA_VSTR 136
#define FA_PSTR 68
#define FA_QS 0
#define FA_KS (128 * FA_QSTR)                  // 16896
#define FA_VS (FA_KS + 64 * FA_KSTR)           // 25344
#define FA_PS (FA_VS + 64 * FA_VSTR)           // 34048
#define FA_SMEM ((FA_PS + 128 * FA_PSTR) * 4)  // 171008 B

__global__ __launch_bounds__(256, 1) void flash_mma(
    const float* __restrict__ Qh, const float* __restrict__ Kh,
    const float* __restrict__ Vh, float* __restrict__ O)
{
    extern __shared__ float sm[];
    float* Qs = sm + FA_QS;
    float* Ks = sm + FA_KS;
    float* Vs = sm + FA_VS;
    float* Ps = sm + FA_PS;

    const int tid  = threadIdx.x;
    const int lane = tid & 31;
    const int wid  = tid >> 5;           // warp_m: 0..7, 16 q-rows each
    const int g    = lane >> 2;
    const int tig  = lane & 3;
    const int qb   = blockIdx.x;         // 128-row query tile
    const int h    = blockIdx.y;
    const int kvh  = h >> 2;

    const float* Qbase = Qh + ((size_t)h * S_LEN + qb * 128) * HD;
    const float* Kbase = Kh + (size_t)kvh * S_LEN * HD;
    const float* Vbase = Vh + (size_t)kvh * S_LEN * HD;

    // Stage Q tile [128][128]
#pragma unroll
    for (int j = 0; j < 16; ++j) {
        const int idx = tid + j * 256;
        const int r = idx >> 5, cb = (idx & 31) * 4;
        *(float4*)&Qs[r * FA_QSTR + cb] = *(const float4*)(Qbase + (size_t)r * HD + cb);
    }

    float s[8][4], o[16][4], m_i[2], l_i[2];
    m_i[0] = m_i[1] = -1e30f;
    l_i[0] = l_i[1] = 0.0f;
#pragma unroll
    for (int nt = 0; nt < 16; ++nt)
#pragma unroll
        for (int i = 0; i < 4; ++i) o[nt][i] = 0.0f;

    const float sc = 0.08838834764831845f;  // 1/sqrt(128)
    const int qrow0 = qb * 128 + wid * 16 + g;
    const int jtmax = 2 * qb + 1;

    for (int jt = 0; jt <= jtmax; ++jt) {
        __syncthreads();  // prev iteration's PV reads of Vs/Ps complete
        // Stage K [64][128] and V [64][128]
#pragma unroll
        for (int j = 0; j < 8; ++j) {
            const int idx = tid + j * 256;
            const int r = idx >> 5, cb = (idx & 31) * 4;
            *(float4*)&Ks[r * FA_KSTR + cb] =
                *(const float4*)(Kbase + (size_t)(jt * 64 + r) * HD + cb);
            *(float4*)&Vs[r * FA_VSTR + cb] =
                *(const float4*)(Vbase + (size_t)(jt * 64 + r) * HD + cb);
        }
        __syncthreads();

        // S = Q K^T  (16 x 64 per warp)
#pragma unroll
        for (int nt = 0; nt < 8; ++nt)
#pragma unroll
            for (int i = 0; i < 4; ++i) s[nt][i] = 0.0f;

#pragma unroll
        for (int ks = 0; ks < 16; ++ks) {
            const int k0 = ks * 8;
            const int r = wid * 16 + g;
            uint32_t a[4];
            a[0] = __float_as_uint(Qs[r * FA_QSTR + k0 + tig]);
            a[1] = __float_as_uint(Qs[(r + 8) * FA_QSTR + k0 + tig]);
            a[2] = __float_as_uint(Qs[r * FA_QSTR + k0 + tig + 4]);
            a[3] = __float_as_uint(Qs[(r + 8) * FA_QSTR + k0 + tig + 4]);
#pragma unroll
            for (int nt = 0; nt < 8; ++nt) {
                const int n = nt * 8 + g;
                uint32_t b[2];
                b[0] = __float_as_uint(Ks[n * FA_KSTR + k0 + tig]);
                b[1] = __float_as_uint(Ks[n * FA_KSTR + k0 + tig + 4]);
                mma_tf32(s[nt], a, b);
            }
        }

        // Scale + causal mask (C frag: rows qrow0 / qrow0+8, cols 2*tig+{0,1})
        const int colb = jt * 64 + tig * 2;
#pragma unroll
        for (int nt = 0; nt < 8; ++nt) {
            const int c0 = colb + nt * 8, c1 = c0 + 1;
            s[nt][0] = (c0 > qrow0)     ? -1e30f : s[nt][0] * sc;
            s[nt][1] = (c1 > qrow0)     ? -1e30f : s[nt][1] * sc;
            s[nt][2] = (c0 > qrow0 + 8) ? -1e30f : s[nt][2] * sc;
            s[nt][3] = (c1 > qrow0 + 8) ? -1e30f : s[nt][3] * sc;
        }

        // Online softmax: two rows per thread, quad (xor 1,2) reductions
        float mx0 = -1e30f, mx1 = -1e30f;
#pragma unroll
        for (int nt = 0; nt < 8; ++nt) {
            mx0 = fmaxf(mx0, fmaxf(s[nt][0], s[nt][1]));
            mx1 = fmaxf(mx1, fmaxf(s[nt][2], s[nt][3]));
        }
        mx0 = fmaxf(mx0, __shfl_xor_sync(0xffffffffu, mx0, 1));
        mx0 = fmaxf(mx0, __shfl_xor_sync(0xffffffffu, mx0, 2));
        mx1 = fmaxf(mx1, __shfl_xor_sync(0xffffffffu, mx1, 1));
        mx1 = fmaxf(mx1, __shfl_xor_sync(0xffffffffu, mx1, 2));

        const float mn0 = fmaxf(m_i[0], mx0);
        const float mn1 = fmaxf(m_i[1], mx1);
        const float al0 = __expf(m_i[0] - mn0);
        const float al1 = __expf(m_i[1] - mn1);
        m_i[0] = mn0; m_i[1] = mn1;

        float rs0 = 0.0f, rs1 = 0.0f;
#pragma unroll
        for (int nt = 0; nt < 8; ++nt) {
            s[nt][0] = __expf(s[nt][0] - mn0);
            s[nt][1] = __expf(s[nt][1] - mn0);
            s[nt][2] = __expf(s[nt][2] - mn1);
            s[nt][3] = __expf(s[nt][3] - mn1);
            rs0 += s[nt][0] + s[nt][1];
            rs1 += s[nt][2] + s[nt][3];
        }
        rs0 += __shfl_xor_sync(0xffffffffu, rs0, 1);
        rs0 += __shfl_xor_sync(0xffffffffu, rs0, 2);
        rs1 += __shfl_xor_sync(0xffffffffu, rs1, 1);
        rs1 += __shfl_xor_sync(0xffffffffu, rs1, 2);
        l_i[0] = l_i[0] * al0 + rs0;
        l_i[1] = l_i[1] * al1 + rs1;
#pragma unroll
        for (int nt = 0; nt < 16; ++nt) {
            o[nt][0] *= al0; o[nt][1] *= al0;
            o[nt][2] *= al1; o[nt][3] *= al1;
        }

        // Stage P (tf32-rounded) for PV mma
        {
            const int r = wid * 16 + g;
#pragma unroll
            for (int nt = 0; nt < 8; ++nt) {
                const int cc = nt * 8 + tig * 2;
                *(float2*)&Ps[r * FA_PSTR + cc] =
                    make_float2(rna_tf32(s[nt][0]), rna_tf32(s[nt][1]));
                *(float2*)&Ps[(r + 8) * FA_PSTR + cc] =
                    make_float2(rna_tf32(s[nt][2]), rna_tf32(s[nt][3]));
            }
        }
        __syncthreads();

        // O += P @ V   (V used K-major directly as col-major B fragments)
#pragma unroll
        for (int ks = 0; ks < 8; ++ks) {
            const int k0 = ks * 8;
            const int r = wid * 16 + g;
            uint32_t a[4];
            a[0] = __float_as_uint(Ps[r * FA_PSTR + k0 + tig]);
            a[1] = __float_as_uint(Ps[(r + 8) * FA_PSTR + k0 + tig]);
            a[2] = __float_as_uint(Ps[r * FA_PSTR + k0 + tig + 4]);
            a[3] = __float_as_uint(Ps[(r + 8) * FA_PSTR + k0 + tig + 4]);
#pragma unroll
            for (int nt = 0; nt < 16; ++nt) {
                const int d = nt * 8 + g;
                uint32_t b[2];
                b[0] = __float_as_uint(Vs[(k0 + tig) * FA_VSTR + d]);
                b[1] = __float_as_uint(Vs[(k0 + tig + 4) * FA_VSTR + d]);
                mma_tf32(o[nt], a, b);
            }
        }
    }

    // Epilogue: normalize, tf32-round, write [S][NQ]
    const float inv0 = 1.0f / l_i[0];
    const float inv1 = 1.0f / l_i[1];
    float* Op = O + (size_t)qrow0 * NQ + h * HD;
#pragma unroll
    for (int nt = 0; nt < 16; ++nt) {
        const int cc = nt * 8 + tig * 2;
        *(float2*)&Op[cc] =
            make_float2(rna_tf32(o[nt][0] * inv0), rna_tf32(o[nt][1] * inv0));
        *(float2*)&Op[(size_t)8 * NQ + cc] =
            make_float2(rna_tf32(o[nt][2] * inv1), rna_tf32(o[nt][3] * inv1));
    }
}

// ---------------------------------------------------------------------------
// Launch. Inputs: 0 hidden_states, 1 attention_mask (unused), 2 wq, 3 wk,
// 4 wv, 5 wo, 6 cos, 7 sin.
// ---------------------------------------------------------------------------
extern "C" void kernel_launch(void* const* d_in, const int* in_sizes, int n_in,
                              void* d_out, int out_size)
{
    (void)in_sizes; (void)n_in; (void)out_size;
    const float* hs = (const float*)d_in[0];
    const float* wq = (const float*)d_in[2];
    const float* wk = (const float*)d_in[3];
    const float* wv = (const float*)d_in[4];
    const float* wo = (const float*)d_in[5];
    const float* cs = (const float*)d_in[6];
    const float* sn = (const float*)d_in[7];
    float* out = (float*)d_out;

    float *hsr, *wqT, *wkvT, *woT, *q, *kvp, *qh, *kh, *vh, *ao;
    cudaGetSymbolAddress((void**)&hsr,  g_hsr);
    cudaGetSymbolAddress((void**)&wqT,  g_wqT);
    cudaGetSymbolAddress((void**)&wkvT, g_wkvT);
    cudaGetSymbolAddress((void**)&woT,  g_woT);
    cudaGetSymbolAddress((void**)&q,    g_q);
    cudaGetSymbolAddress((void**)&kvp,  g_kvp);
    cudaGetSymbolAddress((void**)&qh,   g_qh);
    cudaGetSymbolAddress((void**)&kh,   g_kh);
    cudaGetSymbolAddress((void**)&vh,   g_vh);
    cudaGetSymbolAddress((void**)&ao,   g_ao);

    cudaFuncSetAttribute(gemm_mma,  cudaFuncAttributeMaxDynamicSharedMemorySize, GEMM_SMEM);
    cudaFuncSetAttribute(flash_mma, cudaFuncAttributeMaxDynamicSharedMemorySize, FA_SMEM);

    // Pre-passes: tf32 rounding + K-major weight transposes (wk/wv fused)
    round_tf32_kernel<<<(S_LEN * HID / 4 + 255) / 256, 256>>>(hs, hsr, S_LEN * HID / 4);
    transpose_rna<<<dim3(NQ / 32,   HID / 32), dim3(32, 8)>>>(wq, wqT, HID, NQ);
    transpose_rna<<<dim3(NKVD / 32, HID / 32), dim3(32, 8)>>>(wk, wkvT, HID, NKVD);
    transpose_rna<<<dim3(NKVD / 32, HID / 32), dim3(32, 8)>>>(wv, wkvT + (size_t)NKVD * HID, HID, NKVD);
    transpose_rna<<<dim3(HID / 32,  NQ / 32),  dim3(32, 8)>>>(wo, woT, NQ, HID);

    // Projections (K and V fused into one N=2048 GEMM)
    gemm_mma<<<dim3(NQ / GBN, S_LEN / GBM), 256, GEMM_SMEM>>>(hsr, wqT, q, S_LEN, NQ, HID);
    gemm_mma<<<dim3(2 * NKVD / GBN, S_LEN / GBM), 256, GEMM_SMEM>>>(hsr, wkvT, kvp, S_LEN, 2 * NKVD, HID);

    // RoPE + head-major transpose (tf32-rounded outputs)
    rope_transpose<<<dim3(S_LEN, NH),  128>>>(q,          NQ,       cs, sn, qh, 1);
    rope_transpose<<<dim3(S_LEN, NKV), 128>>>(kvp,        2 * NKVD, cs, sn, kh, 1);
    rope_transpose<<<dim3(S_LEN, NKV), 128>>>(kvp + NKVD, 2 * NKVD, cs, sn, vh, 0);

    // Flash attention on tensor cores
    flash_mma<<<dim3(S_LEN / 128, NH), 256, FA_SMEM>>>(qh, kh, vh, ao);

    // Output projection
    gemm_mma<<<dim3(HID / GBN, S_LEN / GBM), 256, GEMM_SMEM>>>(ao, woT, out, S_LEN, HID, NQ);
}

// round 7
// speedup vs baseline: 3.5281x; 1.6196x over previous
#include <cuda_runtime.h>
#include <cuda_bf16.h>
#include <math.h>
#include <stdint.h>

// Problem constants
#define S_LEN 2048
#define HID   4096
#define NH    32
#define NKV   8
#define HD    128
#define NQ    (NH * HD)    // 4096
#define NKVD  (NKV * HD)   // 1024

// ---------------------------------------------------------------------------
// Scratch (static device arrays; no cudaMalloc allowed)
// ---------------------------------------------------------------------------
__device__ float g_hsr [S_LEN * HID];      // hidden states, tf32-rounded
__device__ float g_wqT [NQ * HID];         // wq^T  [4096][4096]
__device__ float g_wkvT[2 * NKVD * HID];   // [wk^T ; wv^T]  [2048][4096]
__device__ float g_woT [HID * NQ];         // wo^T  [4096][4096]
__device__ float g_q   [S_LEN * NQ];       // Q projection [S][4096]
__device__ float g_kvp [S_LEN * 2 * NKVD]; // KV projection [S][2048]
__device__ float g_qh  [S_LEN * NQ];       // Q rope, head-major [NH][S][HD]
__device__ float g_kh  [S_LEN * NKVD];     // K rope, head-major [NKV][S][HD]
__device__ float g_vt  [S_LEN * NKVD];     // V^T head-major [NKV][HD][S]
__device__ float g_ao  [S_LEN * NQ];       // attention out [S][4096]

// ---------------------------------------------------------------------------
// Helpers
// ---------------------------------------------------------------------------
__device__ __forceinline__ uint32_t smem_u32(const void* p) {
    uint32_t a;
    asm("{ .reg .u64 t; cvta.to.shared.u64 t, %1; cvt.u32.u64 %0, t; }"
        : "=r"(a) : "l"(p));
    return a;
}
__device__ __forceinline__ float rna_tf32(float v) {
    uint32_t o;
    asm("cvt.rna.tf32.f32 %0, %1;" : "=r"(o) : "f"(v));
    return __uint_as_float(o);
}
__device__ __forceinline__ void mma_tf32(float* c, const uint32_t* a, const uint32_t* b) {
    asm("mma.sync.aligned.m16n8k8.row.col.f32.tf32.tf32.f32 "
        "{%0,%1,%2,%3}, {%4,%5,%6,%7}, {%8,%9}, {%0,%1,%2,%3};"
        : "+f"(c[0]), "+f"(c[1]), "+f"(c[2]), "+f"(c[3])
        : "r"(a[0]), "r"(a[1]), "r"(a[2]), "r"(a[3]), "r"(b[0]), "r"(b[1]));
}
__device__ __forceinline__ void ldsm_x4(uint32_t* r, uint32_t saddr) {
    asm volatile("ldmatrix.sync.aligned.m8n8.x4.shared.b16 {%0,%1,%2,%3}, [%4];"
        : "=r"(r[0]), "=r"(r[1]), "=r"(r[2]), "=r"(r[3]) : "r"(saddr));
}
__device__ __forceinline__ void cpasync16(uint32_t dst, const void* src) {
    asm volatile("cp.async.cg.shared.global [%0], [%1], 16;" :: "r"(dst), "l"(src));
}
#define CP_COMMIT()  asm volatile("cp.async.commit_group;" ::: "memory")
#define CP_WAIT0()   asm volatile("cp.async.wait_group 0;" ::: "memory")
#define CP_WAIT1()   asm volatile("cp.async.wait_group 1;" ::: "memory")

// ---------------------------------------------------------------------------
// tf32 mma GEMM: C[M,N] = A[M,K] @ BT[N,K]^T (A row-major, BT K-major, both
// tf32-pre-rounded). Block 128x256, 8 warps (2m x 4n) of 64x64 warp tiles,
// BK=32, 3-stage cp.async pipeline, ldmatrix fragment loads.
// ---------------------------------------------------------------------------
#define GBM 128
#define GBN 256
#define GBK 32
#define ASTR 36               // floats; 36%8=4 -> conflict-free LDSM row groups
#define BSTR 36
#define A_ST (128 * ASTR)     // 4608 floats per A stage
#define B_ST (256 * BSTR)     // 9216 floats per B stage
#define STAGE_FL (A_ST + B_ST)
#define GEMM_SMEM (3 * STAGE_FL * 4)   // 165888 B

__device__ __forceinline__ void gemm_load_stage(
    uint32_t a_dst, uint32_t b_dst, const float* ap, const float* bp, int K)
{
#pragma unroll
    for (int i = 0; i < 4; ++i)
        cpasync16(a_dst + i * 32 * ASTR * 4, ap + (size_t)i * 32 * K);
#pragma unroll
    for (int i = 0; i < 8; ++i)
        cpasync16(b_dst + i * 32 * BSTR * 4, bp + (size_t)i * 32 * K);
}

__global__ __launch_bounds__(256, 1) void gemm_mma(
    const float* __restrict__ A, const float* __restrict__ BT,
    float* __restrict__ C, int M, int N, int K)
{
    extern __shared__ float sm[];
    const uint32_t sb = smem_u32(sm);

    const int tid  = threadIdx.x;
    const int lane = tid & 31;
    const int wid  = tid >> 5;
    const int wm   = wid >> 2;
    const int wn   = wid & 3;
    const int g    = lane >> 2;
    const int tig  = lane & 3;
    const int bm   = blockIdx.y * GBM;
    const int bn   = blockIdx.x * GBN;

    // Loader: thread covers rows lrow+32i, cols lcol..lcol+3 of the BK slab
    const int lrow = tid >> 3;
    const int lcol = (tid & 7) * 4;
    const float* Ap = A  + (size_t)(bm + lrow) * K + lcol;
    const float* Bp = BT + (size_t)(bn + lrow) * K + lcol;
    const uint32_t a_dst = sb + (uint32_t)(lrow * ASTR + lcol) * 4;
    const uint32_t b_dst = sb + (uint32_t)(A_ST + lrow * BSTR + lcol) * 4;

    // ldmatrix per-lane addresses
    const int a_r = wm * 64 + (lane & 7) + ((lane >> 3) & 1) * 8;
    const int a_c = (lane >> 4) * 4;
    const uint32_t a_frag = sb + (uint32_t)(a_r * ASTR + a_c) * 4;
    const int b_r = wn * 64 + ((lane >> 4) & 1) * 8 + (lane & 7);
    const int b_c = ((lane >> 3) & 1) * 4;
    const uint32_t b_frag = sb + (uint32_t)(A_ST + b_r * BSTR + b_c) * 4;

    float c[4][8][4];
#pragma unroll
    for (int mt = 0; mt < 4; ++mt)
#pragma unroll
        for (int nt = 0; nt < 8; ++nt)
#pragma unroll
            for (int i = 0; i < 4; ++i) c[mt][nt][i] = 0.0f;

    const int nkt = K / GBK;
    gemm_load_stage(a_dst, b_dst, Ap, Bp, K); CP_COMMIT();
    gemm_load_stage(a_dst + STAGE_FL * 4, b_dst + STAGE_FL * 4,
                    Ap + GBK, Bp + GBK, K); CP_COMMIT();

#pragma unroll 1
    for (int kt = 0; kt < nkt; ++kt) {
        if (kt + 1 < nkt) { CP_WAIT1(); } else { CP_WAIT0(); }
        __syncthreads();
        if (kt + 2 < nkt) {
            const uint32_t so = (uint32_t)((kt + 2) % 3) * STAGE_FL * 4;
            gemm_load_stage(a_dst + so, b_dst + so,
                            Ap + (kt + 2) * GBK, Bp + (kt + 2) * GBK, K);
        }
        CP_COMMIT();

        const uint32_t so = (uint32_t)(kt % 3) * STAGE_FL * 4;
#pragma unroll
        for (int ks = 0; ks < 4; ++ks) {
            uint32_t af[4][4];
#pragma unroll
            for (int mt = 0; mt < 4; ++mt)
                ldsm_x4(af[mt], a_frag + so + (uint32_t)(mt * 16 * ASTR + ks * 8) * 4);
            uint32_t bf[8][2];
#pragma unroll
            for (int p = 0; p < 4; ++p) {
                uint32_t t4[4];
                ldsm_x4(t4, b_frag + so + (uint32_t)(p * 16 * BSTR + ks * 8) * 4);
                bf[2 * p][0] = t4[0]; bf[2 * p][1] = t4[1];
                bf[2 * p + 1][0] = t4[2]; bf[2 * p + 1][1] = t4[3];
            }
#pragma unroll
            for (int mt = 0; mt < 4; ++mt)
#pragma unroll
                for (int nt = 0; nt < 8; ++nt)
                    mma_tf32(c[mt][nt], af[mt], bf[nt]);
        }
    }

    // Epilogue
#pragma unroll
    for (int mt = 0; mt < 4; ++mt) {
        const int r0 = bm + wm * 64 + mt * 16 + g;
#pragma unroll
        for (int nt = 0; nt < 8; ++nt) {
            const int cc = bn + wn * 64 + nt * 8 + tig * 2;
            *(float2*)&C[(size_t)r0 * N + cc]       = make_float2(c[mt][nt][0], c[mt][nt][1]);
            *(float2*)&C[(size_t)(r0 + 8) * N + cc] = make_float2(c[mt][nt][2], c[mt][nt][3]);
        }
    }
}

// ---------------------------------------------------------------------------
// Pre-passes
// ---------------------------------------------------------------------------
__global__ __launch_bounds__(256) void round_tf32_kernel(
    const float* __restrict__ in, float* __restrict__ out, int n4)
{
    int i = blockIdx.x * 256 + threadIdx.x;
    if (i < n4) {
        float4 v = ((const float4*)in)[i];
        v.x = rna_tf32(v.x); v.y = rna_tf32(v.y);
        v.z = rna_tf32(v.z); v.w = rna_tf32(v.w);
        ((float4*)out)[i] = v;
    }
}

// in: [K][N] row-major -> out: [N][K] row-major, tf32-rounded.
__global__ __launch_bounds__(256) void transpose_rna(
    const float* __restrict__ in, float* __restrict__ out, int K, int N)
{
    __shared__ float t[32][33];
    const int n0 = blockIdx.x * 32, k0 = blockIdx.y * 32;
    const int tx = threadIdx.x, ty = threadIdx.y;  // 32 x 8
#pragma unroll
    for (int i = ty; i < 32; i += 8)
        t[i][tx] = in[(size_t)(k0 + i) * N + n0 + tx];
    __syncthreads();
#pragma unroll
    for (int i = ty; i < 32; i += 8)
        out[(size_t)(n0 + i) * K + k0 + tx] = rna_tf32(t[tx][i]);
}

// V^T pass: out[n][s] = rna(in[s][n]), in stride 2*NKVD (V columns of kvp).
__global__ __launch_bounds__(256) void transpose_vt(
    const float* __restrict__ in, float* __restrict__ out)
{
    __shared__ float t[32][33];
    const int n0 = blockIdx.x * 32, s0 = blockIdx.y * 32;
    const int tx = threadIdx.x, ty = threadIdx.y;  // 32 x 8
#pragma unroll
    for (int i = ty; i < 32; i += 8)
        t[i][tx] = in[(size_t)(s0 + i) * (2 * NKVD) + n0 + tx];
    __syncthreads();
#pragma unroll
    for (int i = ty; i < 32; i += 8)
        out[(size_t)(n0 + i) * S_LEN + s0 + tx] = rna_tf32(t[tx][i]);
}

// ---------------------------------------------------------------------------
// RoPE + head-major transpose, tf32-rounded output.
// ---------------------------------------------------------------------------
__global__ __launch_bounds__(128) void rope_transpose(
    const float* __restrict__ src, int srcStride,
    const float* __restrict__ cosp, const float* __restrict__ sinp,
    float* __restrict__ dst)
{
    const int s = blockIdx.x;
    const int h = blockIdx.y;
    const int d = threadIdx.x;

    const float x   = src[(size_t)s * srcStride + h * HD + d];
    const float p   = src[(size_t)s * srcStride + h * HD + (d ^ 64)];
    const float rot = (d < 64) ? -p : p;
    const float val = x * cosp[s * HD + d] + rot * sinp[s * HD + d];
    dst[((size_t)h * S_LEN + s) * HD + d] = rna_tf32(val);
}

// ---------------------------------------------------------------------------
// Flash attention on mma.sync tf32 + ldmatrix. BM=128, BN=64, 8 warps.
// Q [128][132], K [64][132], V^T [128][68] (d-major), P [128][68].
// ---------------------------------------------------------------------------
#define FA_QSTR 132
#define FA_KSTR 132
#define FA_VSTR 68
#define FA_PSTR 68
#define FA_QS 0
#define FA_KS (128 * FA_QSTR)               // 16896
#define FA_VT (FA_KS + 64 * FA_KSTR)        // 25344
#define FA_PS (FA_VT + 128 * FA_VSTR)       // 34048
#define FA_SMEM ((FA_PS + 128 * FA_PSTR) * 4)   // 171008 B

__global__ __launch_bounds__(256, 1) void flash_mma(
    const float* __restrict__ Qh, const float* __restrict__ Kh,
    const float* __restrict__ VT, float* __restrict__ O)
{
    extern __shared__ float sm[];
    const uint32_t sb = smem_u32(sm);

    const int tid  = threadIdx.x;
    const int lane = tid & 31;
    const int wid  = tid >> 5;
    const int g    = lane >> 2;
    const int tig  = lane & 3;
    const int qb   = blockIdx.x;
    const int h    = blockIdx.y;
    const int kvh  = h >> 2;

    const float* Qbase  = Qh + ((size_t)h * S_LEN + qb * 128) * HD;
    const float* Kbase  = Kh + (size_t)kvh * S_LEN * HD;
    const float* VTbase = VT + (size_t)kvh * HD * S_LEN;

    // Stage Q tile [128][128]
#pragma unroll
    for (int j = 0; j < 16; ++j) {
        const int idx = tid + j * 256;
        const int r = idx >> 5, cb = (idx & 31) * 4;
        *(float4*)&sm[FA_QS + r * FA_QSTR + cb] =
            *(const float4*)(Qbase + (size_t)r * HD + cb);
    }

    // cp.async staging offsets
    const int krow = tid >> 5;             // +8j
    const int kcb  = (tid & 31) * 4;
    const int vrow = tid >> 4;             // +16j
    const int vkk  = (tid & 15) * 4;

    // ldmatrix per-lane bases
    const int rsel = (lane & 7) + ((lane >> 3) & 1) * 8;
    const int csel = (lane >> 4) * 4;
    const int brsel = ((lane >> 4) & 1) * 8 + (lane & 7);
    const int bcsel = ((lane >> 3) & 1) * 4;
    const uint32_t q_frag = sb + (uint32_t)(FA_QS + (wid * 16 + rsel) * FA_QSTR + csel) * 4;
    const uint32_t k_frag = sb + (uint32_t)(FA_KS + brsel * FA_KSTR + bcsel) * 4;
    const uint32_t v_frag = sb + (uint32_t)(FA_VT + brsel * FA_VSTR + bcsel) * 4;
    const uint32_t p_frag = sb + (uint32_t)(FA_PS + (wid * 16 + rsel) * FA_PSTR + csel) * 4;

    float s[8][4], o[16][4], m_i[2], l_i[2];
    m_i[0] = m_i[1] = -1e30f;
    l_i[0] = l_i[1] = 0.0f;
#pragma unroll
    for (int nt = 0; nt < 16; ++nt)
#pragma unroll
        for (int i = 0; i < 4; ++i) o[nt][i] = 0.0f;

    const float sc = 0.08838834764831845f;  // 1/sqrt(128)
    const int qrow0 = qb * 128 + wid * 16 + g;
    const int jtmax = 2 * qb + 1;

    for (int jt = 0; jt <= jtmax; ++jt) {
        __syncthreads();  // everyone done reading Ks/VTs of jt-1
        // Stage K [64][128] and V^T [128][64] via cp.async
#pragma unroll
        for (int j = 0; j < 8; ++j) {
            const int r = krow + 8 * j;
            cpasync16(sb + (uint32_t)(FA_KS + r * FA_KSTR + kcb) * 4,
                      Kbase + (size_t)(jt * 64 + r) * HD + kcb);
        }
#pragma unroll
        for (int j = 0; j < 8; ++j) {
            const int d = vrow + 16 * j;
            cpasync16(sb + (uint32_t)(FA_VT + d * FA_VSTR + vkk) * 4,
                      VTbase + (size_t)d * S_LEN + jt * 64 + vkk);
        }
        CP_COMMIT(); CP_WAIT0();
        __syncthreads();

        // S = Q K^T  (16 x 64 per warp)
#pragma unroll
        for (int nt = 0; nt < 8; ++nt)
#pragma unroll
            for (int i = 0; i < 4; ++i) s[nt][i] = 0.0f;

#pragma unroll
        for (int ks = 0; ks < 16; ++ks) {
            uint32_t a[4];
            ldsm_x4(a, q_frag + ks * 32);
#pragma unroll
            for (int p = 0; p < 4; ++p) {
                uint32_t t4[4];
                ldsm_x4(t4, k_frag + (uint32_t)(p * 16 * FA_KSTR) * 4 + ks * 32);
                mma_tf32(s[2 * p],     a, t4);
                mma_tf32(s[2 * p + 1], a, t4 + 2);
            }
        }

        // Scale + causal mask
        const int colb = jt * 64 + tig * 2;
#pragma unroll
        for (int nt = 0; nt < 8; ++nt) {
            const int c0 = colb + nt * 8, c1 = c0 + 1;
            s[nt][0] = (c0 > qrow0)     ? -1e30f : s[nt][0] * sc;
            s[nt][1] = (c1 > qrow0)     ? -1e30f : s[nt][1] * sc;
            s[nt][2] = (c0 > qrow0 + 8) ? -1e30f : s[nt][2] * sc;
            s[nt][3] = (c1 > qrow0 + 8) ? -1e30f : s[nt][3] * sc;
        }

        // Online softmax
        float mx0 = -1e30f, mx1 = -1e30f;
#pragma unroll
        for (int nt = 0; nt < 8; ++nt) {
            mx0 = fmaxf(mx0, fmaxf(s[nt][0], s[nt][1]));
            mx1 = fmaxf(mx1, fmaxf(s[nt][2], s[nt][3]));
        }
        mx0 = fmaxf(mx0, __shfl_xor_sync(0xffffffffu, mx0, 1));
        mx0 = fmaxf(mx0, __shfl_xor_sync(0xffffffffu, mx0, 2));
        mx1 = fmaxf(mx1, __shfl_xor_sync(0xffffffffu, mx1, 1));
        mx1 = fmaxf(mx1, __shfl_xor_sync(0xffffffffu, mx1, 2));

        const float mn0 = fmaxf(m_i[0], mx0);
        const float mn1 = fmaxf(m_i[1], mx1);
        const float al0 = __expf(m_i[0] - mn0);
        const float al1 = __expf(m_i[1] - mn1);
        m_i[0] = mn0; m_i[1] = mn1;

        float rs0 = 0.0f, rs1 = 0.0f;
#pragma unroll
        for (int nt = 0; nt < 8; ++nt) {
            s[nt][0] = __expf(s[nt][0] - mn0);
            s[nt][1] = __expf(s[nt][1] - mn0);
            s[nt][2] = __expf(s[nt][2] - mn1);
            s[nt][3] = __expf(s[nt][3] - mn1);
            rs0 += s[nt][0] + s[nt][1];
            rs1 += s[nt][2] + s[nt][3];
        }
        rs0 += __shfl_xor_sync(0xffffffffu, rs0, 1);
        rs0 += __shfl_xor_sync(0xffffffffu, rs0, 2);
        rs1 += __shfl_xor_sync(0xffffffffu, rs1, 1);
        rs1 += __shfl_xor_sync(0xffffffffu, rs1, 2);
        l_i[0] = l_i[0] * al0 + rs0;
        l_i[1] = l_i[1] * al1 + rs1;
#pragma unroll
        for (int nt = 0; nt < 16; ++nt) {
            o[nt][0] *= al0; o[nt][1] *= al0;
            o[nt][2] *= al1; o[nt][3] *= al1;
        }

        // Stage P (tf32-rounded). P rows are warp-private -> __syncwarp only.
        {
            const int r = wid * 16 + g;
#pragma unroll
            for (int nt = 0; nt < 8; ++nt) {
                const int cc = nt * 8 + tig * 2;
                *(float2*)&sm[FA_PS + r * FA_PSTR + cc] =
                    make_float2(rna_tf32(s[nt][0]), rna_tf32(s[nt][1]));
                *(float2*)&sm[FA_PS + (r + 8) * FA_PSTR + cc] =
                    make_float2(rna_tf32(s[nt][2]), rna_tf32(s[nt][3]));
            }
        }
        __syncwarp();

        // O += P @ V   (V^T d-major -> LDSM B fragments)
#pragma unroll
        for (int ks = 0; ks < 8; ++ks) {
            uint32_t a[4];
            ldsm_x4(a, p_frag + ks * 32);
#pragma unroll
            for (int p = 0; p < 8; ++p) {
                uint32_t t4[4];
                ldsm_x4(t4, v_frag + (uint32_t)(p * 16 * FA_VSTR) * 4 + ks * 32);
                mma_tf32(o[2 * p],     a, t4);
                mma_tf32(o[2 * p + 1], a, t4 + 2);
            }
        }
    }

    // Epilogue: normalize, tf32-round, write [S][NQ]
    const float inv0 = 1.0f / l_i[0];
    const float inv1 = 1.0f / l_i[1];
    float* Op = O + (size_t)qrow0 * NQ + h * HD;
#pragma unroll
    for (int nt = 0; nt < 16; ++nt) {
        const int cc = nt * 8 + tig * 2;
        *(float2*)&Op[cc] =
            make_float2(rna_tf32(o[nt][0] * inv0), rna_tf32(o[nt][1] * inv0));
        *(float2*)&Op[(size_t)8 * NQ + cc] =
            make_float2(rna_tf32(o[nt][2] * inv1), rna_tf32(o[nt][3] * inv1));
    }
}

// ---------------------------------------------------------------------------
// Launch. Inputs: 0 hidden_states, 1 attention_mask (unused), 2 wq, 3 wk,
// 4 wv, 5 wo, 6 cos, 7 sin.
// ---------------------------------------------------------------------------
extern "C" void kernel_launch(void* const* d_in, const int* in_sizes, int n_in,
                              void* d_out, int out_size)
{
    (void)in_sizes; (void)n_in; (void)out_size;
    const float* hs = (const float*)d_in[0];
    const float* wq = (const float*)d_in[2];
    const float* wk = (const float*)d_in[3];
    const float* wv = (const float*)d_in[4];
    const float* wo = (const float*)d_in[5];
    const float* cs = (const float*)d_in[6];
    const float* sn = (const float*)d_in[7];
    float* out = (float*)d_out;

    float *hsr, *wqT, *wkvT, *woT, *q, *kvp, *qh, *kh, *vt, *ao;
    cudaGetSymbolAddress((void**)&hsr,  g_hsr);
    cudaGetSymbolAddress((void**)&wqT,  g_wqT);
    cudaGetSymbolAddress((void**)&wkvT, g_wkvT);
    cudaGetSymbolAddress((void**)&woT,  g_woT);
    cudaGetSymbolAddress((void**)&q,    g_q);
    cudaGetSymbolAddress((void**)&kvp,  g_kvp);
    cudaGetSymbolAddress((void**)&qh,   g_qh);
    cudaGetSymbolAddress((void**)&kh,   g_kh);
    cudaGetSymbolAddress((void**)&vt,   g_vt);
    cudaGetSymbolAddress((void**)&ao,   g_ao);

    cudaFuncSetAttribute(gemm_mma,  cudaFuncAttributeMaxDynamicSharedMemorySize, GEMM_SMEM);
    cudaFuncSetAttribute(flash_mma, cudaFuncAttributeMaxDynamicSharedMemorySize, FA_SMEM);

    // Pre-passes
    round_tf32_kernel<<<(S_LEN * HID / 4 + 255) / 256, 256>>>(hs, hsr, S_LEN * HID / 4);
    transpose_rna<<<dim3(NQ / 32,   HID / 32), dim3(32, 8)>>>(wq, wqT, HID, NQ);
    transpose_rna<<<dim3(NKVD / 32, HID / 32), dim3(32, 8)>>>(wk, wkvT, HID, NKVD);
    transpose_rna<<<dim3(NKVD / 32, HID / 32), dim3(32, 8)>>>(wv, wkvT + (size_t)NKVD * HID, HID, NKVD);
    transpose_rna<<<dim3(HID / 32,  NQ / 32),  dim3(32, 8)>>>(wo, woT, NQ, HID);

    // Projections (K and V fused into one N=2048 GEMM)
    gemm_mma<<<dim3(NQ / GBN, S_LEN / GBM), 256, GEMM_SMEM>>>(hsr, wqT, q, S_LEN, NQ, HID);
    gemm_mma<<<dim3(2 * NKVD / GBN, S_LEN / GBM), 256, GEMM_SMEM>>>(hsr, wkvT, kvp, S_LEN, 2 * NKVD, HID);

    // RoPE + head-major (Q, K); V -> transposed [NKV][HD][S]
    rope_transpose<<<dim3(S_LEN, NH),  128>>>(q,   NQ,       cs, sn, qh);
    rope_transpose<<<dim3(S_LEN, NKV), 128>>>(kvp, 2 * NKVD, cs, sn, kh);
    transpose_vt<<<dim3(NKVD / 32, S_LEN / 32), dim3(32, 8)>>>(kvp + NKVD, vt);

    // Flash attention on tensor cores
    flash_mma<<<dim3(S_LEN / 128, NH), 256, FA_SMEM>>>(qh, kh, vt, ao);

    // Output projection
    gemm_mma<<<dim3(HID / GBN, S_LEN / GBM), 256, GEMM_SMEM>>>(ao, woT, out, S_LEN, NQ, NQ);
}

// round 8
// speedup vs baseline: 3.5886x; 1.0172x over previous
#include <cuda_runtime.h>
#include <cuda_bf16.h>
#include <math.h>
#include <stdint.h>

// Problem constants
#define S_LEN 2048
#define HID   4096
#define NH    32
#define NKV   8
#define HD    128
#define NQ    (NH * HD)    // 4096
#define NKVD  (NKV * HD)   // 1024

// ---------------------------------------------------------------------------
// Scratch (static device arrays; no cudaMalloc allowed)
// ---------------------------------------------------------------------------
__device__ float g_hsr [S_LEN * HID];      // hidden states, tf32-rounded
__device__ float g_wqT [NQ * HID];         // wq^T  [4096][4096]
__device__ float g_wkvT[2 * NKVD * HID];   // [wk^T ; wv^T]  [2048][4096]
__device__ float g_woT [HID * NQ];         // wo^T  [4096][4096]
__device__ float g_q   [S_LEN * NQ];       // Q projection [S][4096]
__device__ float g_kvp [S_LEN * 2 * NKVD]; // KV projection [S][2048]
__device__ float g_qh  [S_LEN * NQ];       // Q rope, head-major [NH][S][HD]
__device__ float g_kh  [S_LEN * NKVD];     // K rope, head-major [NKV][S][HD]
__device__ float g_vt  [S_LEN * NKVD];     // V^T head-major [NKV][HD][S]
__device__ float g_ao  [S_LEN * NQ];       // attention out [S][4096]

// ---------------------------------------------------------------------------
// Helpers
// ---------------------------------------------------------------------------
__device__ __forceinline__ uint32_t smem_u32(const void* p) {
    uint32_t a;
    asm("{ .reg .u64 t; cvta.to.shared.u64 t, %1; cvt.u32.u64 %0, t; }"
        : "=r"(a) : "l"(p));
    return a;
}
__device__ __forceinline__ float rna_tf32(float v) {
    uint32_t o;
    asm("cvt.rna.tf32.f32 %0, %1;" : "=r"(o) : "f"(v));
    return __uint_as_float(o);
}
__device__ __forceinline__ void mma_tf32(float* c, const uint32_t* a, const uint32_t* b) {
    asm("mma.sync.aligned.m16n8k8.row.col.f32.tf32.tf32.f32 "
        "{%0,%1,%2,%3}, {%4,%5,%6,%7}, {%8,%9}, {%0,%1,%2,%3};"
        : "+f"(c[0]), "+f"(c[1]), "+f"(c[2]), "+f"(c[3])
        : "r"(a[0]), "r"(a[1]), "r"(a[2]), "r"(a[3]), "r"(b[0]), "r"(b[1]));
}
__device__ __forceinline__ void ldsm_x4(uint32_t* r, uint32_t saddr) {
    asm volatile("ldmatrix.sync.aligned.m8n8.x4.shared.b16 {%0,%1,%2,%3}, [%4];"
        : "=r"(r[0]), "=r"(r[1]), "=r"(r[2]), "=r"(r[3]) : "r"(saddr));
}
__device__ __forceinline__ void cpasync16(uint32_t dst, const void* src) {
    asm volatile("cp.async.cg.shared.global [%0], [%1], 16;" :: "r"(dst), "l"(src));
}
#define CP_COMMIT()  asm volatile("cp.async.commit_group;" ::: "memory")
#define CP_WAIT0()   asm volatile("cp.async.wait_group 0;" ::: "memory")
#define CP_WAIT1()   asm volatile("cp.async.wait_group 1;" ::: "memory")

// ---------------------------------------------------------------------------
// tf32 mma GEMM: C[M,N] = A[M,K] @ BT[N,K]^T (A row-major, BT K-major, both
// tf32-pre-rounded). Block 128x256, 8 warps (2m x 4n) of 64x64 warp tiles,
// BK=32, 3-stage cp.async pipeline, ldmatrix fragment loads.
// ---------------------------------------------------------------------------
#define GBM 128
#define GBN 256
#define GBK 32
#define ASTR 36               // floats; 36%8=4 -> conflict-free LDSM row groups
#define BSTR 36
#define A_ST (128 * ASTR)     // 4608 floats per A stage
#define B_ST (256 * BSTR)     // 9216 floats per B stage
#define STAGE_FL (A_ST + B_ST)
#define GEMM_SMEM (3 * STAGE_FL * 4)   // 165888 B

__device__ __forceinline__ void gemm_load_stage(
    uint32_t a_dst, uint32_t b_dst, const float* ap, const float* bp, int K)
{
#pragma unroll
    for (int i = 0; i < 4; ++i)
        cpasync16(a_dst + i * 32 * ASTR * 4, ap + (size_t)i * 32 * K);
#pragma unroll
    for (int i = 0; i < 8; ++i)
        cpasync16(b_dst + i * 32 * BSTR * 4, bp + (size_t)i * 32 * K);
}

__global__ __launch_bounds__(256, 1) void gemm_mma(
    const float* __restrict__ A, const float* __restrict__ BT,
    float* __restrict__ C, int M, int N, int K)
{
    extern __shared__ float sm[];
    const uint32_t sb = smem_u32(sm);

    const int tid  = threadIdx.x;
    const int lane = tid & 31;
    const int wid  = tid >> 5;
    const int wm   = wid >> 2;
    const int wn   = wid & 3;
    const int g    = lane >> 2;
    const int tig  = lane & 3;
    const int bm   = blockIdx.y * GBM;
    const int bn   = blockIdx.x * GBN;

    // Loader: thread covers rows lrow+32i, cols lcol..lcol+3 of the BK slab
    const int lrow = tid >> 3;
    const int lcol = (tid & 7) * 4;
    const float* Ap = A  + (size_t)(bm + lrow) * K + lcol;
    const float* Bp = BT + (size_t)(bn + lrow) * K + lcol;
    const uint32_t a_dst = sb + (uint32_t)(lrow * ASTR + lcol) * 4;
    const uint32_t b_dst = sb + (uint32_t)(A_ST + lrow * BSTR + lcol) * 4;

    // ldmatrix per-lane addresses
    const int a_r = wm * 64 + (lane & 7) + ((lane >> 3) & 1) * 8;
    const int a_c = (lane >> 4) * 4;
    const uint32_t a_frag = sb + (uint32_t)(a_r * ASTR + a_c) * 4;
    const int b_r = wn * 64 + ((lane >> 4) & 1) * 8 + (lane & 7);
    const int b_c = ((lane >> 3) & 1) * 4;
    const uint32_t b_frag = sb + (uint32_t)(A_ST + b_r * BSTR + b_c) * 4;

    float c[4][8][4];
#pragma unroll
    for (int mt = 0; mt < 4; ++mt)
#pragma unroll
        for (int nt = 0; nt < 8; ++nt)
#pragma unroll
            for (int i = 0; i < 4; ++i) c[mt][nt][i] = 0.0f;

    const int nkt = K / GBK;
    gemm_load_stage(a_dst, b_dst, Ap, Bp, K); CP_COMMIT();
    gemm_load_stage(a_dst + STAGE_FL * 4, b_dst + STAGE_FL * 4,
                    Ap + GBK, Bp + GBK, K); CP_COMMIT();

#pragma unroll 1
    for (int kt = 0; kt < nkt; ++kt) {
        if (kt + 1 < nkt) { CP_WAIT1(); } else { CP_WAIT0(); }
        __syncthreads();
        if (kt + 2 < nkt) {
            const uint32_t so = (uint32_t)((kt + 2) % 3) * STAGE_FL * 4;
            gemm_load_stage(a_dst + so, b_dst + so,
                            Ap + (kt + 2) * GBK, Bp + (kt + 2) * GBK, K);
        }
        CP_COMMIT();

        const uint32_t so = (uint32_t)(kt % 3) * STAGE_FL * 4;
#pragma unroll
        for (int ks = 0; ks < 4; ++ks) {
            uint32_t af[4][4];
#pragma unroll
            for (int mt = 0; mt < 4; ++mt)
                ldsm_x4(af[mt], a_frag + so + (uint32_t)(mt * 16 * ASTR + ks * 8) * 4);
            uint32_t bf[8][2];
#pragma unroll
            for (int p = 0; p < 4; ++p) {
                uint32_t t4[4];
                ldsm_x4(t4, b_frag + so + (uint32_t)(p * 16 * BSTR + ks * 8) * 4);
                bf[2 * p][0] = t4[0]; bf[2 * p][1] = t4[1];
                bf[2 * p + 1][0] = t4[2]; bf[2 * p + 1][1] = t4[3];
            }
#pragma unroll
            for (int mt = 0; mt < 4; ++mt)
#pragma unroll
                for (int nt = 0; nt < 8; ++nt)
                    mma_tf32(c[mt][nt], af[mt], bf[nt]);
        }
    }

    // Epilogue
#pragma unroll
    for (int mt = 0; mt < 4; ++mt) {
        const int r0 = bm + wm * 64 + mt * 16 + g;
#pragma unroll
        for (int nt = 0; nt < 8; ++nt) {
            const int cc = bn + wn * 64 + nt * 8 + tig * 2;
            *(float2*)&C[(size_t)r0 * N + cc]       = make_float2(c[mt][nt][0], c[mt][nt][1]);
            *(float2*)&C[(size_t)(r0 + 8) * N + cc] = make_float2(c[mt][nt][2], c[mt][nt][3]);
        }
    }
}

// ---------------------------------------------------------------------------
// Pre-passes
// ---------------------------------------------------------------------------
__global__ __launch_bounds__(256) void round_tf32_kernel(
    const float* __restrict__ in, float* __restrict__ out, int n4)
{
    int i = blockIdx.x * 256 + threadIdx.x;
    if (i < n4) {
        float4 v = ((const float4*)in)[i];
        v.x = rna_tf32(v.x); v.y = rna_tf32(v.y);
        v.z = rna_tf32(v.z); v.w = rna_tf32(v.w);
        ((float4*)out)[i] = v;
    }
}

// in: [K][N] row-major -> out: [N][K] row-major, tf32-rounded.
__global__ __launch_bounds__(256) void transpose_rna(
    const float* __restrict__ in, float* __restrict__ out, int K, int N)
{
    __shared__ float t[32][33];
    const int n0 = blockIdx.x * 32, k0 = blockIdx.y * 32;
    const int tx = threadIdx.x, ty = threadIdx.y;  // 32 x 8
#pragma unroll
    for (int i = ty; i < 32; i += 8)
        t[i][tx] = in[(size_t)(k0 + i) * N + n0 + tx];
    __syncthreads();
#pragma unroll
    for (int i = ty; i < 32; i += 8)
        out[(size_t)(n0 + i) * K + k0 + tx] = rna_tf32(t[tx][i]);
}

// Fused wk+wv transpose: one launch covering both weight matrices.
// blocks with n0 < NKVD read wk, others read wv; out rows n0 (wk) / NKVD+n (wv).
__global__ __launch_bounds__(256) void transpose_kv(
    const float* __restrict__ wk, const float* __restrict__ wv,
    float* __restrict__ out)
{
    __shared__ float t[32][33];
    const int n0g = blockIdx.x * 32;                 // 0..2047
    const int k0  = blockIdx.y * 32;
    const float* in = (n0g < NKVD) ? wk : wv;
    const int n0 = (n0g < NKVD) ? n0g : n0g - NKVD;
    const int tx = threadIdx.x, ty = threadIdx.y;    // 32 x 8
#pragma unroll
    for (int i = ty; i < 32; i += 8)
        t[i][tx] = in[(size_t)(k0 + i) * NKVD + n0 + tx];
    __syncthreads();
#pragma unroll
    for (int i = ty; i < 32; i += 8)
        out[(size_t)(n0g + i) * HID + k0 + tx] = rna_tf32(t[tx][i]);
}

// V^T pass: out[n][s] = rna(in[s][n]), in stride 2*NKVD (V columns of kvp).
__global__ __launch_bounds__(256) void transpose_vt(
    const float* __restrict__ in, float* __restrict__ out)
{
    __shared__ float t[32][33];
    const int n0 = blockIdx.x * 32, s0 = blockIdx.y * 32;
    const int tx = threadIdx.x, ty = threadIdx.y;  // 32 x 8
#pragma unroll
    for (int i = ty; i < 32; i += 8)
        t[i][tx] = in[(size_t)(s0 + i) * (2 * NKVD) + n0 + tx];
    __syncthreads();
#pragma unroll
    for (int i = ty; i < 32; i += 8)
        out[(size_t)(n0 + i) * S_LEN + s0 + tx] = rna_tf32(t[tx][i]);
}

// ---------------------------------------------------------------------------
// RoPE + head-major transpose, tf32-rounded output.
// ---------------------------------------------------------------------------
__global__ __launch_bounds__(128) void rope_transpose(
    const float* __restrict__ src, int srcStride,
    const float* __restrict__ cosp, const float* __restrict__ sinp,
    float* __restrict__ dst)
{
    const int s = blockIdx.x;
    const int h = blockIdx.y;
    const int d = threadIdx.x;

    const float x   = src[(size_t)s * srcStride + h * HD + d];
    const float p   = src[(size_t)s * srcStride + h * HD + (d ^ 64)];
    const float rot = (d < 64) ? -p : p;
    const float val = x * cosp[s * HD + d] + rot * sinp[s * HD + d];
    dst[((size_t)h * S_LEN + s) * HD + d] = rna_tf32(val);
}

// ---------------------------------------------------------------------------
// Flash attention on mma.sync tf32 + ldmatrix. BM=128, BN=64, 8 warps.
// Split-barrier cp.async overlap: K(jt+1) staged during softmax+PV of jt,
// V(jt+1) staged during QK of jt+1. Commit order K,V,K,V...; wait_group 1
// at each consume point completes exactly the needed group.
// ---------------------------------------------------------------------------
#define FA_QSTR 132
#define FA_KSTR 132
#define FA_VSTR 68
#define FA_PSTR 68
#define FA_QS 0
#define FA_KS (128 * FA_QSTR)               // 16896
#define FA_VT (FA_KS + 64 * FA_KSTR)        // 25344
#define FA_PS (FA_VT + 128 * FA_VSTR)       // 34048
#define FA_SMEM ((FA_PS + 128 * FA_PSTR) * 4)   // 171008 B

__global__ __launch_bounds__(256, 1) void flash_mma(
    const float* __restrict__ Qh, const float* __restrict__ Kh,
    const float* __restrict__ VT, float* __restrict__ O)
{
    extern __shared__ float sm[];
    const uint32_t sb = smem_u32(sm);

    const int tid  = threadIdx.x;
    const int lane = tid & 31;
    const int wid  = tid >> 5;
    const int g    = lane >> 2;
    const int tig  = lane & 3;
    const int qb   = gridDim.x - 1 - blockIdx.x;   // heavy (high-qb) CTAs first
    const int h    = blockIdx.y;
    const int kvh  = h >> 2;

    const float* Qbase  = Qh + ((size_t)h * S_LEN + qb * 128) * HD;
    const float* Kbase  = Kh + (size_t)kvh * S_LEN * HD;
    const float* VTbase = VT + (size_t)kvh * HD * S_LEN;

    // Stage Q tile [128][128]
#pragma unroll
    for (int j = 0; j < 16; ++j) {
        const int idx = tid + j * 256;
        const int r = idx >> 5, cb = (idx & 31) * 4;
        *(float4*)&sm[FA_QS + r * FA_QSTR + cb] =
            *(const float4*)(Qbase + (size_t)r * HD + cb);
    }

    // cp.async staging offsets
    const int krow = tid >> 5;             // +8j
    const int kcb  = (tid & 31) * 4;
    const int vrow = tid >> 4;             // +16j
    const int vkk  = (tid & 15) * 4;

    // ldmatrix per-lane bases
    const int rsel = (lane & 7) + ((lane >> 3) & 1) * 8;
    const int csel = (lane >> 4) * 4;
    const int brsel = ((lane >> 4) & 1) * 8 + (lane & 7);
    const int bcsel = ((lane >> 3) & 1) * 4;
    const uint32_t q_frag = sb + (uint32_t)(FA_QS + (wid * 16 + rsel) * FA_QSTR + csel) * 4;
    const uint32_t k_frag = sb + (uint32_t)(FA_KS + brsel * FA_KSTR + bcsel) * 4;
    const uint32_t v_frag = sb + (uint32_t)(FA_VT + brsel * FA_VSTR + bcsel) * 4;
    const uint32_t p_frag = sb + (uint32_t)(FA_PS + (wid * 16 + rsel) * FA_PSTR + csel) * 4;

    float s[8][4], o[16][4], m_i[2], l_i[2];
    m_i[0] = m_i[1] = -1e30f;
    l_i[0] = l_i[1] = 0.0f;
#pragma unroll
    for (int nt = 0; nt < 16; ++nt)
#pragma unroll
        for (int i = 0; i < 4; ++i) o[nt][i] = 0.0f;

    const float sc = 0.08838834764831845f;  // 1/sqrt(128)
    const int qrow0 = qb * 128 + wid * 16 + g;
    const int jtmax = 2 * qb + 1;

    // Preload K(0) then V(0) as two separate cp.async groups
#pragma unroll
    for (int j = 0; j < 8; ++j) {
        const int r = krow + 8 * j;
        cpasync16(sb + (uint32_t)(FA_KS + r * FA_KSTR + kcb) * 4,
                  Kbase + (size_t)r * HD + kcb);
    }
    CP_COMMIT();
#pragma unroll
    for (int j = 0; j < 8; ++j) {
        const int d = vrow + 16 * j;
        cpasync16(sb + (uint32_t)(FA_VT + d * FA_VSTR + vkk) * 4,
                  VTbase + (size_t)d * S_LEN + vkk);
    }
    CP_COMMIT();

    for (int jt = 0; jt <= jtmax; ++jt) {
        CP_WAIT1();          // K(jt) landed (V(jt) may still be in flight)
        __syncthreads();     // K visible to all warps (also covers Q on jt=0)

        // S = Q K^T  (16 x 64 per warp)
#pragma unroll
        for (int nt = 0; nt < 8; ++nt)
#pragma unroll
            for (int i = 0; i < 4; ++i) s[nt][i] = 0.0f;

#pragma unroll
        for (int ks = 0; ks < 16; ++ks) {
            uint32_t a[4];
            ldsm_x4(a, q_frag + ks * 32);
#pragma unroll
            for (int p = 0; p < 4; ++p) {
                uint32_t t4[4];
                ldsm_x4(t4, k_frag + (uint32_t)(p * 16 * FA_KSTR) * 4 + ks * 32);
                mma_tf32(s[2 * p],     a, t4);
                mma_tf32(s[2 * p + 1], a, t4 + 2);
            }
        }

        __syncthreads();     // all warps done reading K(jt)
        if (jt < jtmax) {    // stage K(jt+1); overlaps softmax + PV
#pragma unroll
            for (int j = 0; j < 8; ++j) {
                const int r = krow + 8 * j;
                cpasync16(sb + (uint32_t)(FA_KS + r * FA_KSTR + kcb) * 4,
                          Kbase + (size_t)((jt + 1) * 64 + r) * HD + kcb);
            }
        }
        CP_COMMIT();

        // Scale + causal mask
        const int colb = jt * 64 + tig * 2;
#pragma unroll
        for (int nt = 0; nt < 8; ++nt) {
            const int c0 = colb + nt * 8, c1 = c0 + 1;
            s[nt][0] = (c0 > qrow0)     ? -1e30f : s[nt][0] * sc;
            s[nt][1] = (c1 > qrow0)     ? -1e30f : s[nt][1] * sc;
            s[nt][2] = (c0 > qrow0 + 8) ? -1e30f : s[nt][2] * sc;
            s[nt][3] = (c1 > qrow0 + 8) ? -1e30f : s[nt][3] * sc;
        }

        // Online softmax
        float mx0 = -1e30f, mx1 = -1e30f;
#pragma unroll
        for (int nt = 0; nt < 8; ++nt) {
            mx0 = fmaxf(mx0, fmaxf(s[nt][0], s[nt][1]));
            mx1 = fmaxf(mx1, fmaxf(s[nt][2], s[nt][3]));
        }
        mx0 = fmaxf(mx0, __shfl_xor_sync(0xffffffffu, mx0, 1));
        mx0 = fmaxf(mx0, __shfl_xor_sync(0xffffffffu, mx0, 2));
        mx1 = fmaxf(mx1, __shfl_xor_sync(0xffffffffu, mx1, 1));
        mx1 = fmaxf(mx1, __shfl_xor_sync(0xffffffffu, mx1, 2));

        const float mn0 = fmaxf(m_i[0], mx0);
        const float mn1 = fmaxf(m_i[1], mx1);
        const float al0 = __expf(m_i[0] - mn0);
        const float al1 = __expf(m_i[1] - mn1);
        m_i[0] = mn0; m_i[1] = mn1;

        float rs0 = 0.0f, rs1 = 0.0f;
#pragma unroll
        for (int nt = 0; nt < 8; ++nt) {
            s[nt][0] = __expf(s[nt][0] - mn0);
            s[nt][1] = __expf(s[nt][1] - mn0);
            s[nt][2] = __expf(s[nt][2] - mn1);
            s[nt][3] = __expf(s[nt][3] - mn1);
            rs0 += s[nt][0] + s[nt][1];
            rs1 += s[nt][2] + s[nt][3];
        }
        rs0 += __shfl_xor_sync(0xffffffffu, rs0, 1);
        rs0 += __shfl_xor_sync(0xffffffffu, rs0, 2);
        rs1 += __shfl_xor_sync(0xffffffffu, rs1, 1);
        rs1 += __shfl_xor_sync(0xffffffffu, rs1, 2);
        l_i[0] = l_i[0] * al0 + rs0;
        l_i[1] = l_i[1] * al1 + rs1;
#pragma unroll
        for (int nt = 0; nt < 16; ++nt) {
            o[nt][0] *= al0; o[nt][1] *= al0;
            o[nt][2] *= al1; o[nt][3] *= al1;
        }

        // Stage P (tf32-rounded). P rows are warp-private.
        {
            const int r = wid * 16 + g;
#pragma unroll
            for (int nt = 0; nt < 8; ++nt) {
                const int cc = nt * 8 + tig * 2;
                *(float2*)&sm[FA_PS + r * FA_PSTR + cc] =
                    make_float2(rna_tf32(s[nt][0]), rna_tf32(s[nt][1]));
                *(float2*)&sm[FA_PS + (r + 8) * FA_PSTR + cc] =
                    make_float2(rna_tf32(s[nt][2]), rna_tf32(s[nt][3]));
            }
        }

        CP_WAIT1();          // V(jt) landed (K(jt+1) may still be in flight)
        __syncthreads();     // V visible; also orders P stores (warp-private anyway)

        // O += P @ V   (V^T d-major -> LDSM B fragments)
#pragma unroll
        for (int ks = 0; ks < 8; ++ks) {
            uint32_t a[4];
            ldsm_x4(a, p_frag + ks * 32);
#pragma unroll
            for (int p = 0; p < 8; ++p) {
                uint32_t t4[4];
                ldsm_x4(t4, v_frag + (uint32_t)(p * 16 * FA_VSTR) * 4 + ks * 32);
                mma_tf32(o[2 * p],     a, t4);
                mma_tf32(o[2 * p + 1], a, t4 + 2);
            }
        }

        __syncthreads();     // all warps done reading V(jt)
        if (jt < jtmax) {    // stage V(jt+1); overlaps next QK
#pragma unroll
            for (int j = 0; j < 8; ++j) {
                const int d = vrow + 16 * j;
                cpasync16(sb + (uint32_t)(FA_VT + d * FA_VSTR + vkk) * 4,
                          VTbase + (size_t)d * S_LEN + (jt + 1) * 64 + vkk);
            }
        }
        CP_COMMIT();
    }

    // Epilogue: normalize, tf32-round, write [S][NQ]
    const float inv0 = 1.0f / l_i[0];
    const float inv1 = 1.0f / l_i[1];
    float* Op = O + (size_t)qrow0 * NQ + h * HD;
#pragma unroll
    for (int nt = 0; nt < 16; ++nt) {
        const int cc = nt * 8 + tig * 2;
        *(float2*)&Op[cc] =
            make_float2(rna_tf32(o[nt][0] * inv0), rna_tf32(o[nt][1] * inv0));
        *(float2*)&Op[(size_t)8 * NQ + cc] =
            make_float2(rna_tf32(o[nt][2] * inv1), rna_tf32(o[nt][3] * inv1));
    }
}

// ---------------------------------------------------------------------------
// Launch. Inputs: 0 hidden_states, 1 attention_mask (unused), 2 wq, 3 wk,
// 4 wv, 5 wo, 6 cos, 7 sin.
// Order puts gemm_mma at launches #4 and #5 so the ncu capture window
// lands on a GEMM.
// ---------------------------------------------------------------------------
extern "C" void kernel_launch(void* const* d_in, const int* in_sizes, int n_in,
                              void* d_out, int out_size)
{
    (void)in_sizes; (void)n_in; (void)out_size;
    const float* hs = (const float*)d_in[0];
    const float* wq = (const float*)d_in[2];
    const float* wk = (const float*)d_in[3];
    const float* wv = (const float*)d_in[4];
    const float* wo = (const float*)d_in[5];
    const float* cs = (const float*)d_in[6];
    const float* sn = (const float*)d_in[7];
    float* out = (float*)d_out;

    float *hsr, *wqT, *wkvT, *woT, *q, *kvp, *qh, *kh, *vt, *ao;
    cudaGetSymbolAddress((void**)&hsr,  g_hsr);
    cudaGetSymbolAddress((void**)&wqT,  g_wqT);
    cudaGetSymbolAddress((void**)&wkvT, g_wkvT);
    cudaGetSymbolAddress((void**)&woT,  g_woT);
    cudaGetSymbolAddress((void**)&q,    g_q);
    cudaGetSymbolAddress((void**)&kvp,  g_kvp);
    cudaGetSymbolAddress((void**)&qh,   g_qh);
    cudaGetSymbolAddress((void**)&kh,   g_kh);
    cudaGetSymbolAddress((void**)&vt,   g_vt);
    cudaGetSymbolAddress((void**)&ao,   g_ao);

    cudaFuncSetAttribute(gemm_mma,  cudaFuncAttributeMaxDynamicSharedMemorySize, GEMM_SMEM);
    cudaFuncSetAttribute(flash_mma, cudaFuncAttributeMaxDynamicSharedMemorySize, FA_SMEM);

    // #1-#3: pre-passes needed by the projection GEMMs
    round_tf32_kernel<<<(S_LEN * HID / 4 + 255) / 256, 256>>>(hs, hsr, S_LEN * HID / 4);
    transpose_rna<<<dim3(NQ / 32, HID / 32), dim3(32, 8)>>>(wq, wqT, HID, NQ);
    transpose_kv <<<dim3(2 * NKVD / 32, HID / 32), dim3(32, 8)>>>(wk, wv, wkvT);

    // #4, #5: the projection GEMMs (ncu capture targets)
    gemm_mma<<<dim3(NQ / GBN, S_LEN / GBM), 256, GEMM_SMEM>>>(hsr, wqT, q, S_LEN, NQ, HID);
    gemm_mma<<<dim3(2 * NKVD / GBN, S_LEN / GBM), 256, GEMM_SMEM>>>(hsr, wkvT, kvp, S_LEN, 2 * NKVD, HID);

    // #6: wo transpose (needed only by the final GEMM)
    transpose_rna<<<dim3(HID / 32, NQ / 32), dim3(32, 8)>>>(wo, woT, NQ, HID);

    // #7-#9: RoPE + head-major (Q, K); V -> transposed [NKV][HD][S]
    rope_transpose<<<dim3(S_LEN, NH),  128>>>(q,   NQ,       cs, sn, qh);
    rope_transpose<<<dim3(S_LEN, NKV), 128>>>(kvp, 2 * NKVD, cs, sn, kh);
    transpose_vt<<<dim3(NKVD / 32, S_LEN / 32), dim3(32, 8)>>>(kvp + NKVD, vt);

    // #10: flash attention
    flash_mma<<<dim3(S_LEN / 128, NH), 256, FA_SMEM>>>(qh, kh, vt, ao);

    // #11: output projection
    gemm_mma<<<dim3(HID / GBN, S_LEN / GBM), 256, GEMM_SMEM>>>(ao, woT, out, S_LEN, HID, NQ);
}

// round 9
// speedup vs baseline: 3.6691x; 1.0224x over previous
#include <cuda_runtime.h>
#include <cuda_bf16.h>
#include <math.h>
#include <stdint.h>

// Problem constants
#define S_LEN 2048
#define HID   4096
#define NH    32
#define NKV   8
#define HD    128
#define NQ    (NH * HD)    // 4096
#define NKVD  (NKV * HD)   // 1024

// ---------------------------------------------------------------------------
// Scratch (static device arrays; no cudaMalloc allowed)
// ---------------------------------------------------------------------------
__device__ float g_hsr [S_LEN * HID];      // hidden states, tf32-rounded
__device__ float g_wqT [NQ * HID];         // wq^T  [4096][4096]
__device__ float g_wkvT[2 * NKVD * HID];   // [wk^T ; wv^T]  [2048][4096]
__device__ float g_woT [HID * NQ];         // wo^T  [4096][4096]
__device__ float g_q   [S_LEN * NQ];       // Q projection [S][4096]
__device__ float g_kvp [S_LEN * 2 * NKVD]; // KV projection [S][2048]
__device__ float g_qh  [S_LEN * NQ];       // Q rope, head-major [NH][S][HD]
__device__ float g_kh  [S_LEN * NKVD];     // K rope, head-major [NKV][S][HD]
__device__ float g_vt  [S_LEN * NKVD];     // V^T head-major [NKV][HD][S]
__device__ float g_ao  [S_LEN * NQ];       // attention out [S][4096]

// ---------------------------------------------------------------------------
// Helpers
// ---------------------------------------------------------------------------
__device__ __forceinline__ uint32_t smem_u32(const void* p) {
    uint32_t a;
    asm("{ .reg .u64 t; cvta.to.shared.u64 t, %1; cvt.u32.u64 %0, t; }"
        : "=r"(a) : "l"(p));
    return a;
}
__device__ __forceinline__ float rna_tf32(float v) {
    uint32_t o;
    asm("cvt.rna.tf32.f32 %0, %1;" : "=r"(o) : "f"(v));
    return __uint_as_float(o);
}
__device__ __forceinline__ void mma_tf32(float* c, const uint32_t* a, const uint32_t* b) {
    asm("mma.sync.aligned.m16n8k8.row.col.f32.tf32.tf32.f32 "
        "{%0,%1,%2,%3}, {%4,%5,%6,%7}, {%8,%9}, {%0,%1,%2,%3};"
        : "+f"(c[0]), "+f"(c[1]), "+f"(c[2]), "+f"(c[3])
        : "r"(a[0]), "r"(a[1]), "r"(a[2]), "r"(a[3]), "r"(b[0]), "r"(b[1]));
}
__device__ __forceinline__ void ldsm_x4(uint32_t* r, uint32_t saddr) {
    asm volatile("ldmatrix.sync.aligned.m8n8.x4.shared.b16 {%0,%1,%2,%3}, [%4];"
        : "=r"(r[0]), "=r"(r[1]), "=r"(r[2]), "=r"(r[3]) : "r"(saddr));
}
__device__ __forceinline__ void cpasync16(uint32_t dst, const void* src) {
    asm volatile("cp.async.cg.shared.global [%0], [%1], 16;" :: "r"(dst), "l"(src));
}
#define CP_COMMIT()  asm volatile("cp.async.commit_group;" ::: "memory")
#define CP_WAIT0()   asm volatile("cp.async.wait_group 0;" ::: "memory")
#define CP_WAIT1()   asm volatile("cp.async.wait_group 1;" ::: "memory")

// ---------------------------------------------------------------------------
// tf32 mma GEMM: C[M,N] = A[M,K] @ BT[N,K]^T (A row-major, BT K-major, both
// tf32-pre-rounded). Block 128x128, 8 warps (2m x 4n) of 64x32 warp tiles,
// BK=32, 3-stage cp.async pipeline, ldmatrix fragment loads.
// Sized for 2 CTAs/SM: smem 110.6KB/CTA (221KB/SM), regs capped at 128.
// ---------------------------------------------------------------------------
#define GBM 128
#define GBN 128
#define GBK 32
#define ASTR 36               // floats; 36%8=4 -> conflict-free LDSM row groups
#define BSTR 36
#define A_ST (128 * ASTR)     // 4608 floats per A stage
#define B_ST (128 * BSTR)     // 4608 floats per B stage
#define STAGE_FL (A_ST + B_ST)
#define GEMM_SMEM (3 * STAGE_FL * 4)   // 110592 B

__device__ __forceinline__ void gemm_load_stage(
    uint32_t a_dst, uint32_t b_dst, const float* ap, const float* bp, int K)
{
#pragma unroll
    for (int i = 0; i < 4; ++i)
        cpasync16(a_dst + i * 32 * ASTR * 4, ap + (size_t)i * 32 * K);
#pragma unroll
    for (int i = 0; i < 4; ++i)
        cpasync16(b_dst + i * 32 * BSTR * 4, bp + (size_t)i * 32 * K);
}

__global__ __launch_bounds__(256, 2) void gemm_mma(
    const float* __restrict__ A, const float* __restrict__ BT,
    float* __restrict__ C, int M, int N, int K)
{
    extern __shared__ float sm[];
    const uint32_t sb = smem_u32(sm);

    const int tid  = threadIdx.x;
    const int lane = tid & 31;
    const int wid  = tid >> 5;
    const int wm   = wid >> 2;           // 0..1 (64 rows each)
    const int wn   = wid & 3;            // 0..3 (32 cols each)
    const int g    = lane >> 2;
    const int tig  = lane & 3;
    const int bm   = blockIdx.y * GBM;
    const int bn   = blockIdx.x * GBN;

    // Loader: thread covers rows lrow+32i, cols lcol..lcol+3 of the BK slab
    const int lrow = tid >> 3;
    const int lcol = (tid & 7) * 4;
    const float* Ap = A  + (size_t)(bm + lrow) * K + lcol;
    const float* Bp = BT + (size_t)(bn + lrow) * K + lcol;
    const uint32_t a_dst = sb + (uint32_t)(lrow * ASTR + lcol) * 4;
    const uint32_t b_dst = sb + (uint32_t)(A_ST + lrow * BSTR + lcol) * 4;

    // ldmatrix per-lane addresses
    const int a_r = wm * 64 + (lane & 7) + ((lane >> 3) & 1) * 8;
    const int a_c = (lane >> 4) * 4;
    const uint32_t a_frag = sb + (uint32_t)(a_r * ASTR + a_c) * 4;
    const int b_r = wn * 32 + ((lane >> 4) & 1) * 8 + (lane & 7);
    const int b_c = ((lane >> 3) & 1) * 4;
    const uint32_t b_frag = sb + (uint32_t)(A_ST + b_r * BSTR + b_c) * 4;

    float c[4][4][4];
#pragma unroll
    for (int mt = 0; mt < 4; ++mt)
#pragma unroll
        for (int nt = 0; nt < 4; ++nt)
#pragma unroll
            for (int i = 0; i < 4; ++i) c[mt][nt][i] = 0.0f;

    const int nkt = K / GBK;
    gemm_load_stage(a_dst, b_dst, Ap, Bp, K); CP_COMMIT();
    gemm_load_stage(a_dst + STAGE_FL * 4, b_dst + STAGE_FL * 4,
                    Ap + GBK, Bp + GBK, K); CP_COMMIT();

#pragma unroll 1
    for (int kt = 0; kt < nkt; ++kt) {
        if (kt + 1 < nkt) { CP_WAIT1(); } else { CP_WAIT0(); }
        __syncthreads();
        if (kt + 2 < nkt) {
            const uint32_t so = (uint32_t)((kt + 2) % 3) * STAGE_FL * 4;
            gemm_load_stage(a_dst + so, b_dst + so,
                            Ap + (kt + 2) * GBK, Bp + (kt + 2) * GBK, K);
        }
        CP_COMMIT();

        const uint32_t so = (uint32_t)(kt % 3) * STAGE_FL * 4;
#pragma unroll
        for (int ks = 0; ks < 4; ++ks) {
            uint32_t af[4][4];
#pragma unroll
            for (int mt = 0; mt < 4; ++mt)
                ldsm_x4(af[mt], a_frag + so + (uint32_t)(mt * 16 * ASTR + ks * 8) * 4);
            uint32_t bf[4][2];
#pragma unroll
            for (int p = 0; p < 2; ++p) {
                uint32_t t4[4];
                ldsm_x4(t4, b_frag + so + (uint32_t)(p * 16 * BSTR + ks * 8) * 4);
                bf[2 * p][0] = t4[0]; bf[2 * p][1] = t4[1];
                bf[2 * p + 1][0] = t4[2]; bf[2 * p + 1][1] = t4[3];
            }
#pragma unroll
            for (int mt = 0; mt < 4; ++mt)
#pragma unroll
                for (int nt = 0; nt < 4; ++nt)
                    mma_tf32(c[mt][nt], af[mt], bf[nt]);
        }
    }

    // Epilogue
#pragma unroll
    for (int mt = 0; mt < 4; ++mt) {
        const int r0 = bm + wm * 64 + mt * 16 + g;
#pragma unroll
        for (int nt = 0; nt < 4; ++nt) {
            const int cc = bn + wn * 32 + nt * 8 + tig * 2;
            *(float2*)&C[(size_t)r0 * N + cc]       = make_float2(c[mt][nt][0], c[mt][nt][1]);
            *(float2*)&C[(size_t)(r0 + 8) * N + cc] = make_float2(c[mt][nt][2], c[mt][nt][3]);
        }
    }
}

// ---------------------------------------------------------------------------
// Pre-passes
// ---------------------------------------------------------------------------
__global__ __launch_bounds__(256) void round_tf32_kernel(
    const float* __restrict__ in, float* __restrict__ out, int n4)
{
    int i = blockIdx.x * 256 + threadIdx.x;
    if (i < n4) {
        float4 v = ((const float4*)in)[i];
        v.x = rna_tf32(v.x); v.y = rna_tf32(v.y);
        v.z = rna_tf32(v.z); v.w = rna_tf32(v.w);
        ((float4*)out)[i] = v;
    }
}

// in: [K][N] row-major -> out: [N][K] row-major, tf32-rounded.
__global__ __launch_bounds__(256) void transpose_rna(
    const float* __restrict__ in, float* __restrict__ out, int K, int N)
{
    __shared__ float t[32][33];
    const int n0 = blockIdx.x * 32, k0 = blockIdx.y * 32;
    const int tx = threadIdx.x, ty = threadIdx.y;  // 32 x 8
#pragma unroll
    for (int i = ty; i < 32; i += 8)
        t[i][tx] = in[(size_t)(k0 + i) * N + n0 + tx];
    __syncthreads();
#pragma unroll
    for (int i = ty; i < 32; i += 8)
        out[(size_t)(n0 + i) * K + k0 + tx] = rna_tf32(t[tx][i]);
}

// Fused wk+wv transpose: one launch covering both weight matrices.
__global__ __launch_bounds__(256) void transpose_kv(
    const float* __restrict__ wk, const float* __restrict__ wv,
    float* __restrict__ out)
{
    __shared__ float t[32][33];
    const int n0g = blockIdx.x * 32;                 // 0..2047
    const int k0  = blockIdx.y * 32;
    const float* in = (n0g < NKVD) ? wk : wv;
    const int n0 = (n0g < NKVD) ? n0g : n0g - NKVD;
    const int tx = threadIdx.x, ty = threadIdx.y;    // 32 x 8
#pragma unroll
    for (int i = ty; i < 32; i += 8)
        t[i][tx] = in[(size_t)(k0 + i) * NKVD + n0 + tx];
    __syncthreads();
#pragma unroll
    for (int i = ty; i < 32; i += 8)
        out[(size_t)(n0g + i) * HID + k0 + tx] = rna_tf32(t[tx][i]);
}

// V^T pass: out[n][s] = rna(in[s][n]), in stride 2*NKVD (V columns of kvp).
__global__ __launch_bounds__(256) void transpose_vt(
    const float* __restrict__ in, float* __restrict__ out)
{
    __shared__ float t[32][33];
    const int n0 = blockIdx.x * 32, s0 = blockIdx.y * 32;
    const int tx = threadIdx.x, ty = threadIdx.y;  // 32 x 8
#pragma unroll
    for (int i = ty; i < 32; i += 8)
        t[i][tx] = in[(size_t)(s0 + i) * (2 * NKVD) + n0 + tx];
    __syncthreads();
#pragma unroll
    for (int i = ty; i < 32; i += 8)
        out[(size_t)(n0 + i) * S_LEN + s0 + tx] = rna_tf32(t[tx][i]);
}

// ---------------------------------------------------------------------------
// RoPE + head-major transpose, tf32-rounded output.
// ---------------------------------------------------------------------------
__global__ __launch_bounds__(128) void rope_transpose(
    const float* __restrict__ src, int srcStride,
    const float* __restrict__ cosp, const float* __restrict__ sinp,
    float* __restrict__ dst)
{
    const int s = blockIdx.x;
    const int h = blockIdx.y;
    const int d = threadIdx.x;

    const float x   = src[(size_t)s * srcStride + h * HD + d];
    const float p   = src[(size_t)s * srcStride + h * HD + (d ^ 64)];
    const float rot = (d < 64) ? -p : p;
    const float val = x * cosp[s * HD + d] + rot * sinp[s * HD + d];
    dst[((size_t)h * S_LEN + s) * HD + d] = rna_tf32(val);
}

// ---------------------------------------------------------------------------
// Flash attention on mma.sync tf32 + ldmatrix. BM=128, BN=64, 8 warps.
// Split-barrier cp.async overlap; commit order K,V,K,V...; wait_group 1
// at each consume point completes exactly the needed group.
// ---------------------------------------------------------------------------
#define FA_QSTR 132
#define FA_KSTR 132
#define FA_VSTR 68
#define FA_PSTR 68
#define FA_QS 0
#define FA_KS (128 * FA_QSTR)               // 16896
#define FA_VT (FA_KS + 64 * FA_KSTR)        // 25344
#define FA_PS (FA_VT + 128 * FA_VSTR)       // 34048
#define FA_SMEM ((FA_PS + 128 * FA_PSTR) * 4)   // 171008 B

__global__ __launch_bounds__(256, 1) void flash_mma(
    const float* __restrict__ Qh, const float* __restrict__ Kh,
    const float* __restrict__ VT, float* __restrict__ O)
{
    extern __shared__ float sm[];
    const uint32_t sb = smem_u32(sm);

    const int tid  = threadIdx.x;
    const int lane = tid & 31;
    const int wid  = tid >> 5;
    const int g    = lane >> 2;
    const int tig  = lane & 3;
    const int qb   = gridDim.x - 1 - blockIdx.x;   // heavy (high-qb) CTAs first
    const int h    = blockIdx.y;
    const int kvh  = h >> 2;

    const float* Qbase  = Qh + ((size_t)h * S_LEN + qb * 128) * HD;
    const float* Kbase  = Kh + (size_t)kvh * S_LEN * HD;
    const float* VTbase = VT + (size_t)kvh * HD * S_LEN;

    // Stage Q tile [128][128]
#pragma unroll
    for (int j = 0; j < 16; ++j) {
        const int idx = tid + j * 256;
        const int r = idx >> 5, cb = (idx & 31) * 4;
        *(float4*)&sm[FA_QS + r * FA_QSTR + cb] =
            *(const float4*)(Qbase + (size_t)r * HD + cb);
    }

    // cp.async staging offsets
    const int krow = tid >> 5;             // +8j
    const int kcb  = (tid & 31) * 4;
    const int vrow = tid >> 4;             // +16j
    const int vkk  = (tid & 15) * 4;

    // ldmatrix per-lane bases
    const int rsel = (lane & 7) + ((lane >> 3) & 1) * 8;
    const int csel = (lane >> 4) * 4;
    const int brsel = ((lane >> 4) & 1) * 8 + (lane & 7);
    const int bcsel = ((lane >> 3) & 1) * 4;
    const uint32_t q_frag = sb + (uint32_t)(FA_QS + (wid * 16 + rsel) * FA_QSTR + csel) * 4;
    const uint32_t k_frag = sb + (uint32_t)(FA_KS + brsel * FA_KSTR + bcsel) * 4;
    const uint32_t v_frag = sb + (uint32_t)(FA_VT + brsel * FA_VSTR + bcsel) * 4;
    const uint32_t p_frag = sb + (uint32_t)(FA_PS + (wid * 16 + rsel) * FA_PSTR + csel) * 4;

    float s[8][4], o[16][4], m_i[2], l_i[2];
    m_i[0] = m_i[1] = -1e30f;
    l_i[0] = l_i[1] = 0.0f;
#pragma unroll
    for (int nt = 0; nt < 16; ++nt)
#pragma unroll
        for (int i = 0; i < 4; ++i) o[nt][i] = 0.0f;

    const float sc = 0.08838834764831845f;  // 1/sqrt(128)
    const int qrow0 = qb * 128 + wid * 16 + g;
    const int jtmax = 2 * qb + 1;

    // Preload K(0) then V(0) as two separate cp.async groups
#pragma unroll
    for (int j = 0; j < 8; ++j) {
        const int r = krow + 8 * j;
        cpasync16(sb + (uint32_t)(FA_KS + r * FA_KSTR + kcb) * 4,
                  Kbase + (size_t)r * HD + kcb);
    }
    CP_COMMIT();
#pragma unroll
    for (int j = 0; j < 8; ++j) {
        const int d = vrow + 16 * j;
        cpasync16(sb + (uint32_t)(FA_VT + d * FA_VSTR + vkk) * 4,
                  VTbase + (size_t)d * S_LEN + vkk);
    }
    CP_COMMIT();

    for (int jt = 0; jt <= jtmax; ++jt) {
        CP_WAIT1();          // K(jt) landed (V(jt) may still be in flight)
        __syncthreads();     // K visible to all warps (also covers Q on jt=0)

        // S = Q K^T  (16 x 64 per warp)
#pragma unroll
        for (int nt = 0; nt < 8; ++nt)
#pragma unroll
            for (int i = 0; i < 4; ++i) s[nt][i] = 0.0f;

#pragma unroll
        for (int ks = 0; ks < 16; ++ks) {
            uint32_t a[4];
            ldsm_x4(a, q_frag + ks * 32);
#pragma unroll
            for (int p = 0; p < 4; ++p) {
                uint32_t t4[4];
                ldsm_x4(t4, k_frag + (uint32_t)(p * 16 * FA_KSTR) * 4 + ks * 32);
                mma_tf32(s[2 * p],     a, t4);
                mma_tf32(s[2 * p + 1], a, t4 + 2);
            }
        }

        __syncthreads();     // all warps done reading K(jt)
        if (jt < jtmax) {    // stage K(jt+1); overlaps softmax + PV
#pragma unroll
            for (int j = 0; j < 8; ++j) {
                const int r = krow + 8 * j;
                cpasync16(sb + (uint32_t)(FA_KS + r * FA_KSTR + kcb) * 4,
                          Kbase + (size_t)((jt + 1) * 64 + r) * HD + kcb);
            }
        }
        CP_COMMIT();

        // Scale + causal mask
        const int colb = jt * 64 + tig * 2;
#pragma unroll
        for (int nt = 0; nt < 8; ++nt) {
            const int c0 = colb + nt * 8, c1 = c0 + 1;
            s[nt][0] = (c0 > qrow0)     ? -1e30f : s[nt][0] * sc;
            s[nt][1] = (c1 > qrow0)     ? -1e30f : s[nt][1] * sc;
            s[nt][2] = (c0 > qrow0 + 8) ? -1e30f : s[nt][2] * sc;
            s[nt][3] = (c1 > qrow0 + 8) ? -1e30f : s[nt][3] * sc;
        }

        // Online softmax
        float mx0 = -1e30f, mx1 = -1e30f;
#pragma unroll
        for (int nt = 0; nt < 8; ++nt) {
            mx0 = fmaxf(mx0, fmaxf(s[nt][0], s[nt][1]));
            mx1 = fmaxf(mx1, fmaxf(s[nt][2], s[nt][3]));
        }
        mx0 = fmaxf(mx0, __shfl_xor_sync(0xffffffffu, mx0, 1));
        mx0 = fmaxf(mx0, __shfl_xor_sync(0xffffffffu, mx0, 2));
        mx1 = fmaxf(mx1, __shfl_xor_sync(0xffffffffu, mx1, 1));
        mx1 = fmaxf(mx1, __shfl_xor_sync(0xffffffffu, mx1, 2));

        const float mn0 = fmaxf(m_i[0], mx0);
        const float mn1 = fmaxf(m_i[1], mx1);
        const float al0 = __expf(m_i[0] - mn0);
        const float al1 = __expf(m_i[1] - mn1);
        m_i[0] = mn0; m_i[1] = mn1;

        float rs0 = 0.0f, rs1 = 0.0f;
#pragma unroll
        for (int nt = 0; nt < 8; ++nt) {
            s[nt][0] = __expf(s[nt][0] - mn0);
            s[nt][1] = __expf(s[nt][1] - mn0);
            s[nt][2] = __expf(s[nt][2] - mn1);
            s[nt][3] = __expf(s[nt][3] - mn1);
            rs0 += s[nt][0] + s[nt][1];
            rs1 += s[nt][2] + s[nt][3];
        }
        rs0 += __shfl_xor_sync(0xffffffffu, rs0, 1);
        rs0 += __shfl_xor_sync(0xffffffffu, rs0, 2);
        rs1 += __shfl_xor_sync(0xffffffffu, rs1, 1);
        rs1 += __shfl_xor_sync(0xffffffffu, rs1, 2);
        l_i[0] = l_i[0] * al0 + rs0;
        l_i[1] = l_i[1] * al1 + rs1;
#pragma unroll
        for (int nt = 0; nt < 16; ++nt) {
            o[nt][0] *= al0; o[nt][1] *= al0;
            o[nt][2] *= al1; o[nt][3] *= al1;
        }

        // Stage P (tf32-rounded). P rows are warp-private.
        {
            const int r = wid * 16 + g;
#pragma unroll
            for (int nt = 0; nt < 8; ++nt) {
                const int cc = nt * 8 + tig * 2;
                *(float2*)&sm[FA_PS + r * FA_PSTR + cc] =
                    make_float2(rna_tf32(s[nt][0]), rna_tf32(s[nt][1]));
                *(float2*)&sm[FA_PS + (r + 8) * FA_PSTR + cc] =
                    make_float2(rna_tf32(s[nt][2]), rna_tf32(s[nt][3]));
            }
        }

        CP_WAIT1();          // V(jt) landed (K(jt+1) may still be in flight)
        __syncthreads();     // V visible; also orders P stores

        // O += P @ V   (V^T d-major -> LDSM B fragments)
#pragma unroll
        for (int ks = 0; ks < 8; ++ks) {
            uint32_t a[4];
            ldsm_x4(a, p_frag + ks * 32);
#pragma unroll
            for (int p = 0; p < 8; ++p) {
                uint32_t t4[4];
                ldsm_x4(t4, v_frag + (uint32_t)(p * 16 * FA_VSTR) * 4 + ks * 32);
                mma_tf32(o[2 * p],     a, t4);
                mma_tf32(o[2 * p + 1], a, t4 + 2);
            }
        }

        __syncthreads();     // all warps done reading V(jt)
        if (jt < jtmax) {    // stage V(jt+1); overlaps next QK
#pragma unroll
            for (int j = 0; j < 8; ++j) {
                const int d = vrow + 16 * j;
                cpasync16(sb + (uint32_t)(FA_VT + d * FA_VSTR + vkk) * 4,
                          VTbase + (size_t)d * S_LEN + (jt + 1) * 64 + vkk);
            }
        }
        CP_COMMIT();
    }

    // Epilogue: normalize, tf32-round, write [S][NQ]
    const float inv0 = 1.0f / l_i[0];
    const float inv1 = 1.0f / l_i[1];
    float* Op = O + (size_t)qrow0 * NQ + h * HD;
#pragma unroll
    for (int nt = 0; nt < 16; ++nt) {
        const int cc = nt * 8 + tig * 2;
        *(float2*)&Op[cc] =
            make_float2(rna_tf32(o[nt][0] * inv0), rna_tf32(o[nt][1] * inv0));
        *(float2*)&Op[(size_t)8 * NQ + cc] =
            make_float2(rna_tf32(o[nt][2] * inv1), rna_tf32(o[nt][3] * inv1));
    }
}

// ---------------------------------------------------------------------------
// Launch. Inputs: 0 hidden_states, 1 attention_mask (unused), 2 wq, 3 wk,
// 4 wv, 5 wo, 6 cos, 7 sin.
// ---------------------------------------------------------------------------
extern "C" void kernel_launch(void* const* d_in, const int* in_sizes, int n_in,
                              void* d_out, int out_size)
{
    (void)in_sizes; (void)n_in; (void)out_size;
    const float* hs = (const float*)d_in[0];
    const float* wq = (const float*)d_in[2];
    const float* wk = (const float*)d_in[3];
    const float* wv = (const float*)d_in[4];
    const float* wo = (const float*)d_in[5];
    const float* cs = (const float*)d_in[6];
    const float* sn = (const float*)d_in[7];
    float* out = (float*)d_out;

    float *hsr, *wqT, *wkvT, *woT, *q, *kvp, *qh, *kh, *vt, *ao;
    cudaGetSymbolAddress((void**)&hsr,  g_hsr);
    cudaGetSymbolAddress((void**)&wqT,  g_wqT);
    cudaGetSymbolAddress((void**)&wkvT, g_wkvT);
    cudaGetSymbolAddress((void**)&woT,  g_woT);
    cudaGetSymbolAddress((void**)&q,    g_q);
    cudaGetSymbolAddress((void**)&kvp,  g_kvp);
    cudaGetSymbolAddress((void**)&qh,   g_qh);
    cudaGetSymbolAddress((void**)&kh,   g_kh);
    cudaGetSymbolAddress((void**)&vt,   g_vt);
    cudaGetSymbolAddress((void**)&ao,   g_ao);

    cudaFuncSetAttribute(gemm_mma,  cudaFuncAttributeMaxDynamicSharedMemorySize, GEMM_SMEM);
    cudaFuncSetAttribute(flash_mma, cudaFuncAttributeMaxDynamicSharedMemorySize, FA_SMEM);

    // #1-#3: pre-passes needed by the projection GEMMs
    round_tf32_kernel<<<(S_LEN * HID / 4 + 255) / 256, 256>>>(hs, hsr, S_LEN * HID / 4);
    transpose_rna<<<dim3(NQ / 32, HID / 32), dim3(32, 8)>>>(wq, wqT, HID, NQ);
    transpose_kv <<<dim3(2 * NKVD / 32, HID / 32), dim3(32, 8)>>>(wk, wv, wkvT);

    // #4, #5: the projection GEMMs (ncu capture targets)
    gemm_mma<<<dim3(NQ / GBN, S_LEN / GBM), 256, GEMM_SMEM>>>(hsr, wqT, q, S_LEN, NQ, HID);
    gemm_mma<<<dim3(2 * NKVD / GBN, S_LEN / GBM), 256, GEMM_SMEM>>>(hsr, wkvT, kvp, S_LEN, 2 * NKVD, HID);

    // #6: wo transpose (needed only by the final GEMM)
    transpose_rna<<<dim3(HID / 32, NQ / 32), dim3(32, 8)>>>(wo, woT, NQ, HID);

    // #7-#9: RoPE + head-major (Q, K); V -> transposed [NKV][HD][S]
    rope_transpose<<<dim3(S_LEN, NH),  128>>>(q,   NQ,       cs, sn, qh);
    rope_transpose<<<dim3(S_LEN, NKV), 128>>>(kvp, 2 * NKVD, cs, sn, kh);
    transpose_vt<<<dim3(NKVD / 32, S_LEN / 32), dim3(32, 8)>>>(kvp + NKVD, vt);

    // #10: flash attention
    flash_mma<<<dim3(S_LEN / 128, NH), 256, FA_SMEM>>>(qh, kh, vt, ao);

    // #11: output projection
    gemm_mma<<<dim3(HID / GBN, S_LEN / GBM), 256, GEMM_SMEM>>>(ao, woT, out, S_LEN, HID, NQ);
}

// round 10
// speedup vs baseline: 3.8725x; 1.0554x over previous
#include <cuda_runtime.h>
#include <cuda_bf16.h>
#include <math.h>
#include <stdint.h>

// Problem constants
#define S_LEN 2048
#define HID   4096
#define NH    32
#define NKV   8
#define HD    128
#define NQ    (NH * HD)    // 4096
#define NKVD  (NKV * HD)   // 1024
#define NQKV  (NQ + 2 * NKVD)  // 6144

// ---------------------------------------------------------------------------
// Scratch (static device arrays; no cudaMalloc allowed)
// ---------------------------------------------------------------------------
__device__ float g_hsr  [S_LEN * HID];     // hidden states, tf32-rounded
__device__ float g_wqkvT[NQKV * HID];      // [wq^T ; wk^T ; wv^T]  [6144][4096]
__device__ float g_woT  [HID * NQ];        // wo^T  [4096][4096]
__device__ float g_qkv  [S_LEN * NQKV];    // QKV projection [S][6144]
__device__ float g_kh   [S_LEN * NKVD];    // K rope, head-major [NKV][S][HD]
__device__ float g_vt   [S_LEN * NKVD];    // V^T head-major [NKV][HD][S]
__device__ float g_ao   [S_LEN * NQ];      // attention out [S][4096]

// ---------------------------------------------------------------------------
// Helpers
// ---------------------------------------------------------------------------
__device__ __forceinline__ uint32_t smem_u32(const void* p) {
    uint32_t a;
    asm("{ .reg .u64 t; cvta.to.shared.u64 t, %1; cvt.u32.u64 %0, t; }"
        : "=r"(a) : "l"(p));
    return a;
}
__device__ __forceinline__ float rna_tf32(float v) {
    uint32_t o;
    asm("cvt.rna.tf32.f32 %0, %1;" : "=r"(o) : "f"(v));
    return __uint_as_float(o);
}
__device__ __forceinline__ void mma_tf32(float* c, const uint32_t* a, const uint32_t* b) {
    asm("mma.sync.aligned.m16n8k8.row.col.f32.tf32.tf32.f32 "
        "{%0,%1,%2,%3}, {%4,%5,%6,%7}, {%8,%9}, {%0,%1,%2,%3};"
        : "+f"(c[0]), "+f"(c[1]), "+f"(c[2]), "+f"(c[3])
        : "r"(a[0]), "r"(a[1]), "r"(a[2]), "r"(a[3]), "r"(b[0]), "r"(b[1]));
}
__device__ __forceinline__ void ldsm_x4(uint32_t* r, uint32_t saddr) {
    asm volatile("ldmatrix.sync.aligned.m8n8.x4.shared.b16 {%0,%1,%2,%3}, [%4];"
        : "=r"(r[0]), "=r"(r[1]), "=r"(r[2]), "=r"(r[3]) : "r"(saddr));
}
__device__ __forceinline__ void cpasync16(uint32_t dst, const void* src) {
    asm volatile("cp.async.cg.shared.global [%0], [%1], 16;" :: "r"(dst), "l"(src));
}
#define CP_COMMIT()  asm volatile("cp.async.commit_group;" ::: "memory")
#define CP_WAIT0()   asm volatile("cp.async.wait_group 0;" ::: "memory")
#define CP_WAIT1()   asm volatile("cp.async.wait_group 1;" ::: "memory")

// ---------------------------------------------------------------------------
// tf32 mma GEMM: C[M,N] = A[M,K] @ BT[N,K]^T. Block 128x128, 8 warps of
// 64x32 warp tiles, BK=32, 3-stage cp.async, ldmatrix. 2 CTAs/SM.
// (At ~97% of the tf32 mma.sync instruction-rate ceiling — do not touch.)
// ---------------------------------------------------------------------------
#define GBM 128
#define GBN 128
#define GBK 32
#define ASTR 36
#define BSTR 36
#define A_ST (128 * ASTR)
#define B_ST (128 * BSTR)
#define STAGE_FL (A_ST + B_ST)
#define GEMM_SMEM (3 * STAGE_FL * 4)   // 110592 B

__device__ __forceinline__ void gemm_load_stage(
    uint32_t a_dst, uint32_t b_dst, const float* ap, const float* bp, int K)
{
#pragma unroll
    for (int i = 0; i < 4; ++i)
        cpasync16(a_dst + i * 32 * ASTR * 4, ap + (size_t)i * 32 * K);
#pragma unroll
    for (int i = 0; i < 4; ++i)
        cpasync16(b_dst + i * 32 * BSTR * 4, bp + (size_t)i * 32 * K);
}

__global__ __launch_bounds__(256, 2) void gemm_mma(
    const float* __restrict__ A, const float* __restrict__ BT,
    float* __restrict__ C, int M, int N, int K)
{
    extern __shared__ float sm[];
    const uint32_t sb = smem_u32(sm);

    const int tid  = threadIdx.x;
    const int lane = tid & 31;
    const int wid  = tid >> 5;
    const int wm   = wid >> 2;
    const int wn   = wid & 3;
    const int g    = lane >> 2;
    const int tig  = lane & 3;
    const int bm   = blockIdx.y * GBM;
    const int bn   = blockIdx.x * GBN;

    const int lrow = tid >> 3;
    const int lcol = (tid & 7) * 4;
    const float* Ap = A  + (size_t)(bm + lrow) * K + lcol;
    const float* Bp = BT + (size_t)(bn + lrow) * K + lcol;
    const uint32_t a_dst = sb + (uint32_t)(lrow * ASTR + lcol) * 4;
    const uint32_t b_dst = sb + (uint32_t)(A_ST + lrow * BSTR + lcol) * 4;

    const int a_r = wm * 64 + (lane & 7) + ((lane >> 3) & 1) * 8;
    const int a_c = (lane >> 4) * 4;
    const uint32_t a_frag = sb + (uint32_t)(a_r * ASTR + a_c) * 4;
    const int b_r = wn * 32 + ((lane >> 4) & 1) * 8 + (lane & 7);
    const int b_c = ((lane >> 3) & 1) * 4;
    const uint32_t b_frag = sb + (uint32_t)(A_ST + b_r * BSTR + b_c) * 4;

    float c[4][4][4];
#pragma unroll
    for (int mt = 0; mt < 4; ++mt)
#pragma unroll
        for (int nt = 0; nt < 4; ++nt)
#pragma unroll
            for (int i = 0; i < 4; ++i) c[mt][nt][i] = 0.0f;

    const int nkt = K / GBK;
    gemm_load_stage(a_dst, b_dst, Ap, Bp, K); CP_COMMIT();
    gemm_load_stage(a_dst + STAGE_FL * 4, b_dst + STAGE_FL * 4,
                    Ap + GBK, Bp + GBK, K); CP_COMMIT();

#pragma unroll 1
    for (int kt = 0; kt < nkt; ++kt) {
        if (kt + 1 < nkt) { CP_WAIT1(); } else { CP_WAIT0(); }
        __syncthreads();
        if (kt + 2 < nkt) {
            const uint32_t so = (uint32_t)((kt + 2) % 3) * STAGE_FL * 4;
            gemm_load_stage(a_dst + so, b_dst + so,
                            Ap + (kt + 2) * GBK, Bp + (kt + 2) * GBK, K);
        }
        CP_COMMIT();

        const uint32_t so = (uint32_t)(kt % 3) * STAGE_FL * 4;
#pragma unroll
        for (int ks = 0; ks < 4; ++ks) {
            uint32_t af[4][4];
#pragma unroll
            for (int mt = 0; mt < 4; ++mt)
                ldsm_x4(af[mt], a_frag + so + (uint32_t)(mt * 16 * ASTR + ks * 8) * 4);
            uint32_t bf[4][2];
#pragma unroll
            for (int p = 0; p < 2; ++p) {
                uint32_t t4[4];
                ldsm_x4(t4, b_frag + so + (uint32_t)(p * 16 * BSTR + ks * 8) * 4);
                bf[2 * p][0] = t4[0]; bf[2 * p][1] = t4[1];
                bf[2 * p + 1][0] = t4[2]; bf[2 * p + 1][1] = t4[3];
            }
#pragma unroll
            for (int mt = 0; mt < 4; ++mt)
#pragma unroll
                for (int nt = 0; nt < 4; ++nt)
                    mma_tf32(c[mt][nt], af[mt], bf[nt]);
        }
    }

#pragma unroll
    for (int mt = 0; mt < 4; ++mt) {
        const int r0 = bm + wm * 64 + mt * 16 + g;
#pragma unroll
        for (int nt = 0; nt < 4; ++nt) {
            const int cc = bn + wn * 32 + nt * 8 + tig * 2;
            *(float2*)&C[(size_t)r0 * N + cc]       = make_float2(c[mt][nt][0], c[mt][nt][1]);
            *(float2*)&C[(size_t)(r0 + 8) * N + cc] = make_float2(c[mt][nt][2], c[mt][nt][3]);
        }
    }
}

// ---------------------------------------------------------------------------
// Pre-passes
// ---------------------------------------------------------------------------
__global__ __launch_bounds__(256) void round_tf32_kernel(
    const float* __restrict__ in, float* __restrict__ out, int n4)
{
    int i = blockIdx.x * 256 + threadIdx.x;
    if (i < n4) {
        float4 v = ((const float4*)in)[i];
        v.x = rna_tf32(v.x); v.y = rna_tf32(v.y);
        v.z = rna_tf32(v.z); v.w = rna_tf32(v.w);
        ((float4*)out)[i] = v;
    }
}

// High-MLP transpose + tf32-round: out[n*ldout+k] = rna(in[k*ldin+n]).
// Conflict-free 32x33 smem tiles, 4 k-tiles per block -> 16 independent LDGs
// per thread (latency-bound fix; old version ran at 1.3 TB/s, pure latency).
// Grid: (N/32, K/128).
__global__ __launch_bounds__(256) void transpose_fast(
    const float* __restrict__ in, float* __restrict__ out,
    int K, int N, int ldin, int ldout)
{
    __shared__ float t[4][32][33];
    const int n0 = blockIdx.x * 32;
    const int k0 = blockIdx.y * 128;
    const int tx = threadIdx.x & 31;
    const int wy = threadIdx.x >> 5;  // 0..7
#pragma unroll
    for (int tt = 0; tt < 4; ++tt)
#pragma unroll
        for (int j = 0; j < 4; ++j)
            t[tt][wy + 8 * j][tx] =
                in[(size_t)(k0 + tt * 32 + wy + 8 * j) * ldin + n0 + tx];
    __syncthreads();
#pragma unroll
    for (int tt = 0; tt < 4; ++tt)
#pragma unroll
        for (int j = 0; j < 4; ++j)
            out[(size_t)(n0 + wy + 8 * j) * ldout + k0 + tt * 32 + tx] =
                rna_tf32(t[tt][tx][wy + 8 * j]);
}

// ---------------------------------------------------------------------------
// RoPE + head-major transpose for K, tf32-rounded output.
// ---------------------------------------------------------------------------
__global__ __launch_bounds__(128) void rope_transpose(
    const float* __restrict__ src, int srcStride,
    const float* __restrict__ cosp, const float* __restrict__ sinp,
    float* __restrict__ dst)
{
    const int s = blockIdx.x;
    const int h = blockIdx.y;
    const int d = threadIdx.x;

    const float x   = src[(size_t)s * srcStride + h * HD + d];
    const float p   = src[(size_t)s * srcStride + h * HD + (d ^ 64)];
    const float rot = (d < 64) ? -p : p;
    const float val = x * cosp[s * HD + d] + rot * sinp[s * HD + d];
    dst[((size_t)h * S_LEN + s) * HD + d] = rna_tf32(val);
}

// ---------------------------------------------------------------------------
// Flash attention on mma.sync tf32 + ldmatrix. BM=128, BN=64, 8 warps.
// RoPE for Q applied inline in the prologue (reads raw QKV projection).
// Split-barrier cp.async overlap; commit order K,V,K,V...
// ---------------------------------------------------------------------------
#define FA_QSTR 132
#define FA_KSTR 132
#define FA_VSTR 68
#define FA_PSTR 68
#define FA_QS 0
#define FA_KS (128 * FA_QSTR)
#define FA_VT (FA_KS + 64 * FA_KSTR)
#define FA_PS (FA_VT + 128 * FA_VSTR)
#define FA_SMEM ((FA_PS + 128 * FA_PSTR) * 4)   // 171008 B

__global__ __launch_bounds__(256, 1) void flash_mma(
    const float* __restrict__ QKV, const float* __restrict__ cosp,
    const float* __restrict__ sinp, const float* __restrict__ Kh,
    const float* __restrict__ VT, float* __restrict__ O)
{
    extern __shared__ float sm[];
    const uint32_t sb = smem_u32(sm);

    const int tid  = threadIdx.x;
    const int lane = tid & 31;
    const int wid  = tid >> 5;
    const int g    = lane >> 2;
    const int tig  = lane & 3;
    const int qb   = gridDim.x - 1 - blockIdx.x;   // heavy CTAs first
    const int h    = blockIdx.y;
    const int kvh  = h >> 2;

    const float* Kbase  = Kh + (size_t)kvh * S_LEN * HD;
    const float* VTbase = VT + (size_t)kvh * HD * S_LEN;

    // Stage Q tile [128][128] with inline RoPE (reads raw projection)
#pragma unroll
    for (int j = 0; j < 16; ++j) {
        const int idx = tid + j * 256;
        const int r = idx >> 5, cb = (idx & 31) * 4;
        const int srow = qb * 128 + r;
        const float* qrow = QKV + (size_t)srow * NQKV + h * HD;
        float4 x  = *(const float4*)(qrow + cb);
        float4 p  = *(const float4*)(qrow + (cb ^ 64));
        float4 c4 = *(const float4*)(cosp + srow * HD + cb);
        float4 s4 = *(const float4*)(sinp + srow * HD + cb);
        const float sg = (cb < 64) ? -1.0f : 1.0f;
        float4 v;
        v.x = rna_tf32(x.x * c4.x + sg * p.x * s4.x);
        v.y = rna_tf32(x.y * c4.y + sg * p.y * s4.y);
        v.z = rna_tf32(x.z * c4.z + sg * p.z * s4.z);
        v.w = rna_tf32(x.w * c4.w + sg * p.w * s4.w);
        sm[FA_QS + r * FA_QSTR + cb + 0] = v.x;
        sm[FA_QS + r * FA_QSTR + cb + 1] = v.y;
        sm[FA_QS + r * FA_QSTR + cb + 2] = v.z;
        sm[FA_QS + r * FA_QSTR + cb + 3] = v.w;
    }

    const int krow = tid >> 5;
    const int kcb  = (tid & 31) * 4;
    const int vrow = tid >> 4;
    const int vkk  = (tid & 15) * 4;

    const int rsel = (lane & 7) + ((lane >> 3) & 1) * 8;
    const int csel = (lane >> 4) * 4;
    const int brsel = ((lane >> 4) & 1) * 8 + (lane & 7);
    const int bcsel = ((lane >> 3) & 1) * 4;
    const uint32_t q_frag = sb + (uint32_t)(FA_QS + (wid * 16 + rsel) * FA_QSTR + csel) * 4;
    const uint32_t k_frag = sb + (uint32_t)(FA_KS + brsel * FA_KSTR + bcsel) * 4;
    const uint32_t v_frag = sb + (uint32_t)(FA_VT + brsel * FA_VSTR + bcsel) * 4;
    const uint32_t p_frag = sb + (uint32_t)(FA_PS + (wid * 16 + rsel) * FA_PSTR + csel) * 4;

    float s[8][4], o[16][4], m_i[2], l_i[2];
    m_i[0] = m_i[1] = -1e30f;
    l_i[0] = l_i[1] = 0.0f;
#pragma unroll
    for (int nt = 0; nt < 16; ++nt)
#pragma unroll
        for (int i = 0; i < 4; ++i) o[nt][i] = 0.0f;

    const float sc = 0.08838834764831845f;
    const int qrow0 = qb * 128 + wid * 16 + g;
    const int jtmax = 2 * qb + 1;

    // Preload K(0) then V(0) as two separate cp.async groups
#pragma unroll
    for (int j = 0; j < 8; ++j) {
        const int r = krow + 8 * j;
        cpasync16(sb + (uint32_t)(FA_KS + r * FA_KSTR + kcb) * 4,
                  Kbase + (size_t)r * HD + kcb);
    }
    CP_COMMIT();
#pragma unroll
    for (int j = 0; j < 8; ++j) {
        const int d = vrow + 16 * j;
        cpasync16(sb + (uint32_t)(FA_VT + d * FA_VSTR + vkk) * 4,
                  VTbase + (size_t)d * S_LEN + vkk);
    }
    CP_COMMIT();

    for (int jt = 0; jt <= jtmax; ++jt) {
        CP_WAIT1();
        __syncthreads();

#pragma unroll
        for (int nt = 0; nt < 8; ++nt)
#pragma unroll
            for (int i = 0; i < 4; ++i) s[nt][i] = 0.0f;

#pragma unroll
        for (int ks = 0; ks < 16; ++ks) {
            uint32_t a[4];
            ldsm_x4(a, q_frag + ks * 32);
#pragma unroll
            for (int p = 0; p < 4; ++p) {
                uint32_t t4[4];
                ldsm_x4(t4, k_frag + (uint32_t)(p * 16 * FA_KSTR) * 4 + ks * 32);
                mma_tf32(s[2 * p],     a, t4);
                mma_tf32(s[2 * p + 1], a, t4 + 2);
            }
        }

        __syncthreads();
        if (jt < jtmax) {
#pragma unroll
            for (int j = 0; j < 8; ++j) {
                const int r = krow + 8 * j;
                cpasync16(sb + (uint32_t)(FA_KS + r * FA_KSTR + kcb) * 4,
                          Kbase + (size_t)((jt + 1) * 64 + r) * HD + kcb);
            }
        }
        CP_COMMIT();

        const int colb = jt * 64 + tig * 2;
#pragma unroll
        for (int nt = 0; nt < 8; ++nt) {
            const int c0 = colb + nt * 8, c1 = c0 + 1;
            s[nt][0] = (c0 > qrow0)     ? -1e30f : s[nt][0] * sc;
            s[nt][1] = (c1 > qrow0)     ? -1e30f : s[nt][1] * sc;
            s[nt][2] = (c0 > qrow0 + 8) ? -1e30f : s[nt][2] * sc;
            s[nt][3] = (c1 > qrow0 + 8) ? -1e30f : s[nt][3] * sc;
        }

        float mx0 = -1e30f, mx1 = -1e30f;
#pragma unroll
        for (int nt = 0; nt < 8; ++nt) {
            mx0 = fmaxf(mx0, fmaxf(s[nt][0], s[nt][1]));
            mx1 = fmaxf(mx1, fmaxf(s[nt][2], s[nt][3]));
        }
        mx0 = fmaxf(mx0, __shfl_xor_sync(0xffffffffu, mx0, 1));
        mx0 = fmaxf(mx0, __shfl_xor_sync(0xffffffffu, mx0, 2));
        mx1 = fmaxf(mx1, __shfl_xor_sync(0xffffffffu, mx1, 1));
        mx1 = fmaxf(mx1, __shfl_xor_sync(0xffffffffu, mx1, 2));

        const float mn0 = fmaxf(m_i[0], mx0);
        const float mn1 = fmaxf(m_i[1], mx1);
        const float al0 = __expf(m_i[0] - mn0);
        const float al1 = __expf(m_i[1] - mn1);
        m_i[0] = mn0; m_i[1] = mn1;

        float rs0 = 0.0f, rs1 = 0.0f;
#pragma unroll
        for (int nt = 0; nt < 8; ++nt) {
            s[nt][0] = __expf(s[nt][0] - mn0);
            s[nt][1] = __expf(s[nt][1] - mn0);
            s[nt][2] = __expf(s[nt][2] - mn1);
            s[nt][3] = __expf(s[nt][3] - mn1);
            rs0 += s[nt][0] + s[nt][1];
            rs1 += s[nt][2] + s[nt][3];
        }
        rs0 += __shfl_xor_sync(0xffffffffu, rs0, 1);
        rs0 += __shfl_xor_sync(0xffffffffu, rs0, 2);
        rs1 += __shfl_xor_sync(0xffffffffu, rs1, 1);
        rs1 += __shfl_xor_sync(0xffffffffu, rs1, 2);
        l_i[0] = l_i[0] * al0 + rs0;
        l_i[1] = l_i[1] * al1 + rs1;
#pragma unroll
        for (int nt = 0; nt < 16; ++nt) {
            o[nt][0] *= al0; o[nt][1] *= al0;
            o[nt][2] *= al1; o[nt][3] *= al1;
        }

        {
            const int r = wid * 16 + g;
#pragma unroll
            for (int nt = 0; nt < 8; ++nt) {
                const int cc = nt * 8 + tig * 2;
                *(float2*)&sm[FA_PS + r * FA_PSTR + cc] =
                    make_float2(rna_tf32(s[nt][0]), rna_tf32(s[nt][1]));
                *(float2*)&sm[FA_PS + (r + 8) * FA_PSTR + cc] =
                    make_float2(rna_tf32(s[nt][2]), rna_tf32(s[nt][3]));
            }
        }

        CP_WAIT1();
        __syncthreads();

#pragma unroll
        for (int ks = 0; ks < 8; ++ks) {
            uint32_t a[4];
            ldsm_x4(a, p_frag + ks * 32);
#pragma unroll
            for (int p = 0; p < 8; ++p) {
                uint32_t t4[4];
                ldsm_x4(t4, v_frag + (uint32_t)(p * 16 * FA_VSTR) * 4 + ks * 32);
                mma_tf32(o[2 * p],     a, t4);
                mma_tf32(o[2 * p + 1], a, t4 + 2);
            }
        }

        __syncthreads();
        if (jt < jtmax) {
#pragma unroll
            for (int j = 0; j < 8; ++j) {
                const int d = vrow + 16 * j;
                cpasync16(sb + (uint32_t)(FA_VT + d * FA_VSTR + vkk) * 4,
                          VTbase + (size_t)d * S_LEN + (jt + 1) * 64 + vkk);
            }
        }
        CP_COMMIT();
    }

    const float inv0 = 1.0f / l_i[0];
    const float inv1 = 1.0f / l_i[1];
    float* Op = O + (size_t)qrow0 * NQ + h * HD;
#pragma unroll
    for (int nt = 0; nt < 16; ++nt) {
        const int cc = nt * 8 + tig * 2;
        *(float2*)&Op[cc] =
            make_float2(rna_tf32(o[nt][0] * inv0), rna_tf32(o[nt][1] * inv0));
        *(float2*)&Op[(size_t)8 * NQ + cc] =
            make_float2(rna_tf32(o[nt][2] * inv1), rna_tf32(o[nt][3] * inv1));
    }
}

// ---------------------------------------------------------------------------
// Launch. Inputs: 0 hidden_states, 1 attention_mask (unused), 2 wq, 3 wk,
// 4 wv, 5 wo, 6 cos, 7 sin.
// ---------------------------------------------------------------------------
extern "C" void kernel_launch(void* const* d_in, const int* in_sizes, int n_in,
                              void* d_out, int out_size)
{
    (void)in_sizes; (void)n_in; (void)out_size;
    const float* hs = (const float*)d_in[0];
    const float* wq = (const float*)d_in[2];
    const float* wk = (const float*)d_in[3];
    const float* wv = (const float*)d_in[4];
    const float* wo = (const float*)d_in[5];
    const float* cs = (const float*)d_in[6];
    const float* sn = (const float*)d_in[7];
    float* out = (float*)d_out;

    float *hsr, *wqkvT, *woT, *qkv, *kh, *vt, *ao;
    cudaGetSymbolAddress((void**)&hsr,   g_hsr);
    cudaGetSymbolAddress((void**)&wqkvT, g_wqkvT);
    cudaGetSymbolAddress((void**)&woT,   g_woT);
    cudaGetSymbolAddress((void**)&qkv,   g_qkv);
    cudaGetSymbolAddress((void**)&kh,    g_kh);
    cudaGetSymbolAddress((void**)&vt,    g_vt);
    cudaGetSymbolAddress((void**)&ao,    g_ao);

    cudaFuncSetAttribute(gemm_mma,  cudaFuncAttributeMaxDynamicSharedMemorySize, GEMM_SMEM);
    cudaFuncSetAttribute(flash_mma, cudaFuncAttributeMaxDynamicSharedMemorySize, FA_SMEM);

    // #1-#4: pre-passes for the fused QKV GEMM
    round_tf32_kernel<<<(S_LEN * HID / 4 + 255) / 256, 256>>>(hs, hsr, S_LEN * HID / 4);
    transpose_fast<<<dim3(NQ / 32,   HID / 128), 256>>>(wq, wqkvT,                        HID, NQ,   NQ,   HID);
    transpose_fast<<<dim3(NKVD / 32, HID / 128), 256>>>(wk, wqkvT + (size_t)NQ * HID,     HID, NKVD, NKVD, HID);
    transpose_fast<<<dim3(NKVD / 32, HID / 128), 256>>>(wv, wqkvT + (size_t)(NQ + NKVD) * HID, HID, NKVD, NKVD, HID);

    // #5: fused QKV projection (one N=6144 GEMM)
    gemm_mma<<<dim3(NQKV / GBN, S_LEN / GBM), 256, GEMM_SMEM>>>(hsr, wqkvT, qkv, S_LEN, NQKV, HID);

    // #6: wo transpose (only needed by the final GEMM)
    transpose_fast<<<dim3(HID / 32, NQ / 128), 256>>>(wo, woT, NQ, HID, HID, NQ);

    // #7-#8: K rope (head-major) + V^T
    rope_transpose<<<dim3(S_LEN, NKV), 128>>>(qkv + NQ, NQKV, cs, sn, kh);
    transpose_fast<<<dim3(NKVD / 32, S_LEN / 128), 256>>>(qkv + NQ + NKVD, vt, S_LEN, NKVD, NQKV, S_LEN);

    // #9: flash attention (Q rope fused into prologue)
    flash_mma<<<dim3(S_LEN / 128, NH), 256, FA_SMEM>>>(qkv, cs, sn, kh, vt, ao);

    // #10: output projection
    gemm_mma<<<dim3(HID / GBN, S_LEN / GBM), 256, GEMM_SMEM>>>(ao, woT, out, S_LEN, HID, NQ);
}

// round 11
// speedup vs baseline: 3.9756x; 1.0266x over previous
#include <cuda_runtime.h>
#include <cuda_bf16.h>
#include <math.h>
#include <stdint.h>

// Problem constants
#define S_LEN 2048
#define HID   4096
#define NH    32
#define NKV   8
#define HD    128
#define NQ    (NH * HD)    // 4096
#define NKVD  (NKV * HD)   // 1024
#define NQKV  (NQ + 2 * NKVD)  // 6144

// ---------------------------------------------------------------------------
// Scratch (static device arrays; no cudaMalloc allowed)
// ---------------------------------------------------------------------------
__device__ float g_hsr  [S_LEN * HID];     // hidden states, tf32-rounded
__device__ float g_wqkvT[NQKV * HID];      // [wq^T ; wk^T ; wv^T]  [6144][4096]
__device__ float g_woT  [HID * NQ];        // wo^T  [4096][4096]
__device__ float g_qkv  [S_LEN * NQKV];    // QKV projection [S][6144]
__device__ float g_kh   [S_LEN * NKVD];    // K rope, head-major [NKV][S][HD]
__device__ float g_vt   [S_LEN * NKVD];    // V^T head-major [NKV][HD][S]
__device__ float g_ao   [S_LEN * NQ];      // attention out [S][4096]

// ---------------------------------------------------------------------------
// Helpers
// ---------------------------------------------------------------------------
__device__ __forceinline__ uint32_t smem_u32(const void* p) {
    uint32_t a;
    asm("{ .reg .u64 t; cvta.to.shared.u64 t, %1; cvt.u32.u64 %0, t; }"
        : "=r"(a) : "l"(p));
    return a;
}
__device__ __forceinline__ float rna_tf32(float v) {
    uint32_t o;
    asm("cvt.rna.tf32.f32 %0, %1;" : "=r"(o) : "f"(v));
    return __uint_as_float(o);
}
__device__ __forceinline__ void mma_tf32(float* c, const uint32_t* a, const uint32_t* b) {
    asm("mma.sync.aligned.m16n8k8.row.col.f32.tf32.tf32.f32 "
        "{%0,%1,%2,%3}, {%4,%5,%6,%7}, {%8,%9}, {%0,%1,%2,%3};"
        : "+f"(c[0]), "+f"(c[1]), "+f"(c[2]), "+f"(c[3])
        : "r"(a[0]), "r"(a[1]), "r"(a[2]), "r"(a[3]), "r"(b[0]), "r"(b[1]));
}
__device__ __forceinline__ void ldsm_x4(uint32_t* r, uint32_t saddr) {
    asm volatile("ldmatrix.sync.aligned.m8n8.x4.shared.b16 {%0,%1,%2,%3}, [%4];"
        : "=r"(r[0]), "=r"(r[1]), "=r"(r[2]), "=r"(r[3]) : "r"(saddr));
}
__device__ __forceinline__ void cpasync16(uint32_t dst, const void* src) {
    asm volatile("cp.async.cg.shared.global [%0], [%1], 16;" :: "r"(dst), "l"(src));
}
#define CP_COMMIT()  asm volatile("cp.async.commit_group;" ::: "memory")
#define CP_WAIT0()   asm volatile("cp.async.wait_group 0;" ::: "memory")
#define CP_WAIT1()   asm volatile("cp.async.wait_group 1;" ::: "memory")

// ---------------------------------------------------------------------------
// tf32 mma GEMM: C[M,N] = A[M,K] @ BT[N,K]^T. Block 128x128, 8 warps of
// 64x32 warp tiles, BK=32, 3-stage cp.async, ldmatrix. 2 CTAs/SM.
// (At ~97% of the tf32 mma.sync instruction-rate ceiling — do not touch.)
// ---------------------------------------------------------------------------
#define GBM 128
#define GBN 128
#define GBK 32
#define ASTR 36
#define BSTR 36
#define A_ST (128 * ASTR)
#define B_ST (128 * BSTR)
#define STAGE_FL (A_ST + B_ST)
#define GEMM_SMEM (3 * STAGE_FL * 4)   // 110592 B

__device__ __forceinline__ void gemm_load_stage(
    uint32_t a_dst, uint32_t b_dst, const float* ap, const float* bp, int K)
{
#pragma unroll
    for (int i = 0; i < 4; ++i)
        cpasync16(a_dst + i * 32 * ASTR * 4, ap + (size_t)i * 32 * K);
#pragma unroll
    for (int i = 0; i < 4; ++i)
        cpasync16(b_dst + i * 32 * BSTR * 4, bp + (size_t)i * 32 * K);
}

__global__ __launch_bounds__(256, 2) void gemm_mma(
    const float* __restrict__ A, const float* __restrict__ BT,
    float* __restrict__ C, int M, int N, int K)
{
    extern __shared__ float sm[];
    const uint32_t sb = smem_u32(sm);

    const int tid  = threadIdx.x;
    const int lane = tid & 31;
    const int wid  = tid >> 5;
    const int wm   = wid >> 2;
    const int wn   = wid & 3;
    const int g    = lane >> 2;
    const int tig  = lane & 3;
    const int bm   = blockIdx.y * GBM;
    const int bn   = blockIdx.x * GBN;

    const int lrow = tid >> 3;
    const int lcol = (tid & 7) * 4;
    const float* Ap = A  + (size_t)(bm + lrow) * K + lcol;
    const float* Bp = BT + (size_t)(bn + lrow) * K + lcol;
    const uint32_t a_dst = sb + (uint32_t)(lrow * ASTR + lcol) * 4;
    const uint32_t b_dst = sb + (uint32_t)(A_ST + lrow * BSTR + lcol) * 4;

    const int a_r = wm * 64 + (lane & 7) + ((lane >> 3) & 1) * 8;
    const int a_c = (lane >> 4) * 4;
    const uint32_t a_frag = sb + (uint32_t)(a_r * ASTR + a_c) * 4;
    const int b_r = wn * 32 + ((lane >> 4) & 1) * 8 + (lane & 7);
    const int b_c = ((lane >> 3) & 1) * 4;
    const uint32_t b_frag = sb + (uint32_t)(A_ST + b_r * BSTR + b_c) * 4;

    float c[4][4][4];
#pragma unroll
    for (int mt = 0; mt < 4; ++mt)
#pragma unroll
        for (int nt = 0; nt < 4; ++nt)
#pragma unroll
            for (int i = 0; i < 4; ++i) c[mt][nt][i] = 0.0f;

    const int nkt = K / GBK;
    gemm_load_stage(a_dst, b_dst, Ap, Bp, K); CP_COMMIT();
    gemm_load_stage(a_dst + STAGE_FL * 4, b_dst + STAGE_FL * 4,
                    Ap + GBK, Bp + GBK, K); CP_COMMIT();

#pragma unroll 1
    for (int kt = 0; kt < nkt; ++kt) {
        if (kt + 1 < nkt) { CP_WAIT1(); } else { CP_WAIT0(); }
        __syncthreads();
        if (kt + 2 < nkt) {
            const uint32_t so = (uint32_t)((kt + 2) % 3) * STAGE_FL * 4;
            gemm_load_stage(a_dst + so, b_dst + so,
                            Ap + (kt + 2) * GBK, Bp + (kt + 2) * GBK, K);
        }
        CP_COMMIT();

        const uint32_t so = (uint32_t)(kt % 3) * STAGE_FL * 4;
#pragma unroll
        for (int ks = 0; ks < 4; ++ks) {
            uint32_t af[4][4];
#pragma unroll
            for (int mt = 0; mt < 4; ++mt)
                ldsm_x4(af[mt], a_frag + so + (uint32_t)(mt * 16 * ASTR + ks * 8) * 4);
            uint32_t bf[4][2];
#pragma unroll
            for (int p = 0; p < 2; ++p) {
                uint32_t t4[4];
                ldsm_x4(t4, b_frag + so + (uint32_t)(p * 16 * BSTR + ks * 8) * 4);
                bf[2 * p][0] = t4[0]; bf[2 * p][1] = t4[1];
                bf[2 * p + 1][0] = t4[2]; bf[2 * p + 1][1] = t4[3];
            }
#pragma unroll
            for (int mt = 0; mt < 4; ++mt)
#pragma unroll
                for (int nt = 0; nt < 4; ++nt)
                    mma_tf32(c[mt][nt], af[mt], bf[nt]);
        }
    }

#pragma unroll
    for (int mt = 0; mt < 4; ++mt) {
        const int r0 = bm + wm * 64 + mt * 16 + g;
#pragma unroll
        for (int nt = 0; nt < 4; ++nt) {
            const int cc = bn + wn * 32 + nt * 8 + tig * 2;
            *(float2*)&C[(size_t)r0 * N + cc]       = make_float2(c[mt][nt][0], c[mt][nt][1]);
            *(float2*)&C[(size_t)(r0 + 8) * N + cc] = make_float2(c[mt][nt][2], c[mt][nt][3]);
        }
    }
}

// ---------------------------------------------------------------------------
// Pre-passes
// ---------------------------------------------------------------------------
__global__ __launch_bounds__(256) void round_tf32_kernel(
    const float* __restrict__ in, float* __restrict__ out, int n4)
{
    int i = blockIdx.x * 256 + threadIdx.x;
    if (i < n4) {
        float4 v = ((const float4*)in)[i];
        v.x = rna_tf32(v.x); v.y = rna_tf32(v.y);
        v.z = rna_tf32(v.z); v.w = rna_tf32(v.w);
        ((float4*)out)[i] = v;
    }
}

// High-MLP transpose + tf32-round: out[n*ldout+k] = rna(in[k*ldin+n]).
__global__ __launch_bounds__(256) void transpose_fast(
    const float* __restrict__ in, float* __restrict__ out,
    int K, int N, int ldin, int ldout)
{
    __shared__ float t[4][32][33];
    const int n0 = blockIdx.x * 32;
    const int k0 = blockIdx.y * 128;
    const int tx = threadIdx.x & 31;
    const int wy = threadIdx.x >> 5;  // 0..7
#pragma unroll
    for (int tt = 0; tt < 4; ++tt)
#pragma unroll
        for (int j = 0; j < 4; ++j)
            t[tt][wy + 8 * j][tx] =
                in[(size_t)(k0 + tt * 32 + wy + 8 * j) * ldin + n0 + tx];
    __syncthreads();
#pragma unroll
    for (int tt = 0; tt < 4; ++tt)
#pragma unroll
        for (int j = 0; j < 4; ++j)
            out[(size_t)(n0 + wy + 8 * j) * ldout + k0 + tt * 32 + tx] =
                rna_tf32(t[tt][tx][wy + 8 * j]);
}

// ---------------------------------------------------------------------------
// RoPE + head-major transpose for K, tf32-rounded output.
// ---------------------------------------------------------------------------
__global__ __launch_bounds__(128) void rope_transpose(
    const float* __restrict__ src, int srcStride,
    const float* __restrict__ cosp, const float* __restrict__ sinp,
    float* __restrict__ dst)
{
    const int s = blockIdx.x;
    const int h = blockIdx.y;
    const int d = threadIdx.x;

    const float x   = src[(size_t)s * srcStride + h * HD + d];
    const float p   = src[(size_t)s * srcStride + h * HD + (d ^ 64)];
    const float rot = (d < 64) ? -p : p;
    const float val = x * cosp[s * HD + d] + rot * sinp[s * HD + d];
    dst[((size_t)h * S_LEN + s) * HD + d] = rna_tf32(val);
}

// ---------------------------------------------------------------------------
// Flash attention, 2 CTAs/SM version. BM=64, BN=64, 4 warps (16 q-rows each).
// No P smem: PV A-fragments built from softmax C-fragments via quad shuffles.
// Q rope fused in prologue. Split-barrier cp.async overlap (K,V,K,V groups).
// smem: Q 64x132 + K 64x132 + VT 128x68 = 102400 B -> 2 CTAs/SM.
// ---------------------------------------------------------------------------
#define FB_QSTR 132
#define FB_KSTR 132
#define FB_VSTR 68
#define FB_QS 0
#define FB_KS (64 * FB_QSTR)                // 8448
#define FB_VT (FB_KS + 64 * FB_KSTR)        // 16896
#define FB_SMEM ((FB_VT + 128 * FB_VSTR) * 4)   // 102400 B

__global__ __launch_bounds__(128, 2) void flash_mma(
    const float* __restrict__ QKV, const float* __restrict__ cosp,
    const float* __restrict__ sinp, const float* __restrict__ Kh,
    const float* __restrict__ VT, float* __restrict__ O)
{
    extern __shared__ float sm[];
    const uint32_t sb = smem_u32(sm);

    const int tid  = threadIdx.x;
    const int lane = tid & 31;
    const int wid  = tid >> 5;          // 0..3, 16 q-rows each
    const int g    = lane >> 2;
    const int tig  = lane & 3;
    const int qb   = gridDim.x - 1 - blockIdx.x;   // heavy CTAs first
    const int h    = blockIdx.y;
    const int kvh  = h >> 2;

    const float* Kbase  = Kh + (size_t)kvh * S_LEN * HD;
    const float* VTbase = VT + (size_t)kvh * HD * S_LEN;

    // Stage Q tile [64][128] with inline RoPE (reads raw projection)
#pragma unroll
    for (int j = 0; j < 16; ++j) {
        const int idx = tid + j * 128;
        const int r = idx >> 5, cb = (idx & 31) * 4;
        const int srow = qb * 64 + r;
        const float* qrow = QKV + (size_t)srow * NQKV + h * HD;
        float4 x  = *(const float4*)(qrow + cb);
        float4 p  = *(const float4*)(qrow + (cb ^ 64));
        float4 c4 = *(const float4*)(cosp + srow * HD + cb);
        float4 s4 = *(const float4*)(sinp + srow * HD + cb);
        const float sg = (cb < 64) ? -1.0f : 1.0f;
        sm[FB_QS + r * FB_QSTR + cb + 0] = rna_tf32(x.x * c4.x + sg * p.x * s4.x);
        sm[FB_QS + r * FB_QSTR + cb + 1] = rna_tf32(x.y * c4.y + sg * p.y * s4.y);
        sm[FB_QS + r * FB_QSTR + cb + 2] = rna_tf32(x.z * c4.z + sg * p.z * s4.z);
        sm[FB_QS + r * FB_QSTR + cb + 3] = rna_tf32(x.w * c4.w + sg * p.w * s4.w);
    }

    // ldmatrix per-lane bases
    const int rsel  = (lane & 7) + ((lane >> 3) & 1) * 8;
    const int csel  = (lane >> 4) * 4;
    const int brsel = ((lane >> 4) & 1) * 8 + (lane & 7);
    const int bcsel = ((lane >> 3) & 1) * 4;
    const uint32_t q_frag = sb + (uint32_t)(FB_QS + (wid * 16 + rsel) * FB_QSTR + csel) * 4;
    const uint32_t k_frag = sb + (uint32_t)(FB_KS + brsel * FB_KSTR + bcsel) * 4;
    const uint32_t v_frag = sb + (uint32_t)(FB_VT + brsel * FB_VSTR + bcsel) * 4;

    float s[8][4], o[16][4], m_i[2], l_i[2];
    m_i[0] = m_i[1] = -1e30f;
    l_i[0] = l_i[1] = 0.0f;
#pragma unroll
    for (int nt = 0; nt < 16; ++nt)
#pragma unroll
        for (int i = 0; i < 4; ++i) o[nt][i] = 0.0f;

    const float sc = 0.08838834764831845f;  // 1/sqrt(128)
    const int qrow0 = qb * 64 + wid * 16 + g;
    const int jtmax = qb;

    // Preload K(0) then V(0) as two separate cp.async groups.
    // K: 64 rows x 128 cols; V^T: 128 rows x 64 cols. 16 chunks/thread each.
#pragma unroll
    for (int j = 0; j < 16; ++j) {
        const int idx = tid + j * 128;
        const int r = idx >> 5, c = (idx & 31) * 4;
        cpasync16(sb + (uint32_t)(FB_KS + r * FB_KSTR + c) * 4,
                  Kbase + (size_t)r * HD + c);
    }
    CP_COMMIT();
#pragma unroll
    for (int j = 0; j < 16; ++j) {
        const int idx = tid + j * 128;
        const int d = idx >> 4, c = (idx & 15) * 4;
        cpasync16(sb + (uint32_t)(FB_VT + d * FB_VSTR + c) * 4,
                  VTbase + (size_t)d * S_LEN + c);
    }
    CP_COMMIT();

    for (int jt = 0; jt <= jtmax; ++jt) {
        CP_WAIT1();          // K(jt) landed (V(jt) may still be in flight)
        __syncthreads();

        // S = Q K^T  (16 x 64 per warp)
#pragma unroll
        for (int nt = 0; nt < 8; ++nt)
#pragma unroll
            for (int i = 0; i < 4; ++i) s[nt][i] = 0.0f;

#pragma unroll
        for (int ks = 0; ks < 16; ++ks) {
            uint32_t a[4];
            ldsm_x4(a, q_frag + ks * 32);
#pragma unroll
            for (int p = 0; p < 4; ++p) {
                uint32_t t4[4];
                ldsm_x4(t4, k_frag + (uint32_t)(p * 16 * FB_KSTR) * 4 + ks * 32);
                mma_tf32(s[2 * p],     a, t4);
                mma_tf32(s[2 * p + 1], a, t4 + 2);
            }
        }

        __syncthreads();     // all warps done reading K(jt)
        if (jt < jtmax) {    // stage K(jt+1); overlaps softmax + PV
#pragma unroll
            for (int j = 0; j < 16; ++j) {
                const int idx = tid + j * 128;
                const int r = idx >> 5, c = (idx & 31) * 4;
                cpasync16(sb + (uint32_t)(FB_KS + r * FB_KSTR + c) * 4,
                          Kbase + (size_t)((jt + 1) * 64 + r) * HD + c);
            }
        }
        CP_COMMIT();

        // Scale + causal mask
        const int colb = jt * 64 + tig * 2;
#pragma unroll
        for (int nt = 0; nt < 8; ++nt) {
            const int c0 = colb + nt * 8, c1 = c0 + 1;
            s[nt][0] = (c0 > qrow0)     ? -1e30f : s[nt][0] * sc;
            s[nt][1] = (c1 > qrow0)     ? -1e30f : s[nt][1] * sc;
            s[nt][2] = (c0 > qrow0 + 8) ? -1e30f : s[nt][2] * sc;
            s[nt][3] = (c1 > qrow0 + 8) ? -1e30f : s[nt][3] * sc;
        }

        // Online softmax (rows warp-private; quad reductions)
        float mx0 = -1e30f, mx1 = -1e30f;
#pragma unroll
        for (int nt = 0; nt < 8; ++nt) {
            mx0 = fmaxf(mx0, fmaxf(s[nt][0], s[nt][1]));
            mx1 = fmaxf(mx1, fmaxf(s[nt][2], s[nt][3]));
        }
        mx0 = fmaxf(mx0, __shfl_xor_sync(0xffffffffu, mx0, 1));
        mx0 = fmaxf(mx0, __shfl_xor_sync(0xffffffffu, mx0, 2));
        mx1 = fmaxf(mx1, __shfl_xor_sync(0xffffffffu, mx1, 1));
        mx1 = fmaxf(mx1, __shfl_xor_sync(0xffffffffu, mx1, 2));

        const float mn0 = fmaxf(m_i[0], mx0);
        const float mn1 = fmaxf(m_i[1], mx1);
        const float al0 = __expf(m_i[0] - mn0);
        const float al1 = __expf(m_i[1] - mn1);
        m_i[0] = mn0; m_i[1] = mn1;

        float rs0 = 0.0f, rs1 = 0.0f;
#pragma unroll
        for (int nt = 0; nt < 8; ++nt) {
            s[nt][0] = __expf(s[nt][0] - mn0);
            s[nt][1] = __expf(s[nt][1] - mn0);
            s[nt][2] = __expf(s[nt][2] - mn1);
            s[nt][3] = __expf(s[nt][3] - mn1);
            rs0 += s[nt][0] + s[nt][1];
            rs1 += s[nt][2] + s[nt][3];
        }
        rs0 += __shfl_xor_sync(0xffffffffu, rs0, 1);
        rs0 += __shfl_xor_sync(0xffffffffu, rs0, 2);
        rs1 += __shfl_xor_sync(0xffffffffu, rs1, 1);
        rs1 += __shfl_xor_sync(0xffffffffu, rs1, 2);
        l_i[0] = l_i[0] * al0 + rs0;
        l_i[1] = l_i[1] * al1 + rs1;
#pragma unroll
        for (int nt = 0; nt < 16; ++nt) {
            o[nt][0] *= al0; o[nt][1] *= al0;
            o[nt][2] *= al1; o[nt][3] *= al1;
        }

        CP_WAIT1();          // V(jt) landed (K(jt+1) may still be in flight)
        __syncthreads();

        // O += P @ V. A-fragments built from C-layout s[] via quad shuffles:
        // C-frag: lane holds (g, 2tig),(g, 2tig+1),(g+8, 2tig),(g+8, 2tig+1).
        // A-frag needs (g,tig),(g+8,tig),(g,tig+4),(g+8,tig+4):
        //   col tig   lives in quad-lane tig>>1, element tig&1
        //   col tig+4 lives in quad-lane (tig>>1)+2, element tig&1
        const int qbase = lane & ~3;
        const int srcA  = qbase | (tig >> 1);
        const int srcB  = srcA + 2;
        const bool odd  = (tig & 1);
#pragma unroll
        for (int ks = 0; ks < 8; ++ks) {
            const float p0 = s[ks][0], p1 = s[ks][1];
            const float p2 = s[ks][2], p3 = s[ks][3];
            const float a0A = __shfl_sync(0xffffffffu, p0, srcA);
            const float a1A = __shfl_sync(0xffffffffu, p1, srcA);
            const float a2A = __shfl_sync(0xffffffffu, p2, srcA);
            const float a3A = __shfl_sync(0xffffffffu, p3, srcA);
            const float a0B = __shfl_sync(0xffffffffu, p0, srcB);
            const float a1B = __shfl_sync(0xffffffffu, p1, srcB);
            const float a2B = __shfl_sync(0xffffffffu, p2, srcB);
            const float a3B = __shfl_sync(0xffffffffu, p3, srcB);
            uint32_t a[4];
            a[0] = __float_as_uint(rna_tf32(odd ? a1A : a0A));  // (g,    tig)
            a[1] = __float_as_uint(rna_tf32(odd ? a3A : a2A));  // (g+8,  tig)
            a[2] = __float_as_uint(rna_tf32(odd ? a1B : a0B));  // (g,    tig+4)
            a[3] = __float_as_uint(rna_tf32(odd ? a3B : a2B));  // (g+8,  tig+4)
#pragma unroll
            for (int p = 0; p < 8; ++p) {
                uint32_t t4[4];
                ldsm_x4(t4, v_frag + (uint32_t)(p * 16 * FB_VSTR) * 4 + ks * 32);
                mma_tf32(o[2 * p],     a, t4);
                mma_tf32(o[2 * p + 1], a, t4 + 2);
            }
        }

        __syncthreads();     // all warps done reading V(jt)
        if (jt < jtmax) {    // stage V(jt+1); overlaps next QK
#pragma unroll
            for (int j = 0; j < 16; ++j) {
                const int idx = tid + j * 128;
                const int d = idx >> 4, c = (idx & 15) * 4;
                cpasync16(sb + (uint32_t)(FB_VT + d * FB_VSTR + c) * 4,
                          VTbase + (size_t)d * S_LEN + (jt + 1) * 64 + c);
            }
        }
        CP_COMMIT();
    }

    // Epilogue: normalize, tf32-round, write [S][NQ]
    const float inv0 = 1.0f / l_i[0];
    const float inv1 = 1.0f / l_i[1];
    float* Op = O + (size_t)qrow0 * NQ + h * HD;
#pragma unroll
    for (int nt = 0; nt < 16; ++nt) {
        const int cc = nt * 8 + tig * 2;
        *(float2*)&Op[cc] =
            make_float2(rna_tf32(o[nt][0] * inv0), rna_tf32(o[nt][1] * inv0));
        *(float2*)&Op[(size_t)8 * NQ + cc] =
            make_float2(rna_tf32(o[nt][2] * inv1), rna_tf32(o[nt][3] * inv1));
    }
}

// ---------------------------------------------------------------------------
// Launch. Inputs: 0 hidden_states, 1 attention_mask (unused), 2 wq, 3 wk,
// 4 wv, 5 wo, 6 cos, 7 sin.
// ---------------------------------------------------------------------------
extern "C" void kernel_launch(void* const* d_in, const int* in_sizes, int n_in,
                              void* d_out, int out_size)
{
    (void)in_sizes; (void)n_in; (void)out_size;
    const float* hs = (const float*)d_in[0];
    const float* wq = (const float*)d_in[2];
    const float* wk = (const float*)d_in[3];
    const float* wv = (const float*)d_in[4];
    const float* wo = (const float*)d_in[5];
    const float* cs = (const float*)d_in[6];
    const float* sn = (const float*)d_in[7];
    float* out = (float*)d_out;

    float *hsr, *wqkvT, *woT, *qkv, *kh, *vt, *ao;
    cudaGetSymbolAddress((void**)&hsr,   g_hsr);
    cudaGetSymbolAddress((void**)&wqkvT, g_wqkvT);
    cudaGetSymbolAddress((void**)&woT,   g_woT);
    cudaGetSymbolAddress((void**)&qkv,   g_qkv);
    cudaGetSymbolAddress((void**)&kh,    g_kh);
    cudaGetSymbolAddress((void**)&vt,    g_vt);
    cudaGetSymbolAddress((void**)&ao,    g_ao);

    cudaFuncSetAttribute(gemm_mma,  cudaFuncAttributeMaxDynamicSharedMemorySize, GEMM_SMEM);
    cudaFuncSetAttribute(flash_mma, cudaFuncAttributeMaxDynamicSharedMemorySize, FB_SMEM);

    // #1-#4: pre-passes for the fused QKV GEMM
    round_tf32_kernel<<<(S_LEN * HID / 4 + 255) / 256, 256>>>(hs, hsr, S_LEN * HID / 4);
    transpose_fast<<<dim3(NQ / 32,   HID / 128), 256>>>(wq, wqkvT,                        HID, NQ,   NQ,   HID);
    transpose_fast<<<dim3(NKVD / 32, HID / 128), 256>>>(wk, wqkvT + (size_t)NQ * HID,     HID, NKVD, NKVD, HID);
    transpose_fast<<<dim3(NKVD / 32, HID / 128), 256>>>(wv, wqkvT + (size_t)(NQ + NKVD) * HID, HID, NKVD, NKVD, HID);

    // #5: fused QKV projection (one N=6144 GEMM)
    gemm_mma<<<dim3(NQKV / GBN, S_LEN / GBM), 256, GEMM_SMEM>>>(hsr, wqkvT, qkv, S_LEN, NQKV, HID);

    // #6: wo transpose (only needed by the final GEMM)
    transpose_fast<<<dim3(HID / 32, NQ / 128), 256>>>(wo, woT, NQ, HID, HID, NQ);

    // #7-#8: K rope (head-major) + V^T
    rope_transpose<<<dim3(S_LEN, NKV), 128>>>(qkv + NQ, NQKV, cs, sn, kh);
    transpose_fast<<<dim3(NKVD / 32, S_LEN / 128), 256>>>(qkv + NQ + NKVD, vt, S_LEN, NKVD, NQKV, S_LEN);

    // #9: flash attention (2 CTAs/SM, BM=64, shuffle-P)
    flash_mma<<<dim3(S_LEN / 64, NH), 128, FB_SMEM>>>(qkv, cs, sn, kh, vt, ao);

    // #10: output projection
    gemm_mma<<<dim3(HID / GBN, S_LEN / GBM), 256, GEMM_SMEM>>>(ao, woT, out, S_LEN, HID, NQ);
}

// round 12
// speedup vs baseline: 4.0197x; 1.0111x over previous
#include <cuda_runtime.h>
#include <cuda_bf16.h>
#include <math.h>
#include <stdint.h>

// Problem constants
#define S_LEN 2048
#define HID   4096
#define NH    32
#define NKV   8
#define HD    128
#define NQ    (NH * HD)    // 4096
#define NKVD  (NKV * HD)   // 1024
#define NQKV  (NQ + 2 * NKVD)  // 6144

// ---------------------------------------------------------------------------
// Scratch (static device arrays; no cudaMalloc allowed)
// ---------------------------------------------------------------------------
__device__ float g_hsr  [S_LEN * HID];     // hidden states, tf32-rounded
__device__ float g_wqkvT[NQKV * HID];      // [wq^T ; wk^T ; wv^T]  [6144][4096]
__device__ float g_woT  [HID * NQ];        // wo^T  [4096][4096]
__device__ float g_qkv  [S_LEN * NQKV];    // QKV projection [S][6144]
__device__ float g_kh   [S_LEN * NKVD];    // K rope, head-major [NKV][S][HD]
__device__ float g_vt   [S_LEN * NKVD];    // V^T head-major [NKV][HD][S]
__device__ float g_ao   [S_LEN * NQ];      // attention out [S][4096]

// ---------------------------------------------------------------------------
// Helpers
// ---------------------------------------------------------------------------
__device__ __forceinline__ uint32_t smem_u32(const void* p) {
    uint32_t a;
    asm("{ .reg .u64 t; cvta.to.shared.u64 t, %1; cvt.u32.u64 %0, t; }"
        : "=r"(a) : "l"(p));
    return a;
}
__device__ __forceinline__ float rna_tf32(float v) {
    uint32_t o;
    asm("cvt.rna.tf32.f32 %0, %1;" : "=r"(o) : "f"(v));
    return __uint_as_float(o);
}
__device__ __forceinline__ void mma_tf32(float* c, const uint32_t* a, const uint32_t* b) {
    asm("mma.sync.aligned.m16n8k8.row.col.f32.tf32.tf32.f32 "
        "{%0,%1,%2,%3}, {%4,%5,%6,%7}, {%8,%9}, {%0,%1,%2,%3};"
        : "+f"(c[0]), "+f"(c[1]), "+f"(c[2]), "+f"(c[3])
        : "r"(a[0]), "r"(a[1]), "r"(a[2]), "r"(a[3]), "r"(b[0]), "r"(b[1]));
}
__device__ __forceinline__ void ldsm_x4(uint32_t* r, uint32_t saddr) {
    asm volatile("ldmatrix.sync.aligned.m8n8.x4.shared.b16 {%0,%1,%2,%3}, [%4];"
        : "=r"(r[0]), "=r"(r[1]), "=r"(r[2]), "=r"(r[3]) : "r"(saddr));
}
__device__ __forceinline__ void cpasync16(uint32_t dst, const void* src) {
    asm volatile("cp.async.cg.shared.global [%0], [%1], 16;" :: "r"(dst), "l"(src));
}
#define CP_COMMIT()  asm volatile("cp.async.commit_group;" ::: "memory")
#define CP_WAIT0()   asm volatile("cp.async.wait_group 0;" ::: "memory")
#define CP_WAIT1()   asm volatile("cp.async.wait_group 1;" ::: "memory")

// ---------------------------------------------------------------------------
// Shared transpose tile (32n x 128k) + tf32 round: out[n][k] = rna(in[k][n]).
// tb must hold 4*32*33 floats.
// ---------------------------------------------------------------------------
__device__ __forceinline__ void transpose_tile_rna(
    const float* __restrict__ in, float* __restrict__ out,
    int ldin, int ldout, int n0, int k0, float* tb)
{
    const int tx = threadIdx.x & 31;
    const int wy = threadIdx.x >> 5;  // 0..7
#pragma unroll
    for (int tt = 0; tt < 4; ++tt)
#pragma unroll
        for (int j = 0; j < 4; ++j)
            tb[(tt * 32 + wy + 8 * j) * 33 + tx] =
                in[(size_t)(k0 + tt * 32 + wy + 8 * j) * ldin + n0 + tx];
    __syncthreads();
#pragma unroll
    for (int tt = 0; tt < 4; ++tt)
#pragma unroll
        for (int j = 0; j < 4; ++j)
            out[(size_t)(n0 + wy + 8 * j) * ldout + k0 + tt * 32 + tx] =
                rna_tf32(tb[(tt * 32 + tx) * 33 + wy + 8 * j]);
}

// ---------------------------------------------------------------------------
// tf32 mma GEMM body: C[M,N] = A[M,K] @ BT[N,K]^T. 128x128 block tile, 8
// warps of 64x32 warp tiles, BK=32, 3-stage cp.async, ldmatrix. 2 CTAs/SM.
// (At ~97% of the tf32 mma.sync instruction-rate ceiling — do not touch.)
// ---------------------------------------------------------------------------
#define GBM 128
#define GBN 128
#define GBK 32
#define ASTR 36
#define BSTR 36
#define A_ST (128 * ASTR)
#define B_ST (128 * BSTR)
#define STAGE_FL (A_ST + B_ST)
#define GEMM_SMEM (3 * STAGE_FL * 4)   // 110592 B

__device__ __forceinline__ void gemm_load_stage(
    uint32_t a_dst, uint32_t b_dst, const float* ap, const float* bp, int K)
{
#pragma unroll
    for (int i = 0; i < 4; ++i)
        cpasync16(a_dst + i * 32 * ASTR * 4, ap + (size_t)i * 32 * K);
#pragma unroll
    for (int i = 0; i < 4; ++i)
        cpasync16(b_dst + i * 32 * BSTR * 4, bp + (size_t)i * 32 * K);
}

__device__ __forceinline__ void gemm_body(
    const float* __restrict__ A, const float* __restrict__ BT,
    float* __restrict__ C, int N, int K, int bm, int bn, float* sm)
{
    const uint32_t sb = smem_u32(sm);
    const int tid  = threadIdx.x;
    const int lane = tid & 31;
    const int wid  = tid >> 5;
    const int wm   = wid >> 2;
    const int wn   = wid & 3;
    const int g    = lane >> 2;
    const int tig  = lane & 3;

    const int lrow = tid >> 3;
    const int lcol = (tid & 7) * 4;
    const float* Ap = A  + (size_t)(bm + lrow) * K + lcol;
    const float* Bp = BT + (size_t)(bn + lrow) * K + lcol;
    const uint32_t a_dst = sb + (uint32_t)(lrow * ASTR + lcol) * 4;
    const uint32_t b_dst = sb + (uint32_t)(A_ST + lrow * BSTR + lcol) * 4;

    const int a_r = wm * 64 + (lane & 7) + ((lane >> 3) & 1) * 8;
    const int a_c = (lane >> 4) * 4;
    const uint32_t a_frag = sb + (uint32_t)(a_r * ASTR + a_c) * 4;
    const int b_r = wn * 32 + ((lane >> 4) & 1) * 8 + (lane & 7);
    const int b_c = ((lane >> 3) & 1) * 4;
    const uint32_t b_frag = sb + (uint32_t)(A_ST + b_r * BSTR + b_c) * 4;

    float c[4][4][4];
#pragma unroll
    for (int mt = 0; mt < 4; ++mt)
#pragma unroll
        for (int nt = 0; nt < 4; ++nt)
#pragma unroll
            for (int i = 0; i < 4; ++i) c[mt][nt][i] = 0.0f;

    const int nkt = K / GBK;
    gemm_load_stage(a_dst, b_dst, Ap, Bp, K); CP_COMMIT();
    gemm_load_stage(a_dst + STAGE_FL * 4, b_dst + STAGE_FL * 4,
                    Ap + GBK, Bp + GBK, K); CP_COMMIT();

#pragma unroll 1
    for (int kt = 0; kt < nkt; ++kt) {
        if (kt + 1 < nkt) { CP_WAIT1(); } else { CP_WAIT0(); }
        __syncthreads();
        if (kt + 2 < nkt) {
            const uint32_t so = (uint32_t)((kt + 2) % 3) * STAGE_FL * 4;
            gemm_load_stage(a_dst + so, b_dst + so,
                            Ap + (kt + 2) * GBK, Bp + (kt + 2) * GBK, K);
        }
        CP_COMMIT();

        const uint32_t so = (uint32_t)(kt % 3) * STAGE_FL * 4;
#pragma unroll
        for (int ks = 0; ks < 4; ++ks) {
            uint32_t af[4][4];
#pragma unroll
            for (int mt = 0; mt < 4; ++mt)
                ldsm_x4(af[mt], a_frag + so + (uint32_t)(mt * 16 * ASTR + ks * 8) * 4);
            uint32_t bf[4][2];
#pragma unroll
            for (int p = 0; p < 2; ++p) {
                uint32_t t4[4];
                ldsm_x4(t4, b_frag + so + (uint32_t)(p * 16 * BSTR + ks * 8) * 4);
                bf[2 * p][0] = t4[0]; bf[2 * p][1] = t4[1];
                bf[2 * p + 1][0] = t4[2]; bf[2 * p + 1][1] = t4[3];
            }
#pragma unroll
            for (int mt = 0; mt < 4; ++mt)
#pragma unroll
                for (int nt = 0; nt < 4; ++nt)
                    mma_tf32(c[mt][nt], af[mt], bf[nt]);
        }
    }

#pragma unroll
    for (int mt = 0; mt < 4; ++mt) {
        const int r0 = bm + wm * 64 + mt * 16 + g;
#pragma unroll
        for (int nt = 0; nt < 4; ++nt) {
            const int cc = bn + wn * 32 + nt * 8 + tig * 2;
            *(float2*)&C[(size_t)r0 * N + cc]       = make_float2(c[mt][nt][0], c[mt][nt][1]);
            *(float2*)&C[(size_t)(r0 + 8) * N + cc] = make_float2(c[mt][nt][2], c[mt][nt][3]);
        }
    }
}

// Plain GEMM wrapper (O-projection)
__global__ __launch_bounds__(256, 2) void gemm_mma(
    const float* __restrict__ A, const float* __restrict__ BT,
    float* __restrict__ C, int M, int N, int K)
{
    extern __shared__ float sm[];
    gemm_body(A, BT, C, N, K, blockIdx.y * GBM, blockIdx.x * GBN, sm);
}

// Fused QKV GEMM + wo-transpose: blocks 0..767 run the GEMM (48 N-tiles x
// 16 M-tiles, x-fastest), blocks 768.. fill the GEMM's tail wave with the
// independent wo -> woT transpose tiles.
#define QKV_GEMM_BLKS (48 * 16)      // 768
#define WO_T_BLKS     (128 * 32)     // 4096
__global__ __launch_bounds__(256, 2) void gemm_qkv_wo(
    const float* __restrict__ A, const float* __restrict__ BT,
    float* __restrict__ C, const float* __restrict__ wo,
    float* __restrict__ woT)
{
    extern __shared__ float sm[];
    const int bid = blockIdx.x;
    if (bid < QKV_GEMM_BLKS) {
        gemm_body(A, BT, C, NQKV, HID, (bid / 48) * GBM, (bid % 48) * GBN, sm);
    } else {
        const int l = bid - QKV_GEMM_BLKS;
        // wo [NQ][HID] -> woT [HID][NQ]; n0 in HID, k0 in NQ
        transpose_tile_rna(wo, woT, HID, NQ, (l % 128) * 32, (l / 128) * 128, sm);
    }
}

// ---------------------------------------------------------------------------
// Fused pre-pass: round(hidden) + wq/wk/wv transposes, one launch.
// ---------------------------------------------------------------------------
#define PREP_ROUND_BLKS (S_LEN * HID / 4 / 256)   // 8192
#define PREP_WQ_BLKS    (128 * 32)                // 4096
#define PREP_WK_BLKS    (32 * 32)                 // 1024
#define PREP_WV_BLKS    (32 * 32)                 // 1024
#define PREP_BLKS (PREP_ROUND_BLKS + PREP_WQ_BLKS + PREP_WK_BLKS + PREP_WV_BLKS)

__global__ __launch_bounds__(256) void prep_fused(
    const float* __restrict__ hs, const float* __restrict__ wq,
    const float* __restrict__ wk, const float* __restrict__ wv,
    float* __restrict__ hsr, float* __restrict__ wqkvT)
{
    __shared__ float tb[4 * 32 * 33];
    int bid = blockIdx.x;
    if (bid < PREP_ROUND_BLKS) {
        const int i = bid * 256 + threadIdx.x;
        float4 v = ((const float4*)hs)[i];
        v.x = rna_tf32(v.x); v.y = rna_tf32(v.y);
        v.z = rna_tf32(v.z); v.w = rna_tf32(v.w);
        ((float4*)hsr)[i] = v;
        return;
    }
    bid -= PREP_ROUND_BLKS;
    if (bid < PREP_WQ_BLKS) {
        transpose_tile_rna(wq, wqkvT, NQ, HID, (bid % 128) * 32, (bid / 128) * 128, tb);
        return;
    }
    bid -= PREP_WQ_BLKS;
    if (bid < PREP_WK_BLKS) {
        transpose_tile_rna(wk, wqkvT + (size_t)NQ * HID, NKVD, HID,
                           (bid % 32) * 32, (bid / 32) * 128, tb);
        return;
    }
    bid -= PREP_WK_BLKS;
    transpose_tile_rna(wv, wqkvT + (size_t)(NQ + NKVD) * HID, NKVD, HID,
                       (bid % 32) * 32, (bid / 32) * 128, tb);
}

// ---------------------------------------------------------------------------
// Fused K-rope (head-major) + V^T transpose, one launch.
// rope blocks: 8192 (each 2 s-rows x 1 kv-head x 128 d); vt blocks: 512.
// ---------------------------------------------------------------------------
#define RK_ROPE_BLKS (S_LEN / 2 * NKV)            // 8192
#define RK_VT_BLKS   (32 * 16)                    // 512
#define RK_BLKS (RK_ROPE_BLKS + RK_VT_BLKS)

__global__ __launch_bounds__(256) void ropek_vt(
    const float* __restrict__ qkv, const float* __restrict__ cosp,
    const float* __restrict__ sinp, float* __restrict__ kh,
    float* __restrict__ vt)
{
    __shared__ float tb[4 * 32 * 33];
    int bid = blockIdx.x;
    if (bid < RK_ROPE_BLKS) {
        const int h = bid % NKV;
        const int s = (bid / NKV) * 2 + (threadIdx.x >> 7);
        const int d = threadIdx.x & 127;
        const float* src = qkv + (size_t)s * NQKV + NQ + h * HD;
        const float x   = src[d];
        const float p   = src[d ^ 64];
        const float rot = (d < 64) ? -p : p;
        const float val = x * cosp[s * HD + d] + rot * sinp[s * HD + d];
        kh[((size_t)h * S_LEN + s) * HD + d] = rna_tf32(val);
        return;
    }
    bid -= RK_ROPE_BLKS;
    // V region of qkv (row stride NQKV) -> vt [NKVD][S_LEN]
    transpose_tile_rna(qkv + NQ + NKVD, vt, NQKV, S_LEN,
                       (bid % 32) * 32, (bid / 32) * 128, tb);
}

// ---------------------------------------------------------------------------
// Flash attention, 2 CTAs/SM. BM=64, BN=64, 4 warps (16 q-rows each).
// No P smem: PV A-fragments built from softmax C-fragments via quad shuffles.
// Q rope fused in prologue. Split-barrier cp.async overlap (K,V,K,V groups).
// smem: Q 64x132 + K 64x132 + VT 128x68 = 102400 B -> 2 CTAs/SM.
// ---------------------------------------------------------------------------
#define FB_QSTR 132
#define FB_KSTR 132
#define FB_VSTR 68
#define FB_QS 0
#define FB_KS (64 * FB_QSTR)                // 8448
#define FB_VT (FB_KS + 64 * FB_KSTR)        // 16896
#define FB_SMEM ((FB_VT + 128 * FB_VSTR) * 4)   // 102400 B

__global__ __launch_bounds__(128, 2) void flash_mma(
    const float* __restrict__ QKV, const float* __restrict__ cosp,
    const float* __restrict__ sinp, const float* __restrict__ Kh,
    const float* __restrict__ VT, float* __restrict__ O)
{
    extern __shared__ float sm[];
    const uint32_t sb = smem_u32(sm);

    const int tid  = threadIdx.x;
    const int lane = tid & 31;
    const int wid  = tid >> 5;          // 0..3, 16 q-rows each
    const int g    = lane >> 2;
    const int tig  = lane & 3;
    const int qb   = gridDim.x - 1 - blockIdx.x;   // heavy CTAs first
    const int h    = blockIdx.y;
    const int kvh  = h >> 2;

    const float* Kbase  = Kh + (size_t)kvh * S_LEN * HD;
    const float* VTbase = VT + (size_t)kvh * HD * S_LEN;

    // Stage Q tile [64][128] with inline RoPE (reads raw projection)
#pragma unroll
    for (int j = 0; j < 16; ++j) {
        const int idx = tid + j * 128;
        const int r = idx >> 5, cb = (idx & 31) * 4;
        const int srow = qb * 64 + r;
        const float* qrow = QKV + (size_t)srow * NQKV + h * HD;
        float4 x  = *(const float4*)(qrow + cb);
        float4 p  = *(const float4*)(qrow + (cb ^ 64));
        float4 c4 = *(const float4*)(cosp + srow * HD + cb);
        float4 s4 = *(const float4*)(sinp + srow * HD + cb);
        const float sg = (cb < 64) ? -1.0f : 1.0f;
        sm[FB_QS + r * FB_QSTR + cb + 0] = rna_tf32(x.x * c4.x + sg * p.x * s4.x);
        sm[FB_QS + r * FB_QSTR + cb + 1] = rna_tf32(x.y * c4.y + sg * p.y * s4.y);
        sm[FB_QS + r * FB_QSTR + cb + 2] = rna_tf32(x.z * c4.z + sg * p.z * s4.z);
        sm[FB_QS + r * FB_QSTR + cb + 3] = rna_tf32(x.w * c4.w + sg * p.w * s4.w);
    }

    // ldmatrix per-lane bases
    const int rsel  = (lane & 7) + ((lane >> 3) & 1) * 8;
    const int csel  = (lane >> 4) * 4;
    const int brsel = ((lane >> 4) & 1) * 8 + (lane & 7);
    const int bcsel = ((lane >> 3) & 1) * 4;
    const uint32_t q_frag = sb + (uint32_t)(FB_QS + (wid * 16 + rsel) * FB_QSTR + csel) * 4;
    const uint32_t k_frag = sb + (uint32_t)(FB_KS + brsel * FB_KSTR + bcsel) * 4;
    const uint32_t v_frag = sb + (uint32_t)(FB_VT + brsel * FB_VSTR + bcsel) * 4;

    float s[8][4], o[16][4], m_i[2], l_i[2];
    m_i[0] = m_i[1] = -1e30f;
    l_i[0] = l_i[1] = 0.0f;
#pragma unroll
    for (int nt = 0; nt < 16; ++nt)
#pragma unroll
        for (int i = 0; i < 4; ++i) o[nt][i] = 0.0f;

    const float sc = 0.08838834764831845f;  // 1/sqrt(128)
    const int qrow0 = qb * 64 + wid * 16 + g;
    const int jtmax = qb;

    // Preload K(0) then V(0) as two separate cp.async groups.
#pragma unroll
    for (int j = 0; j < 16; ++j) {
        const int idx = tid + j * 128;
        const int r = idx >> 5, c = (idx & 31) * 4;
        cpasync16(sb + (uint32_t)(FB_KS + r * FB_KSTR + c) * 4,
                  Kbase + (size_t)r * HD + c);
    }
    CP_COMMIT();
#pragma unroll
    for (int j = 0; j < 16; ++j) {
        const int idx = tid + j * 128;
        const int d = idx >> 4, c = (idx & 15) * 4;
        cpasync16(sb + (uint32_t)(FB_VT + d * FB_VSTR + c) * 4,
                  VTbase + (size_t)d * S_LEN + c);
    }
    CP_COMMIT();

    for (int jt = 0; jt <= jtmax; ++jt) {
        CP_WAIT1();          // K(jt) landed (V(jt) may still be in flight)
        __syncthreads();

        // S = Q K^T  (16 x 64 per warp)
#pragma unroll
        for (int nt = 0; nt < 8; ++nt)
#pragma unroll
            for (int i = 0; i < 4; ++i) s[nt][i] = 0.0f;

#pragma unroll
        for (int ks = 0; ks < 16; ++ks) {
            uint32_t a[4];
            ldsm_x4(a, q_frag + ks * 32);
#pragma unroll
            for (int p = 0; p < 4; ++p) {
                uint32_t t4[4];
                ldsm_x4(t4, k_frag + (uint32_t)(p * 16 * FB_KSTR) * 4 + ks * 32);
                mma_tf32(s[2 * p],     a, t4);
                mma_tf32(s[2 * p + 1], a, t4 + 2);
            }
        }

        __syncthreads();     // all warps done reading K(jt)
        if (jt < jtmax) {    // stage K(jt+1); overlaps softmax + PV
#pragma unroll
            for (int j = 0; j < 16; ++j) {
                const int idx = tid + j * 128;
                const int r = idx >> 5, c = (idx & 31) * 4;
                cpasync16(sb + (uint32_t)(FB_KS + r * FB_KSTR + c) * 4,
                          Kbase + (size_t)((jt + 1) * 64 + r) * HD + c);
            }
        }
        CP_COMMIT();

        // Scale + causal mask
        const int colb = jt * 64 + tig * 2;
#pragma unroll
        for (int nt = 0; nt < 8; ++nt) {
            const int c0 = colb + nt * 8, c1 = c0 + 1;
            s[nt][0] = (c0 > qrow0)     ? -1e30f : s[nt][0] * sc;
            s[nt][1] = (c1 > qrow0)     ? -1e30f : s[nt][1] * sc;
            s[nt][2] = (c0 > qrow0 + 8) ? -1e30f : s[nt][2] * sc;
            s[nt][3] = (c1 > qrow0 + 8) ? -1e30f : s[nt][3] * sc;
        }

        // Online softmax (rows warp-private; quad reductions)
        float mx0 = -1e30f, mx1 = -1e30f;
#pragma unroll
        for (int nt = 0; nt < 8; ++nt) {
            mx0 = fmaxf(mx0, fmaxf(s[nt][0], s[nt][1]));
            mx1 = fmaxf(mx1, fmaxf(s[nt][2], s[nt][3]));
        }
        mx0 = fmaxf(mx0, __shfl_xor_sync(0xffffffffu, mx0, 1));
        mx0 = fmaxf(mx0, __shfl_xor_sync(0xffffffffu, mx0, 2));
        mx1 = fmaxf(mx1, __shfl_xor_sync(0xffffffffu, mx1, 1));
        mx1 = fmaxf(mx1, __shfl_xor_sync(0xffffffffu, mx1, 2));

        const float mn0 = fmaxf(m_i[0], mx0);
        const float mn1 = fmaxf(m_i[1], mx1);
        const float al0 = __expf(m_i[0] - mn0);
        const float al1 = __expf(m_i[1] - mn1);
        m_i[0] = mn0; m_i[1] = mn1;

        float rs0 = 0.0f, rs1 = 0.0f;
#pragma unroll
        for (int nt = 0; nt < 8; ++nt) {
            s[nt][0] = __expf(s[nt][0] - mn0);
            s[nt][1] = __expf(s[nt][1] - mn0);
            s[nt][2] = __expf(s[nt][2] - mn1);
            s[nt][3] = __expf(s[nt][3] - mn1);
            rs0 += s[nt][0] + s[nt][1];
            rs1 += s[nt][2] + s[nt][3];
        }
        rs0 += __shfl_xor_sync(0xffffffffu, rs0, 1);
        rs0 += __shfl_xor_sync(0xffffffffu, rs0, 2);
        rs1 += __shfl_xor_sync(0xffffffffu, rs1, 1);
        rs1 += __shfl_xor_sync(0xffffffffu, rs1, 2);
        l_i[0] = l_i[0] * al0 + rs0;
        l_i[1] = l_i[1] * al1 + rs1;
#pragma unroll
        for (int nt = 0; nt < 16; ++nt) {
            o[nt][0] *= al0; o[nt][1] *= al0;
            o[nt][2] *= al1; o[nt][3] *= al1;
        }

        CP_WAIT1();          // V(jt) landed (K(jt+1) may still be in flight)
        __syncthreads();

        // O += P @ V. A-fragments from C-layout s[] via quad shuffles.
        const int qbase = lane & ~3;
        const int srcA  = qbase | (tig >> 1);
        const int srcB  = srcA + 2;
        const bool odd  = (tig & 1);
#pragma unroll
        for (int ks = 0; ks < 8; ++ks) {
            const float p0 = s[ks][0], p1 = s[ks][1];
            const float p2 = s[ks][2], p3 = s[ks][3];
            const float a0A = __shfl_sync(0xffffffffu, p0, srcA);
            const float a1A = __shfl_sync(0xffffffffu, p1, srcA);
            const float a2A = __shfl_sync(0xffffffffu, p2, srcA);
            const float a3A = __shfl_sync(0xffffffffu, p3, srcA);
            const float a0B = __shfl_sync(0xffffffffu, p0, srcB);
            const float a1B = __shfl_sync(0xffffffffu, p1, srcB);
            const float a2B = __shfl_sync(0xffffffffu, p2, srcB);
            const float a3B = __shfl_sync(0xffffffffu, p3, srcB);
            uint32_t a[4];
            a[0] = __float_as_uint(rna_tf32(odd ? a1A : a0A));
            a[1] = __float_as_uint(rna_tf32(odd ? a3A : a2A));
            a[2] = __float_as_uint(rna_tf32(odd ? a1B : a0B));
            a[3] = __float_as_uint(rna_tf32(odd ? a3B : a2B));
#pragma unroll
            for (int p = 0; p < 8; ++p) {
                uint32_t t4[4];
                ldsm_x4(t4, v_frag + (uint32_t)(p * 16 * FB_VSTR) * 4 + ks * 32);
                mma_tf32(o[2 * p],     a, t4);
                mma_tf32(o[2 * p + 1], a, t4 + 2);
            }
        }

        __syncthreads();     // all warps done reading V(jt)
        if (jt < jtmax) {    // stage V(jt+1); overlaps next QK
#pragma unroll
            for (int j = 0; j < 16; ++j) {
                const int idx = tid + j * 128;
                const int d = idx >> 4, c = (idx & 15) * 4;
                cpasync16(sb + (uint32_t)(FB_VT + d * FB_VSTR + c) * 4,
                          VTbase + (size_t)d * S_LEN + (jt + 1) * 64 + c);
            }
        }
        CP_COMMIT();
    }

    // Epilogue: normalize, tf32-round, write [S][NQ]
    const float inv0 = 1.0f / l_i[0];
    const float inv1 = 1.0f / l_i[1];
    float* Op = O + (size_t)qrow0 * NQ + h * HD;
#pragma unroll
    for (int nt = 0; nt < 16; ++nt) {
        const int cc = nt * 8 + tig * 2;
        *(float2*)&Op[cc] =
            make_float2(rna_tf32(o[nt][0] * inv0), rna_tf32(o[nt][1] * inv0));
        *(float2*)&Op[(size_t)8 * NQ + cc] =
            make_float2(rna_tf32(o[nt][2] * inv1), rna_tf32(o[nt][3] * inv1));
    }
}

// ---------------------------------------------------------------------------
// Launch. Inputs: 0 hidden_states, 1 attention_mask (unused), 2 wq, 3 wk,
// 4 wv, 5 wo, 6 cos, 7 sin.
// Five launches: prep, qkv-gemm+wo-transpose, ropeK+vt, flash, O-proj.
// ---------------------------------------------------------------------------
extern "C" void kernel_launch(void* const* d_in, const int* in_sizes, int n_in,
                              void* d_out, int out_size)
{
    (void)in_sizes; (void)n_in; (void)out_size;
    const float* hs = (const float*)d_in[0];
    const float* wq = (const float*)d_in[2];
    const float* wk = (const float*)d_in[3];
    const float* wv = (const float*)d_in[4];
    const float* wo = (const float*)d_in[5];
    const float* cs = (const float*)d_in[6];
    const float* sn = (const float*)d_in[7];
    float* out = (float*)d_out;

    float *hsr, *wqkvT, *woT, *qkv, *kh, *vt, *ao;
    cudaGetSymbolAddress((void**)&hsr,   g_hsr);
    cudaGetSymbolAddress((void**)&wqkvT, g_wqkvT);
    cudaGetSymbolAddress((void**)&woT,   g_woT);
    cudaGetSymbolAddress((void**)&qkv,   g_qkv);
    cudaGetSymbolAddress((void**)&kh,    g_kh);
    cudaGetSymbolAddress((void**)&vt,    g_vt);
    cudaGetSymbolAddress((void**)&ao,    g_ao);

    cudaFuncSetAttribute(gemm_mma,    cudaFuncAttributeMaxDynamicSharedMemorySize, GEMM_SMEM);
    cudaFuncSetAttribute(gemm_qkv_wo, cudaFuncAttributeMaxDynamicSharedMemorySize, GEMM_SMEM);
    cudaFuncSetAttribute(flash_mma,   cudaFuncAttributeMaxDynamicSharedMemorySize, FB_SMEM);

    // #1: fused pre-pass (round + wq/wk/wv transposes)
    prep_fused<<<PREP_BLKS, 256>>>(hs, wq, wk, wv, hsr, wqkvT);

    // #2: QKV projection GEMM with wo-transpose blocks packed into its tail
    gemm_qkv_wo<<<QKV_GEMM_BLKS + WO_T_BLKS, 256, GEMM_SMEM>>>(
        hsr, wqkvT, qkv, wo, woT);

    // #3: K rope (head-major) + V^T, fused
    ropek_vt<<<RK_BLKS, 256>>>(qkv, cs, sn, kh, vt);

    // #4: flash attention (2 CTAs/SM, BM=64, shuffle-P, fused Q-rope)
    flash_mma<<<dim3(S_LEN / 64, NH), 128, FB_SMEM>>>(qkv, cs, sn, kh, vt, ao);

    // #5: output projection
    gemm_mma<<<dim3(HID / GBN, S_LEN / GBM), 256, GEMM_SMEM>>>(ao, woT, out, S_LEN, HID, NQ);
}

// round 13
// speedup vs baseline: 4.0640x; 1.0110x over previous
#include <cuda_runtime.h>
#include <cuda_bf16.h>
#include <math.h>
#include <stdint.h>

// Problem constants
#define S_LEN 2048
#define HID   4096
#define NH    32
#define NKV   8
#define HD    128
#define NQ    (NH * HD)    // 4096
#define NKVD  (NKV * HD)   // 1024
#define NQKV  (NQ + 2 * NKVD)  // 6144

// ---------------------------------------------------------------------------
// Scratch (static device arrays; no cudaMalloc allowed)
// ---------------------------------------------------------------------------
__device__ float g_hsr  [S_LEN * HID];     // hidden states, tf32-rounded
__device__ float g_wqkvT[NQKV * HID];      // [wq^T ; wk^T ; wv^T]  [6144][4096]
__device__ float g_woT  [HID * NQ];        // wo^T  [4096][4096]
__device__ float g_qkv  [S_LEN * NQKV];    // QKV projection (Q region used)
__device__ float g_kh   [S_LEN * NKVD];    // K rope, head-major [NKV][S][HD]
__device__ float g_vt   [S_LEN * NKVD];    // V^T head-major [NKV][HD][S]
__device__ float g_ao   [S_LEN * NQ];      // attention out [S][4096]

// ---------------------------------------------------------------------------
// Helpers
// ---------------------------------------------------------------------------
__device__ __forceinline__ uint32_t smem_u32(const void* p) {
    uint32_t a;
    asm("{ .reg .u64 t; cvta.to.shared.u64 t, %1; cvt.u32.u64 %0, t; }"
        : "=r"(a) : "l"(p));
    return a;
}
__device__ __forceinline__ float rna_tf32(float v) {
    uint32_t o;
    asm("cvt.rna.tf32.f32 %0, %1;" : "=r"(o) : "f"(v));
    return __uint_as_float(o);
}
__device__ __forceinline__ void mma_tf32(float* c, const uint32_t* a, const uint32_t* b) {
    asm("mma.sync.aligned.m16n8k8.row.col.f32.tf32.tf32.f32 "
        "{%0,%1,%2,%3}, {%4,%5,%6,%7}, {%8,%9}, {%0,%1,%2,%3};"
        : "+f"(c[0]), "+f"(c[1]), "+f"(c[2]), "+f"(c[3])
        : "r"(a[0]), "r"(a[1]), "r"(a[2]), "r"(a[3]), "r"(b[0]), "r"(b[1]));
}
__device__ __forceinline__ void ldsm_x4(uint32_t* r, uint32_t saddr) {
    asm volatile("ldmatrix.sync.aligned.m8n8.x4.shared.b16 {%0,%1,%2,%3}, [%4];"
        : "=r"(r[0]), "=r"(r[1]), "=r"(r[2]), "=r"(r[3]) : "r"(saddr));
}
__device__ __forceinline__ void cpasync16(uint32_t dst, const void* src) {
    asm volatile("cp.async.cg.shared.global [%0], [%1], 16;" :: "r"(dst), "l"(src));
}
#define CP_COMMIT()  asm volatile("cp.async.commit_group;" ::: "memory")
#define CP_WAIT0()   asm volatile("cp.async.wait_group 0;" ::: "memory")
#define CP_WAIT1()   asm volatile("cp.async.wait_group 1;" ::: "memory")

// ---------------------------------------------------------------------------
// Shared transpose tile (32n x 128k) + tf32 round: out[n][k] = rna(in[k][n]).
// tb must hold 4*32*33 floats.
// ---------------------------------------------------------------------------
__device__ __forceinline__ void transpose_tile_rna(
    const float* __restrict__ in, float* __restrict__ out,
    int ldin, int ldout, int n0, int k0, float* tb)
{
    const int tx = threadIdx.x & 31;
    const int wy = threadIdx.x >> 5;  // 0..7
#pragma unroll
    for (int tt = 0; tt < 4; ++tt)
#pragma unroll
        for (int j = 0; j < 4; ++j)
            tb[(tt * 32 + wy + 8 * j) * 33 + tx] =
                in[(size_t)(k0 + tt * 32 + wy + 8 * j) * ldin + n0 + tx];
    __syncthreads();
#pragma unroll
    for (int tt = 0; tt < 4; ++tt)
#pragma unroll
        for (int j = 0; j < 4; ++j)
            out[(size_t)(n0 + wy + 8 * j) * ldout + k0 + tt * 32 + tx] =
                rna_tf32(tb[(tt * 32 + tx) * 33 + wy + 8 * j]);
}

// ---------------------------------------------------------------------------
// tf32 mma GEMM body: 128x128 block tile, 8 warps of 64x32 warp tiles,
// BK=32, 3-stage cp.async, ldmatrix. 2 CTAs/SM.
// Epilogue modes: 0 = plain row write to C (stride N);
//                 1 = rope-K (stage smem, d^64 mix, write dst [S][HD]);
//                 2 = V^T   (stage smem, write dst [HD][S] transposed).
// ---------------------------------------------------------------------------
#define GBM 128
#define GBN 128
#define GBK 32
#define ASTR 36
#define BSTR 36
#define A_ST (128 * ASTR)
#define B_ST (128 * BSTR)
#define STAGE_FL (A_ST + B_ST)
#define GEMM_SMEM (3 * STAGE_FL * 4)   // 110592 B
#define EP_STR 132

__device__ __forceinline__ void gemm_load_stage(
    uint32_t a_dst, uint32_t b_dst, const float* ap, const float* bp, int K)
{
#pragma unroll
    for (int i = 0; i < 4; ++i)
        cpasync16(a_dst + i * 32 * ASTR * 4, ap + (size_t)i * 32 * K);
#pragma unroll
    for (int i = 0; i < 4; ++i)
        cpasync16(b_dst + i * 32 * BSTR * 4, bp + (size_t)i * 32 * K);
}

__device__ __forceinline__ void gemm_body(
    const float* __restrict__ A, const float* __restrict__ BT,
    float* __restrict__ C, int N, int K, int bm, int bn, float* sm,
    int mode, const float* __restrict__ cosp, const float* __restrict__ sinp,
    float* __restrict__ dst)
{
    const uint32_t sb = smem_u32(sm);
    const int tid  = threadIdx.x;
    const int lane = tid & 31;
    const int wid  = tid >> 5;
    const int wm   = wid >> 2;
    const int wn   = wid & 3;
    const int g    = lane >> 2;
    const int tig  = lane & 3;

    const int lrow = tid >> 3;
    const int lcol = (tid & 7) * 4;
    const float* Ap = A  + (size_t)(bm + lrow) * K + lcol;
    const float* Bp = BT + (size_t)(bn + lrow) * K + lcol;
    const uint32_t a_dst = sb + (uint32_t)(lrow * ASTR + lcol) * 4;
    const uint32_t b_dst = sb + (uint32_t)(A_ST + lrow * BSTR + lcol) * 4;

    const int a_r = wm * 64 + (lane & 7) + ((lane >> 3) & 1) * 8;
    const int a_c = (lane >> 4) * 4;
    const uint32_t a_frag = sb + (uint32_t)(a_r * ASTR + a_c) * 4;
    const int b_r = wn * 32 + ((lane >> 4) & 1) * 8 + (lane & 7);
    const int b_c = ((lane >> 3) & 1) * 4;
    const uint32_t b_frag = sb + (uint32_t)(A_ST + b_r * BSTR + b_c) * 4;

    float c[4][4][4];
#pragma unroll
    for (int mt = 0; mt < 4; ++mt)
#pragma unroll
        for (int nt = 0; nt < 4; ++nt)
#pragma unroll
            for (int i = 0; i < 4; ++i) c[mt][nt][i] = 0.0f;

    const int nkt = K / GBK;
    gemm_load_stage(a_dst, b_dst, Ap, Bp, K); CP_COMMIT();
    gemm_load_stage(a_dst + STAGE_FL * 4, b_dst + STAGE_FL * 4,
                    Ap + GBK, Bp + GBK, K); CP_COMMIT();

#pragma unroll 1
    for (int kt = 0; kt < nkt; ++kt) {
        if (kt + 1 < nkt) { CP_WAIT1(); } else { CP_WAIT0(); }
        __syncthreads();
        if (kt + 2 < nkt) {
            const uint32_t so = (uint32_t)((kt + 2) % 3) * STAGE_FL * 4;
            gemm_load_stage(a_dst + so, b_dst + so,
                            Ap + (kt + 2) * GBK, Bp + (kt + 2) * GBK, K);
        }
        CP_COMMIT();

        const uint32_t so = (uint32_t)(kt % 3) * STAGE_FL * 4;
#pragma unroll
        for (int ks = 0; ks < 4; ++ks) {
            uint32_t af[4][4];
#pragma unroll
            for (int mt = 0; mt < 4; ++mt)
                ldsm_x4(af[mt], a_frag + so + (uint32_t)(mt * 16 * ASTR + ks * 8) * 4);
            uint32_t bf[4][2];
#pragma unroll
            for (int p = 0; p < 2; ++p) {
                uint32_t t4[4];
                ldsm_x4(t4, b_frag + so + (uint32_t)(p * 16 * BSTR + ks * 8) * 4);
                bf[2 * p][0] = t4[0]; bf[2 * p][1] = t4[1];
                bf[2 * p + 1][0] = t4[2]; bf[2 * p + 1][1] = t4[3];
            }
#pragma unroll
            for (int mt = 0; mt < 4; ++mt)
#pragma unroll
                for (int nt = 0; nt < 4; ++nt)
                    mma_tf32(c[mt][nt], af[mt], bf[nt]);
        }
    }

    if (mode == 0) {
#pragma unroll
        for (int mt = 0; mt < 4; ++mt) {
            const int r0 = bm + wm * 64 + mt * 16 + g;
#pragma unroll
            for (int nt = 0; nt < 4; ++nt) {
                const int cc = bn + wn * 32 + nt * 8 + tig * 2;
                *(float2*)&C[(size_t)r0 * N + cc]       = make_float2(c[mt][nt][0], c[mt][nt][1]);
                *(float2*)&C[(size_t)(r0 + 8) * N + cc] = make_float2(c[mt][nt][2], c[mt][nt][3]);
            }
        }
        return;
    }

    // Fused K-rope / V^T epilogue: stage fp32 accumulators into smem tile
    // S[r][d] (r = local s-row 0..127, d = head dim 0..127).
    __syncthreads();   // all warps done with stage-buffer ldsm reads
#pragma unroll
    for (int mt = 0; mt < 4; ++mt) {
        const int r0 = wm * 64 + mt * 16 + g;
#pragma unroll
        for (int nt = 0; nt < 4; ++nt) {
            const int cc = wn * 32 + nt * 8 + tig * 2;
            *(float2*)&sm[r0 * EP_STR + cc]       = make_float2(c[mt][nt][0], c[mt][nt][1]);
            *(float2*)&sm[(r0 + 8) * EP_STR + cc] = make_float2(c[mt][nt][2], c[mt][nt][3]);
        }
    }
    __syncthreads();

    if (mode == 1) {
        // rope: dst is kh head base [S_LEN][HD]; rows bm..bm+127
        const int r    = tid >> 1;
        const int c0   = (tid & 1) * 64;
        const int srow = bm + r;
        const float sg = (c0 < 64) ? -1.0f : 1.0f;
#pragma unroll
        for (int i = 0; i < 16; ++i) {
            float4 x  = *(float4*)&sm[r * EP_STR + c0 + 4 * i];
            float4 p  = *(float4*)&sm[r * EP_STR + (c0 ^ 64) + 4 * i];
            float4 cv = *(const float4*)(cosp + (size_t)srow * HD + c0 + 4 * i);
            float4 sv = *(const float4*)(sinp + (size_t)srow * HD + c0 + 4 * i);
            float4 o;
            o.x = rna_tf32(x.x * cv.x + sg * p.x * sv.x);
            o.y = rna_tf32(x.y * cv.y + sg * p.y * sv.y);
            o.z = rna_tf32(x.z * cv.z + sg * p.z * sv.z);
            o.w = rna_tf32(x.w * cv.w + sg * p.w * sv.w);
            *(float4*)&dst[(size_t)srow * HD + c0 + 4 * i] = o;
        }
    } else {
        // V^T: dst is vt head base [HD][S_LEN]; cols bm..bm+127
        const int d  = tid >> 1;
        const int h2 = tid & 1;
#pragma unroll
        for (int i = 0; i < 16; ++i) {
            const int r = h2 * 64 + 4 * i;
            float4 o;
            o.x = rna_tf32(sm[(r + 0) * EP_STR + d]);
            o.y = rna_tf32(sm[(r + 1) * EP_STR + d]);
            o.z = rna_tf32(sm[(r + 2) * EP_STR + d]);
            o.w = rna_tf32(sm[(r + 3) * EP_STR + d]);
            *(float4*)&dst[(size_t)d * S_LEN + bm + r] = o;
        }
    }
}

// Plain GEMM wrapper (O-projection)
__global__ __launch_bounds__(256, 2) void gemm_mma(
    const float* __restrict__ A, const float* __restrict__ BT,
    float* __restrict__ C, int M, int N, int K)
{
    extern __shared__ float sm[];
    gemm_body(A, BT, C, N, K, blockIdx.y * GBM, blockIdx.x * GBN, sm,
              0, 0, 0, 0);
}

// Fused QKV GEMM (+rope-K/V^T epilogues) + wo-transpose tail fill.
#define QKV_GEMM_BLKS (48 * 16)      // 768
#define WO_T_BLKS     (128 * 32)     // 4096
__global__ __launch_bounds__(256, 2) void gemm_qkv_wo(
    const float* __restrict__ A, const float* __restrict__ BT,
    float* __restrict__ qkv, const float* __restrict__ wo,
    float* __restrict__ woT, const float* __restrict__ cosp,
    const float* __restrict__ sinp, float* __restrict__ kh,
    float* __restrict__ vt)
{
    extern __shared__ float sm[];
    const int bid = blockIdx.x;
    if (bid < QKV_GEMM_BLKS) {
        const int tm = bid / 48, tn = bid % 48;
        const int bm = tm * GBM, bn = tn * GBN;
        if (tn < 32) {
            gemm_body(A, BT, qkv, NQKV, HID, bm, bn, sm, 0, 0, 0, 0);
        } else if (tn < 40) {
            gemm_body(A, BT, qkv, NQKV, HID, bm, bn, sm, 1, cosp, sinp,
                      kh + (size_t)(tn - 32) * S_LEN * HD);
        } else {
            gemm_body(A, BT, qkv, NQKV, HID, bm, bn, sm, 2, 0, 0,
                      vt + (size_t)(tn - 40) * HD * S_LEN);
        }
    } else {
        const int l = bid - QKV_GEMM_BLKS;
        transpose_tile_rna(wo, woT, HID, NQ, (l % 128) * 32, (l / 128) * 128, sm);
    }
}

// ---------------------------------------------------------------------------
// Fused pre-pass: round(hidden) + wq/wk/wv transposes, one launch.
// ---------------------------------------------------------------------------
#define PREP_ROUND_BLKS (S_LEN * HID / 4 / 256)   // 8192
#define PREP_WQ_BLKS    (128 * 32)                // 4096
#define PREP_WK_BLKS    (32 * 32)                 // 1024
#define PREP_WV_BLKS    (32 * 32)                 // 1024
#define PREP_BLKS (PREP_ROUND_BLKS + PREP_WQ_BLKS + PREP_WK_BLKS + PREP_WV_BLKS)

__global__ __launch_bounds__(256) void prep_fused(
    const float* __restrict__ hs, const float* __restrict__ wq,
    const float* __restrict__ wk, const float* __restrict__ wv,
    float* __restrict__ hsr, float* __restrict__ wqkvT)
{
    __shared__ float tb[4 * 32 * 33];
    int bid = blockIdx.x;
    if (bid < PREP_ROUND_BLKS) {
        const int i = bid * 256 + threadIdx.x;
        float4 v = ((const float4*)hs)[i];
        v.x = rna_tf32(v.x); v.y = rna_tf32(v.y);
        v.z = rna_tf32(v.z); v.w = rna_tf32(v.w);
        ((float4*)hsr)[i] = v;
        return;
    }
    bid -= PREP_ROUND_BLKS;
    if (bid < PREP_WQ_BLKS) {
        transpose_tile_rna(wq, wqkvT, NQ, HID, (bid % 128) * 32, (bid / 128) * 128, tb);
        return;
    }
    bid -= PREP_WQ_BLKS;
    if (bid < PREP_WK_BLKS) {
        transpose_tile_rna(wk, wqkvT + (size_t)NQ * HID, NKVD, HID,
                           (bid % 32) * 32, (bid / 32) * 128, tb);
        return;
    }
    bid -= PREP_WK_BLKS;
    transpose_tile_rna(wv, wqkvT + (size_t)(NQ + NKVD) * HID, NKVD, HID,
                       (bid % 32) * 32, (bid / 32) * 128, tb);
}

// ---------------------------------------------------------------------------
// Flash attention, 2 CTAs/SM. BM=64, BN=64, 4 warps (16 q-rows each).
// No P smem (quad-shuffle A-fragments). Q rope fused in prologue.
// 3 barriers/jt: K(jt+1) prefetch issued after the V-ready barrier (which
// already proves all warps exited QK). Commit order K,V,K,V...
// smem: Q 64x132 + K 64x132 + VT 128x68 = 102400 B -> 2 CTAs/SM.
// ---------------------------------------------------------------------------
#define FB_QSTR 132
#define FB_KSTR 132
#define FB_VSTR 68
#define FB_QS 0
#define FB_KS (64 * FB_QSTR)                // 8448
#define FB_VT (FB_KS + 64 * FB_KSTR)        // 16896
#define FB_SMEM ((FB_VT + 128 * FB_VSTR) * 4)   // 102400 B

__global__ __launch_bounds__(128, 2) void flash_mma(
    const float* __restrict__ QKV, const float* __restrict__ cosp,
    const float* __restrict__ sinp, const float* __restrict__ Kh,
    const float* __restrict__ VT, float* __restrict__ O)
{
    extern __shared__ float sm[];
    const uint32_t sb = smem_u32(sm);

    const int tid  = threadIdx.x;
    const int lane = tid & 31;
    const int wid  = tid >> 5;          // 0..3, 16 q-rows each
    const int g    = lane >> 2;
    const int tig  = lane & 3;
    const int qb   = gridDim.x - 1 - blockIdx.x;   // heavy CTAs first
    const int h    = blockIdx.y;
    const int kvh  = h >> 2;

    const float* Kbase  = Kh + (size_t)kvh * S_LEN * HD;
    const float* VTbase = VT + (size_t)kvh * HD * S_LEN;

    // Stage Q tile [64][128] with inline RoPE (reads raw projection)
#pragma unroll
    for (int j = 0; j < 16; ++j) {
        const int idx = tid + j * 128;
        const int r = idx >> 5, cb = (idx & 31) * 4;
        const int srow = qb * 64 + r;
        const float* qrow = QKV + (size_t)srow * NQKV + h * HD;
        float4 x  = *(const float4*)(qrow + cb);
        float4 p  = *(const float4*)(qrow + (cb ^ 64));
        float4 c4 = *(const float4*)(cosp + srow * HD + cb);
        float4 s4 = *(const float4*)(sinp + srow * HD + cb);
        const float sg = (cb < 64) ? -1.0f : 1.0f;
        sm[FB_QS + r * FB_QSTR + cb + 0] = rna_tf32(x.x * c4.x + sg * p.x * s4.x);
        sm[FB_QS + r * FB_QSTR + cb + 1] = rna_tf32(x.y * c4.y + sg * p.y * s4.y);
        sm[FB_QS + r * FB_QSTR + cb + 2] = rna_tf32(x.z * c4.z + sg * p.z * s4.z);
        sm[FB_QS + r * FB_QSTR + cb + 3] = rna_tf32(x.w * c4.w + sg * p.w * s4.w);
    }

    // ldmatrix per-lane bases
    const int rsel  = (lane & 7) + ((lane >> 3) & 1) * 8;
    const int csel  = (lane >> 4) * 4;
    const int brsel = ((lane >> 4) & 1) * 8 + (lane & 7);
    const int bcsel = ((lane >> 3) & 1) * 4;
    const uint32_t q_frag = sb + (uint32_t)(FB_QS + (wid * 16 + rsel) * FB_QSTR + csel) * 4;
    const uint32_t k_frag = sb + (uint32_t)(FB_KS + brsel * FB_KSTR + bcsel) * 4;
    const uint32_t v_frag = sb + (uint32_t)(FB_VT + brsel * FB_VSTR + bcsel) * 4;

    float s[8][4], o[16][4], m_i[2], l_i[2];
    m_i[0] = m_i[1] = -1e30f;
    l_i[0] = l_i[1] = 0.0f;
#pragma unroll
    for (int nt = 0; nt < 16; ++nt)
#pragma unroll
        for (int i = 0; i < 4; ++i) o[nt][i] = 0.0f;

    const float sc = 0.08838834764831845f;  // 1/sqrt(128)
    const int qrow0 = qb * 64 + wid * 16 + g;
    const int jtmax = qb;

    // Preload K(0) then V(0) as two separate cp.async groups.
#pragma unroll
    for (int j = 0; j < 16; ++j) {
        const int idx = tid + j * 128;
        const int r = idx >> 5, c = (idx & 31) * 4;
        cpasync16(sb + (uint32_t)(FB_KS + r * FB_KSTR + c) * 4,
                  Kbase + (size_t)r * HD + c);
    }
    CP_COMMIT();
#pragma unroll
    for (int j = 0; j < 16; ++j) {
        const int idx = tid + j * 128;
        const int d = idx >> 4, c = (idx & 15) * 4;
        cpasync16(sb + (uint32_t)(FB_VT + d * FB_VSTR + c) * 4,
                  VTbase + (size_t)d * S_LEN + c);
    }
    CP_COMMIT();

    for (int jt = 0; jt <= jtmax; ++jt) {
        CP_WAIT1();          // K(jt) landed (V(jt) may still be in flight)
        __syncthreads();

        // S = Q K^T  (16 x 64 per warp)
#pragma unroll
        for (int nt = 0; nt < 8; ++nt)
#pragma unroll
            for (int i = 0; i < 4; ++i) s[nt][i] = 0.0f;

#pragma unroll
        for (int ks = 0; ks < 16; ++ks) {
            uint32_t a[4];
            ldsm_x4(a, q_frag + ks * 32);
#pragma unroll
            for (int p = 0; p < 4; ++p) {
                uint32_t t4[4];
                ldsm_x4(t4, k_frag + (uint32_t)(p * 16 * FB_KSTR) * 4 + ks * 32);
                mma_tf32(s[2 * p],     a, t4);
                mma_tf32(s[2 * p + 1], a, t4 + 2);
            }
        }

        // Scale + causal mask
        const int colb = jt * 64 + tig * 2;
#pragma unroll
        for (int nt = 0; nt < 8; ++nt) {
            const int c0 = colb + nt * 8, c1 = c0 + 1;
            s[nt][0] = (c0 > qrow0)     ? -1e30f : s[nt][0] * sc;
            s[nt][1] = (c1 > qrow0)     ? -1e30f : s[nt][1] * sc;
            s[nt][2] = (c0 > qrow0 + 8) ? -1e30f : s[nt][2] * sc;
            s[nt][3] = (c1 > qrow0 + 8) ? -1e30f : s[nt][3] * sc;
        }

        // Online softmax (rows warp-private; quad reductions)
        float mx0 = -1e30f, mx1 = -1e30f;
#pragma unroll
        for (int nt = 0; nt < 8; ++nt) {
            mx0 = fmaxf(mx0, fmaxf(s[nt][0], s[nt][1]));
            mx1 = fmaxf(mx1, fmaxf(s[nt][2], s[nt][3]));
        }
        mx0 = fmaxf(mx0, __shfl_xor_sync(0xffffffffu, mx0, 1));
        mx0 = fmaxf(mx0, __shfl_xor_sync(0xffffffffu, mx0, 2));
        mx1 = fmaxf(mx1, __shfl_xor_sync(0xffffffffu, mx1, 1));
        mx1 = fmaxf(mx1, __shfl_xor_sync(0xffffffffu, mx1, 2));

        const float mn0 = fmaxf(m_i[0], mx0);
        const float mn1 = fmaxf(m_i[1], mx1);
        const float al0 = __expf(m_i[0] - mn0);
        const float al1 = __expf(m_i[1] - mn1);
        m_i[0] = mn0; m_i[1] = mn1;

        float rs0 = 0.0f, rs1 = 0.0f;
#pragma unroll
        for (int nt = 0; nt < 8; ++nt) {
            s[nt][0] = __expf(s[nt][0] - mn0);
            s[nt][1] = __expf(s[nt][1] - mn0);
            s[nt][2] = __expf(s[nt][2] - mn1);
            s[nt][3] = __expf(s[nt][3] - mn1);
            rs0 += s[nt][0] + s[nt][1];
            rs1 += s[nt][2] + s[nt][3];
        }
        rs0 += __shfl_xor_sync(0xffffffffu, rs0, 1);
        rs0 += __shfl_xor_sync(0xffffffffu, rs0, 2);
        rs1 += __shfl_xor_sync(0xffffffffu, rs1, 1);
        rs1 += __shfl_xor_sync(0xffffffffu, rs1, 2);
        l_i[0] = l_i[0] * al0 + rs0;
        l_i[1] = l_i[1] * al1 + rs1;
#pragma unroll
        for (int nt = 0; nt < 16; ++nt) {
            o[nt][0] *= al0; o[nt][1] *= al0;
            o[nt][2] *= al1; o[nt][3] *= al1;
        }

        CP_WAIT0();          // V(jt) landed (only group in flight here)
        __syncthreads();     // all warps see V; all warps past QK -> K reusable
        if (jt < jtmax) {    // stage K(jt+1); overlaps PV
#pragma unroll
            for (int j = 0; j < 16; ++j) {
                const int idx = tid + j * 128;
                const int r = idx >> 5, c = (idx & 31) * 4;
                cpasync16(sb + (uint32_t)(FB_KS + r * FB_KSTR + c) * 4,
                          Kbase + (size_t)((jt + 1) * 64 + r) * HD + c);
            }
        }
        CP_COMMIT();

        // O += P @ V. A-fragments from C-layout s[] via quad shuffles.
        const int qbase = lane & ~3;
        const int srcA  = qbase | (tig >> 1);
        const int srcB  = srcA + 2;
        const bool odd  = (tig & 1);
#pragma unroll
        for (int ks = 0; ks < 8; ++ks) {
            const float p0 = s[ks][0], p1 = s[ks][1];
            const float p2 = s[ks][2], p3 = s[ks][3];
            const float a0A = __shfl_sync(0xffffffffu, p0, srcA);
            const float a1A = __shfl_sync(0xffffffffu, p1, srcA);
            const float a2A = __shfl_sync(0xffffffffu, p2, srcA);
            const float a3A = __shfl_sync(0xffffffffu, p3, srcA);
            const float a0B = __shfl_sync(0xffffffffu, p0, srcB);
            const float a1B = __shfl_sync(0xffffffffu, p1, srcB);
            const float a2B = __shfl_sync(0xffffffffu, p2, srcB);
            const float a3B = __shfl_sync(0xffffffffu, p3, srcB);
            uint32_t a[4];
            a[0] = __float_as_uint(rna_tf32(odd ? a1A : a0A));
            a[1] = __float_as_uint(rna_tf32(odd ? a3A : a2A));
            a[2] = __float_as_uint(rna_tf32(odd ? a1B : a0B));
            a[3] = __float_as_uint(rna_tf32(odd ? a3B : a2B));
#pragma unroll
            for (int p = 0; p < 8; ++p) {
                uint32_t t4[4];
                ldsm_x4(t4, v_frag + (uint32_t)(p * 16 * FB_VSTR) * 4 + ks * 32);
                mma_tf32(o[2 * p],     a, t4);
                mma_tf32(o[2 * p + 1], a, t4 + 2);
            }
        }

        __syncthreads();     // all warps done reading V(jt)
        if (jt < jtmax) {    // stage V(jt+1); overlaps next QK
#pragma unroll
            for (int j = 0; j < 16; ++j) {
                const int idx = tid + j * 128;
                const int d = idx >> 4, c = (idx & 15) * 4;
                cpasync16(sb + (uint32_t)(FB_VT + d * FB_VSTR + c) * 4,
                          VTbase + (size_t)d * S_LEN + (jt + 1) * 64 + c);
            }
        }
        CP_COMMIT();
    }

    // Epilogue: normalize, tf32-round, write [S][NQ]
    const float inv0 = 1.0f / l_i[0];
    const float inv1 = 1.0f / l_i[1];
    float* Op = O + (size_t)qrow0 * NQ + h * HD;
#pragma unroll
    for (int nt = 0; nt < 16; ++nt) {
        const int cc = nt * 8 + tig * 2;
        *(float2*)&Op[cc] =
            make_float2(rna_tf32(o[nt][0] * inv0), rna_tf32(o[nt][1] * inv0));
        *(float2*)&Op[(size_t)8 * NQ + cc] =
            make_float2(rna_tf32(o[nt][2] * inv1), rna_tf32(o[nt][3] * inv1));
    }
}

// ---------------------------------------------------------------------------
// Launch. Inputs: 0 hidden_states, 1 attention_mask (unused), 2 wq, 3 wk,
// 4 wv, 5 wo, 6 cos, 7 sin.
// Four launches: prep, qkv-gemm(+rope/vt epilogue)+wo-transpose, flash, O-proj.
// ---------------------------------------------------------------------------
extern "C" void kernel_launch(void* const* d_in, const int* in_sizes, int n_in,
                              void* d_out, int out_size)
{
    (void)in_sizes; (void)n_in; (void)out_size;
    const float* hs = (const float*)d_in[0];
    const float* wq = (const float*)d_in[2];
    const float* wk = (const float*)d_in[3];
    const float* wv = (const float*)d_in[4];
    const float* wo = (const float*)d_in[5];
    const float* cs = (const float*)d_in[6];
    const float* sn = (const float*)d_in[7];
    float* out = (float*)d_out;

    float *hsr, *wqkvT, *woT, *qkv, *kh, *vt, *ao;
    cudaGetSymbolAddress((void**)&hsr,   g_hsr);
    cudaGetSymbolAddress((void**)&wqkvT, g_wqkvT);
    cudaGetSymbolAddress((void**)&woT,   g_woT);
    cudaGetSymbolAddress((void**)&qkv,   g_qkv);
    cudaGetSymbolAddress((void**)&kh,    g_kh);
    cudaGetSymbolAddress((void**)&vt,    g_vt);
    cudaGetSymbolAddress((void**)&ao,    g_ao);

    cudaFuncSetAttribute(gemm_mma,    cudaFuncAttributeMaxDynamicSharedMemorySize, GEMM_SMEM);
    cudaFuncSetAttribute(gemm_qkv_wo, cudaFuncAttributeMaxDynamicSharedMemorySize, GEMM_SMEM);
    cudaFuncSetAttribute(flash_mma,   cudaFuncAttributeMaxDynamicSharedMemorySize, FB_SMEM);

    // #1: fused pre-pass (round + wq/wk/wv transposes)
    prep_fused<<<PREP_BLKS, 256>>>(hs, wq, wk, wv, hsr, wqkvT);

    // #2: QKV GEMM with fused rope-K / V^T epilogues + wo-transpose tail
    gemm_qkv_wo<<<QKV_GEMM_BLKS + WO_T_BLKS, 256, GEMM_SMEM>>>(
        hsr, wqkvT, qkv, wo, woT, cs, sn, kh, vt);

    // #3: flash attention (2 CTAs/SM, BM=64, shuffle-P, fused Q-rope)
    flash_mma<<<dim3(S_LEN / 64, NH), 128, FB_SMEM>>>(qkv, cs, sn, kh, vt, ao);

    // #4: output projection
    gemm_mma<<<dim3(HID / GBN, S_LEN / GBM), 256, GEMM_SMEM>>>(ao, woT, out, S_LEN, HID, NQ);
}